// round 1
// baseline (speedup 1.0000x reference)
#include <cuda_runtime.h>

#define BATCH   16384
#define D_DIM   768
#define H_DIM   256
#define NQ      8
#define NL      2

// ---------------- scratch (device globals; no runtime allocation) -----------
__device__ float  g_h[BATCH * H_DIM];   // gelu(x@W1+b1)
__device__ float  g_e[BATCH * H_DIM];   // gelu(z@W3+b3)
__device__ float  g_y[BATCH * D_DIM];   // x + e@W4 + b4 (pre-LN)
__device__ float2 g_C[NL][NQ][4];       // variational 2x2 complex per (layer,wire)

// ---------------- helpers ----------------------------------------------------
__device__ __forceinline__ float2 cmul(float2 a, float2 b) {
    return make_float2(a.x * b.x - a.y * b.y, a.x * b.y + a.y * b.x);
}
__device__ __forceinline__ float2 cadd(float2 a, float2 b) {
    return make_float2(a.x + b.x, a.y + b.y);
}
__device__ __forceinline__ float gelu_exact(float v) {
    return 0.5f * v * (1.0f + erff(v * 0.70710678118654752f));
}

// ---------------- K0: precompute C[l][i] = RZ(w2) @ RY(w1) @ RZ(w0) ---------
__global__ void prep_gates(const float* __restrict__ qw) {
    int t = threadIdx.x;
    if (t >= NL * NQ) return;
    int l = t / NQ, i = t % NQ;
    float w0 = qw[(l * NQ + i) * 3 + 0];
    float w1 = qw[(l * NQ + i) * 3 + 1];
    float w2 = qw[(l * NQ + i) * 3 + 2];
    float c0 = cosf(0.5f * w0), s0 = sinf(0.5f * w0);
    float c1 = cosf(0.5f * w1), s1 = sinf(0.5f * w1);
    float c2 = cosf(0.5f * w2), s2 = sinf(0.5f * w2);
    float2 e0  = make_float2(c0, -s0);  // exp(-i w0/2)
    float2 e0c = make_float2(c0,  s0);
    // T = RY(w1) @ RZ(w0) : column q scaled by RZ diag
    float2 T00 = make_float2( c1 * e0.x,   c1 * e0.y);
    float2 T01 = make_float2(-s1 * e0c.x, -s1 * e0c.y);
    float2 T10 = make_float2( s1 * e0.x,   s1 * e0.y);
    float2 T11 = make_float2( c1 * e0c.x,  c1 * e0c.y);
    // C = RZ(w2) @ T : row p scaled
    float2 e2  = make_float2(c2, -s2);
    float2 e2c = make_float2(c2,  s2);
    g_C[l][i][0] = cmul(e2,  T00);
    g_C[l][i][1] = cmul(e2,  T01);
    g_C[l][i][2] = cmul(e2c, T10);
    g_C[l][i][3] = cmul(e2c, T11);
}

// ---------------- K1/K3: 128x128x8 SGEMM, 8x8 per thread ---------------------
// EPI==0: C = gelu(A@B + bias)          -> writes g_h   (A = x)
// EPI==1: C = resid + A@B + bias        -> writes g_y   (A = g_e, resid = x)
template <int EPI>
__global__ __launch_bounds__(256) void sgemm128(
    const float* __restrict__ A_in, const float* __restrict__ B,
    const float* __restrict__ bias, const float* __restrict__ resid,
    int M, int N, int K)
{
    const float* A = (EPI == 1) ? (const float*)g_e : A_in;
    float*       C = (EPI == 1) ? g_y : g_h;

    __shared__ float As[8][128];
    __shared__ float Bs[8][128];

    int t    = threadIdx.x;
    int brow = blockIdx.y * 128;
    int bcol = blockIdx.x * 128;

    int arow = t >> 1;          // 0..127
    int acol = (t & 1) * 4;     // 0 or 4
    int bro  = t >> 5;          // 0..7
    int bco  = (t & 31) * 4;    // 0..124

    const float* Aptr = A + (size_t)(brow + arow) * K + acol;
    const float* Bptr = B + (size_t)bro * N + bcol + bco;

    float acc[8][8];
#pragma unroll
    for (int r = 0; r < 8; ++r)
#pragma unroll
        for (int c = 0; c < 8; ++c) acc[r][c] = 0.0f;

    int ty = (t >> 4) << 3;
    int tx = (t & 15) << 3;

    for (int k0 = 0; k0 < K; k0 += 8) {
        float4 av = *(const float4*)(Aptr + k0);
        float4 bv = *(const float4*)(Bptr + (size_t)k0 * N);
        As[acol + 0][arow] = av.x;
        As[acol + 1][arow] = av.y;
        As[acol + 2][arow] = av.z;
        As[acol + 3][arow] = av.w;
        *(float4*)&Bs[bro][bco] = bv;
        __syncthreads();

#pragma unroll
        for (int kk = 0; kk < 8; ++kk) {
            float a[8], b[8];
            *(float4*)(a + 0) = *(const float4*)&As[kk][ty];
            *(float4*)(a + 4) = *(const float4*)&As[kk][ty + 4];
            *(float4*)(b + 0) = *(const float4*)&Bs[kk][tx];
            *(float4*)(b + 4) = *(const float4*)&Bs[kk][tx + 4];
#pragma unroll
            for (int r = 0; r < 8; ++r)
#pragma unroll
                for (int c = 0; c < 8; ++c) acc[r][c] += a[r] * b[c];
        }
        __syncthreads();
    }

#pragma unroll
    for (int r = 0; r < 8; ++r) {
        int grow = brow + ty + r;
        size_t base = (size_t)grow * N + bcol + tx;
#pragma unroll
        for (int c = 0; c < 8; ++c) {
            float v = acc[r][c] + bias[bcol + tx + c];
            if (EPI == 0) v = gelu_exact(v);
            else          v = resid[base + c] + v;
            C[base + c] = v;
        }
    }
}

// ---------------- K2: quantum bottleneck, one warp per row -------------------
#define QWARPS 4
__global__ __launch_bounds__(QWARPS * 32) void quantum_kernel(
    const float* __restrict__ W2, const float* __restrict__ b2,
    const float* __restrict__ W3, const float* __restrict__ b3,
    int Brows)
{
    __shared__ float2 st_s[QWARPS][256];
    int warp = threadIdx.x >> 5;
    int lane = threadIdx.x & 31;
    int row  = blockIdx.x * QWARPS + warp;
    if (row >= Brows) return;
    float2* st = st_s[warp];

    // ---- feats_j = h_row . W2[:,j] + b2[j] ----
    const float* hrow = g_h + (size_t)row * H_DIM;
    float fj[8] = {0, 0, 0, 0, 0, 0, 0, 0};
#pragma unroll
    for (int m = 0; m < 8; ++m) {
        int k = lane + 32 * m;
        float hv = hrow[k];
        const float4* w2p = (const float4*)(W2 + (size_t)k * 8);
        float4 wa = w2p[0], wb = w2p[1];
        fj[0] += hv * wa.x; fj[1] += hv * wa.y;
        fj[2] += hv * wa.z; fj[3] += hv * wa.w;
        fj[4] += hv * wb.x; fj[5] += hv * wb.y;
        fj[6] += hv * wb.z; fj[7] += hv * wb.w;
    }
#pragma unroll
    for (int j = 0; j < 8; ++j)
#pragma unroll
        for (int o = 16; o; o >>= 1)
            fj[j] += __shfl_xor_sync(0xffffffffu, fj[j], o);

    float cf[8], sf[8];
#pragma unroll
    for (int j = 0; j < 8; ++j) {
        float f = 0.5f * (fj[j] + b2[j]);
        cf[j] = cosf(f);
        sf[j] = sinf(f);
    }

    // ---- init |0...0> ----
#pragma unroll
    for (int r = 0; r < 8; ++r) st[lane + 32 * r] = make_float2(0.f, 0.f);
    __syncwarp();
    if (lane == 0) st[0] = make_float2(1.f, 0.f);
    __syncwarp();

    // ---- layers ----
    for (int l = 0; l < NL; ++l) {
#pragma unroll
        for (int i = 0; i < NQ; ++i) {
            float2 C00 = g_C[l][i][0], C01 = g_C[l][i][1];
            float2 C10 = g_C[l][i][2], C11 = g_C[l][i][3];
            float c = cf[i], s = sf[i];
            // U = C @ RY(f_i)
            float2 U00 = make_float2(C00.x * c + C01.x * s, C00.y * c + C01.y * s);
            float2 U01 = make_float2(C01.x * c - C00.x * s, C01.y * c - C00.y * s);
            float2 U10 = make_float2(C10.x * c + C11.x * s, C10.y * c + C11.y * s);
            float2 U11 = make_float2(C11.x * c - C10.x * s, C11.y * c - C10.y * s);
            int sbit = 7 - i;
            int stride = 1 << sbit;
#pragma unroll
            for (int r = 0; r < 4; ++r) {
                int p  = lane + 32 * r;
                int i0 = ((p >> sbit) << (sbit + 1)) | (p & (stride - 1));
                int i1 = i0 | stride;
                float2 a = st[i0], b = st[i1];
                st[i0] = cadd(cmul(U00, a), cmul(U01, b));
                st[i1] = cadd(cmul(U10, a), cmul(U11, b));
            }
            __syncwarp();
        }
#pragma unroll
        for (int i = 0; i < NQ; ++i) {
            int tq = (i + 1) & 7;
            int cmask = 1 << (7 - i);
            int tmask = 1 << (7 - tq);
#pragma unroll
            for (int r = 0; r < 8; ++r) {
                int idx = lane + 32 * r;
                if ((idx & cmask) && !(idx & tmask)) {
                    float2 a = st[idx], b = st[idx | tmask];
                    st[idx] = b;
                    st[idx | tmask] = a;
                }
            }
            __syncwarp();
        }
    }

    // ---- z_i = sum p * (+1 if bit==0 else -1) ----
    float zf[8] = {0, 0, 0, 0, 0, 0, 0, 0};
#pragma unroll
    for (int r = 0; r < 8; ++r) {
        int idx = lane + 32 * r;
        float2 a = st[idx];
        float p = a.x * a.x + a.y * a.y;
#pragma unroll
        for (int i = 0; i < 8; ++i)
            zf[i] += ((idx >> (7 - i)) & 1) ? -p : p;
    }
#pragma unroll
    for (int j = 0; j < 8; ++j)
#pragma unroll
        for (int o = 16; o; o >>= 1)
            zf[j] += __shfl_xor_sync(0xffffffffu, zf[j], o);

    // ---- e = gelu(z @ W3 + b3) ----
    float* erow = g_e + (size_t)row * H_DIM;
#pragma unroll
    for (int m = 0; m < 8; ++m) {
        int k = lane + 32 * m;
        float acc = b3[k];
#pragma unroll
        for (int j = 0; j < 8; ++j) acc += zf[j] * W3[j * H_DIM + k];
        erow[k] = gelu_exact(acc);
    }
}

// ---------------- K4: LayerNorm over D=768 -----------------------------------
__global__ __launch_bounds__(256) void ln_kernel(
    const float* __restrict__ gamma, const float* __restrict__ beta,
    float* __restrict__ out)
{
    int row = blockIdx.x;
    const float* yr = g_y + (size_t)row * D_DIM;
    int tid = threadIdx.x;

    float v[3];
    float sum = 0.f, sq = 0.f;
#pragma unroll
    for (int m = 0; m < 3; ++m) {
        v[m] = yr[tid + 256 * m];
        sum += v[m];
        sq  += v[m] * v[m];
    }
#pragma unroll
    for (int o = 16; o; o >>= 1) {
        sum += __shfl_xor_sync(0xffffffffu, sum, o);
        sq  += __shfl_xor_sync(0xffffffffu, sq,  o);
    }
    __shared__ float red[2][8];
    int w = tid >> 5;
    if ((tid & 31) == 0) { red[0][w] = sum; red[1][w] = sq; }
    __syncthreads();
    sum = 0.f; sq = 0.f;
#pragma unroll
    for (int i = 0; i < 8; ++i) { sum += red[0][i]; sq += red[1][i]; }

    float mu  = sum * (1.0f / D_DIM);
    float var = sq * (1.0f / D_DIM) - mu * mu;
    float inv = rsqrtf(var + 1e-5f);

    float* orow = out + (size_t)row * D_DIM;
#pragma unroll
    for (int m = 0; m < 3; ++m) {
        int k = tid + 256 * m;
        orow[k] = gamma[k] * (v[m] - mu) * inv + beta[k];
    }
}

// ---------------- launch ------------------------------------------------------
extern "C" void kernel_launch(void* const* d_in, const int* in_sizes, int n_in,
                              void* d_out, int out_size) {
    const float* x     = (const float*)d_in[0];
    const float* W1    = (const float*)d_in[1];
    const float* b1    = (const float*)d_in[2];
    const float* W2    = (const float*)d_in[3];
    const float* b2    = (const float*)d_in[4];
    const float* qw    = (const float*)d_in[5];
    const float* W3    = (const float*)d_in[6];
    const float* b3    = (const float*)d_in[7];
    const float* W4    = (const float*)d_in[8];
    const float* b4    = (const float*)d_in[9];
    const float* gamma = (const float*)d_in[10];
    const float* beta  = (const float*)d_in[11];
    float* out = (float*)d_out;

    int Brows = in_sizes[0] / D_DIM;   // 16384

    prep_gates<<<1, 32>>>(qw);

    // h = gelu(x @ W1 + b1)   [Brows x 256, K=768]
    dim3 g1(H_DIM / 128, Brows / 128);
    sgemm128<0><<<g1, 256>>>(x, W1, b1, nullptr, Brows, H_DIM, D_DIM);

    // quantum bottleneck -> e  [Brows x 256]
    quantum_kernel<<<Brows / QWARPS, QWARPS * 32>>>(W2, b2, W3, b3, Brows);

    // y = x + e @ W4 + b4     [Brows x 768, K=256]
    dim3 g2(D_DIM / 128, Brows / 128);
    sgemm128<1><<<g2, 256>>>(nullptr, W4, b4, x, Brows, D_DIM, H_DIM);

    // out = LN(y) * gamma + beta
    ln_kernel<<<Brows, 256>>>(gamma, beta, out);
}

// round 2
// speedup vs baseline: 1.0364x; 1.0364x over previous
#include <cuda_runtime.h>

#define BATCH   16384
#define D_DIM   768
#define H_DIM   256
#define NQ      8
#define NL      2

// ---------------- scratch (device globals; no runtime allocation) -----------
__device__ float  g_h[BATCH * H_DIM];   // gelu(x@W1+b1)
__device__ float  g_e[BATCH * H_DIM];   // gelu(z@W3+b3)
__device__ float  g_y[BATCH * D_DIM];   // x + e@W4 + b4 (pre-LN)
__device__ float2 g_C[NL][NQ][4];       // variational 2x2 complex per (layer,wire)

// ---------------- helpers ----------------------------------------------------
__device__ __forceinline__ float2 cmul(float2 a, float2 b) {
    return make_float2(a.x * b.x - a.y * b.y, a.x * b.y + a.y * b.x);
}
__device__ __forceinline__ float2 cadd(float2 a, float2 b) {
    return make_float2(a.x + b.x, a.y + b.y);
}
__device__ __forceinline__ float gelu_exact(float v) {
    return 0.5f * v * (1.0f + erff(v * 0.70710678118654752f));
}

// packed fp32x2 FMA (sm_100+): d.lo += a.lo*b.lo ; d.hi += a.hi*b.hi
__device__ __forceinline__ unsigned long long pack2(float lo, float hi) {
    unsigned long long r;
    asm("mov.b64 %0, {%1, %2};" : "=l"(r) : "f"(lo), "f"(hi));
    return r;
}
__device__ __forceinline__ void ffma2(unsigned long long& d,
                                      unsigned long long a,
                                      unsigned long long b) {
    asm("fma.rn.f32x2 %0, %1, %2, %0;" : "+l"(d) : "l"(a), "l"(b));
}

// ---------------- K0: precompute C[l][i] = RZ(w2) @ RY(w1) @ RZ(w0) ---------
__global__ void prep_gates(const float* __restrict__ qw) {
    int t = threadIdx.x;
    if (t >= NL * NQ) return;
    int l = t / NQ, i = t % NQ;
    float w0 = qw[(l * NQ + i) * 3 + 0];
    float w1 = qw[(l * NQ + i) * 3 + 1];
    float w2 = qw[(l * NQ + i) * 3 + 2];
    float c0 = cosf(0.5f * w0), s0 = sinf(0.5f * w0);
    float c1 = cosf(0.5f * w1), s1 = sinf(0.5f * w1);
    float c2 = cosf(0.5f * w2), s2 = sinf(0.5f * w2);
    float2 e0  = make_float2(c0, -s0);  // exp(-i w0/2)
    float2 e0c = make_float2(c0,  s0);
    // T = RY(w1) @ RZ(w0)
    float2 T00 = make_float2( c1 * e0.x,   c1 * e0.y);
    float2 T01 = make_float2(-s1 * e0c.x, -s1 * e0c.y);
    float2 T10 = make_float2( s1 * e0.x,   s1 * e0.y);
    float2 T11 = make_float2( c1 * e0c.x,  c1 * e0c.y);
    // C = RZ(w2) @ T
    float2 e2  = make_float2(c2, -s2);
    float2 e2c = make_float2(c2,  s2);
    g_C[l][i][0] = cmul(e2,  T00);
    g_C[l][i][1] = cmul(e2,  T01);
    g_C[l][i][2] = cmul(e2c, T10);
    g_C[l][i][3] = cmul(e2c, T11);
}

// ---------------- K1/K3: 128x128x8 SGEMM, 8x8 per thread, FFMA2 + dbuf -------
// EPI==0: C = gelu(A@B + bias)          -> writes g_h   (A = x)
// EPI==1: C = resid + A@B + bias        -> writes g_y   (A = g_e, resid = x)
template <int EPI>
__global__ __launch_bounds__(256) void sgemm128(
    const float* __restrict__ A_in, const float* __restrict__ B,
    const float* __restrict__ bias, const float* __restrict__ resid,
    int M, int N, int K)
{
    const float* A = (EPI == 1) ? (const float*)g_e : A_in;
    float*       C = (EPI == 1) ? g_y : g_h;

    __shared__ float As[2][8][128];
    __shared__ float Bs[2][8][128];

    int t    = threadIdx.x;
    int brow = blockIdx.y * 128;
    int bcol = blockIdx.x * 128;

    int arow = t >> 1;          // 0..127
    int acol = (t & 1) * 4;     // 0 or 4
    int bro  = t >> 5;          // 0..7
    int bco  = (t & 31) * 4;    // 0..124

    const float* Aptr = A + (size_t)(brow + arow) * K + acol;
    const float* Bptr = B + (size_t)bro * N + bcol + bco;

    unsigned long long acc2[8][4];
#pragma unroll
    for (int r = 0; r < 8; ++r)
#pragma unroll
        for (int c = 0; c < 4; ++c) acc2[r][c] = 0ull;

    int ty = (t >> 4) << 3;
    int tx = (t & 15) << 3;

    // preload panel 0
    {
        float4 av = *(const float4*)(Aptr);
        float4 bv = *(const float4*)(Bptr);
        As[0][acol + 0][arow] = av.x;
        As[0][acol + 1][arow] = av.y;
        As[0][acol + 2][arow] = av.z;
        As[0][acol + 3][arow] = av.w;
        *(float4*)&Bs[0][bro][bco] = bv;
    }
    __syncthreads();

    for (int k0 = 0; k0 < K; k0 += 8) {
        int cur = (k0 >> 3) & 1;
        int nxt = cur ^ 1;
        bool more = (k0 + 8) < K;

        float4 av, bv;
        if (more) {
            av = *(const float4*)(Aptr + k0 + 8);
            bv = *(const float4*)(Bptr + (size_t)(k0 + 8) * N);
        }

#pragma unroll
        for (int kk = 0; kk < 8; ++kk) {
            float a[8];
            *(float4*)(a + 0) = *(const float4*)&As[cur][kk][ty];
            *(float4*)(a + 4) = *(const float4*)&As[cur][kk][ty + 4];
            unsigned long long b2[4];
            {
                longlong2 p0 = *(const longlong2*)&Bs[cur][kk][tx];
                longlong2 p1 = *(const longlong2*)&Bs[cur][kk][tx + 4];
                b2[0] = (unsigned long long)p0.x;
                b2[1] = (unsigned long long)p0.y;
                b2[2] = (unsigned long long)p1.x;
                b2[3] = (unsigned long long)p1.y;
            }
#pragma unroll
            for (int r = 0; r < 8; ++r) {
                unsigned long long ar = pack2(a[r], a[r]);
#pragma unroll
                for (int c = 0; c < 4; ++c) ffma2(acc2[r][c], ar, b2[c]);
            }
        }

        if (more) {
            As[nxt][acol + 0][arow] = av.x;
            As[nxt][acol + 1][arow] = av.y;
            As[nxt][acol + 2][arow] = av.z;
            As[nxt][acol + 3][arow] = av.w;
            *(float4*)&Bs[nxt][bro][bco] = bv;
        }
        __syncthreads();
    }

#pragma unroll
    for (int r = 0; r < 8; ++r) {
        int grow = brow + ty + r;
        size_t base = (size_t)grow * N + bcol + tx;
#pragma unroll
        for (int c = 0; c < 4; ++c) {
            float2 f = *(float2*)&acc2[r][c];
            float v0 = f.x + bias[bcol + tx + 2 * c + 0];
            float v1 = f.y + bias[bcol + tx + 2 * c + 1];
            if (EPI == 0) {
                v0 = gelu_exact(v0);
                v1 = gelu_exact(v1);
            } else {
                v0 += resid[base + 2 * c + 0];
                v1 += resid[base + 2 * c + 1];
            }
            C[base + 2 * c + 0] = v0;
            C[base + 2 * c + 1] = v1;
        }
    }
}

// ---------------- K2: quantum bottleneck, one warp per row -------------------
#define QWARPS 4
__global__ __launch_bounds__(QWARPS * 32) void quantum_kernel(
    const float* __restrict__ W2, const float* __restrict__ b2,
    const float* __restrict__ W3, const float* __restrict__ b3,
    int Brows)
{
    __shared__ float2 st_s[QWARPS][256];
    int warp = threadIdx.x >> 5;
    int lane = threadIdx.x & 31;
    int row  = blockIdx.x * QWARPS + warp;
    if (row >= Brows) return;
    float2* st = st_s[warp];

    // ---- feats_j = h_row . W2[:,j] + b2[j] ----
    const float* hrow = g_h + (size_t)row * H_DIM;
    float fj[8] = {0, 0, 0, 0, 0, 0, 0, 0};
#pragma unroll
    for (int m = 0; m < 8; ++m) {
        int k = lane + 32 * m;
        float hv = hrow[k];
        const float4* w2p = (const float4*)(W2 + (size_t)k * 8);
        float4 wa = w2p[0], wb = w2p[1];
        fj[0] += hv * wa.x; fj[1] += hv * wa.y;
        fj[2] += hv * wa.z; fj[3] += hv * wa.w;
        fj[4] += hv * wb.x; fj[5] += hv * wb.y;
        fj[6] += hv * wb.z; fj[7] += hv * wb.w;
    }
#pragma unroll
    for (int j = 0; j < 8; ++j)
#pragma unroll
        for (int o = 16; o; o >>= 1)
            fj[j] += __shfl_xor_sync(0xffffffffu, fj[j], o);

    float cf[8], sf[8];
#pragma unroll
    for (int j = 0; j < 8; ++j) {
        float f = 0.5f * (fj[j] + b2[j]);
        cf[j] = cosf(f);
        sf[j] = sinf(f);
    }

    // ---- init |0...0> ----
#pragma unroll
    for (int r = 0; r < 8; ++r) st[lane + 32 * r] = make_float2(0.f, 0.f);
    __syncwarp();
    if (lane == 0) st[0] = make_float2(1.f, 0.f);
    __syncwarp();

    // ---- layers ----
    for (int l = 0; l < NL; ++l) {
#pragma unroll
        for (int i = 0; i < NQ; ++i) {
            float2 C00 = g_C[l][i][0], C01 = g_C[l][i][1];
            float2 C10 = g_C[l][i][2], C11 = g_C[l][i][3];
            float c = cf[i], s = sf[i];
            // U = C @ RY(f_i)
            float2 U00 = make_float2(C00.x * c + C01.x * s, C00.y * c + C01.y * s);
            float2 U01 = make_float2(C01.x * c - C00.x * s, C01.y * c - C00.y * s);
            float2 U10 = make_float2(C10.x * c + C11.x * s, C10.y * c + C11.y * s);
            float2 U11 = make_float2(C11.x * c - C10.x * s, C11.y * c - C10.y * s);
            int sbit = 7 - i;
            int stride = 1 << sbit;
#pragma unroll
            for (int r = 0; r < 4; ++r) {
                int p  = lane + 32 * r;
                int i0 = ((p >> sbit) << (sbit + 1)) | (p & (stride - 1));
                int i1 = i0 | stride;
                float2 a = st[i0], b = st[i1];
                st[i0] = cadd(cmul(U00, a), cmul(U01, b));
                st[i1] = cadd(cmul(U10, a), cmul(U11, b));
            }
            __syncwarp();
        }
#pragma unroll
        for (int i = 0; i < NQ; ++i) {
            int tq = (i + 1) & 7;
            int cmask = 1 << (7 - i);
            int tmask = 1 << (7 - tq);
#pragma unroll
            for (int r = 0; r < 8; ++r) {
                int idx = lane + 32 * r;
                if ((idx & cmask) && !(idx & tmask)) {
                    float2 a = st[idx], b = st[idx | tmask];
                    st[idx] = b;
                    st[idx | tmask] = a;
                }
            }
            __syncwarp();
        }
    }

    // ---- z_i = sum p * (+1 if bit==0 else -1) ----
    float zf[8] = {0, 0, 0, 0, 0, 0, 0, 0};
#pragma unroll
    for (int r = 0; r < 8; ++r) {
        int idx = lane + 32 * r;
        float2 a = st[idx];
        float p = a.x * a.x + a.y * a.y;
#pragma unroll
        for (int i = 0; i < 8; ++i)
            zf[i] += ((idx >> (7 - i)) & 1) ? -p : p;
    }
#pragma unroll
    for (int j = 0; j < 8; ++j)
#pragma unroll
        for (int o = 16; o; o >>= 1)
            zf[j] += __shfl_xor_sync(0xffffffffu, zf[j], o);

    // ---- e = gelu(z @ W3 + b3) ----
    float* erow = g_e + (size_t)row * H_DIM;
#pragma unroll
    for (int m = 0; m < 8; ++m) {
        int k = lane + 32 * m;
        float acc = b3[k];
#pragma unroll
        for (int j = 0; j < 8; ++j) acc += zf[j] * W3[j * H_DIM + k];
        erow[k] = gelu_exact(acc);
    }
}

// ---------------- K4: LayerNorm over D=768 -----------------------------------
__global__ __launch_bounds__(256) void ln_kernel(
    const float* __restrict__ gamma, const float* __restrict__ beta,
    float* __restrict__ out)
{
    int row = blockIdx.x;
    const float* yr = g_y + (size_t)row * D_DIM;
    int tid = threadIdx.x;

    float v[3];
    float sum = 0.f, sq = 0.f;
#pragma unroll
    for (int m = 0; m < 3; ++m) {
        v[m] = yr[tid + 256 * m];
        sum += v[m];
        sq  += v[m] * v[m];
    }
#pragma unroll
    for (int o = 16; o; o >>= 1) {
        sum += __shfl_xor_sync(0xffffffffu, sum, o);
        sq  += __shfl_xor_sync(0xffffffffu, sq,  o);
    }
    __shared__ float red[2][8];
    int w = tid >> 5;
    if ((tid & 31) == 0) { red[0][w] = sum; red[1][w] = sq; }
    __syncthreads();
    sum = 0.f; sq = 0.f;
#pragma unroll
    for (int i = 0; i < 8; ++i) { sum += red[0][i]; sq += red[1][i]; }

    float mu  = sum * (1.0f / D_DIM);
    float var = sq * (1.0f / D_DIM) - mu * mu;
    float inv = rsqrtf(var + 1e-5f);

    float* orow = out + (size_t)row * D_DIM;
#pragma unroll
    for (int m = 0; m < 3; ++m) {
        int k = tid + 256 * m;
        orow[k] = gamma[k] * (v[m] - mu) * inv + beta[k];
    }
}

// ---------------- launch ------------------------------------------------------
extern "C" void kernel_launch(void* const* d_in, const int* in_sizes, int n_in,
                              void* d_out, int out_size) {
    const float* x     = (const float*)d_in[0];
    const float* W1    = (const float*)d_in[1];
    const float* b1    = (const float*)d_in[2];
    const float* W2    = (const float*)d_in[3];
    const float* b2    = (const float*)d_in[4];
    const float* qw    = (const float*)d_in[5];
    const float* W3    = (const float*)d_in[6];
    const float* b3    = (const float*)d_in[7];
    const float* W4    = (const float*)d_in[8];
    const float* b4    = (const float*)d_in[9];
    const float* gamma = (const float*)d_in[10];
    const float* beta  = (const float*)d_in[11];
    float* out = (float*)d_out;

    int Brows = in_sizes[0] / D_DIM;   // 16384

    prep_gates<<<1, 32>>>(qw);

    // h = gelu(x @ W1 + b1)   [Brows x 256, K=768]
    dim3 g1(H_DIM / 128, Brows / 128);
    sgemm128<0><<<g1, 256>>>(x, W1, b1, nullptr, Brows, H_DIM, D_DIM);

    // quantum bottleneck -> e  [Brows x 256]
    quantum_kernel<<<Brows / QWARPS, QWARPS * 32>>>(W2, b2, W3, b3, Brows);

    // y = x + e @ W4 + b4     [Brows x 768, K=256]
    dim3 g2(D_DIM / 128, Brows / 128);
    sgemm128<1><<<g2, 256>>>(nullptr, W4, b4, x, Brows, D_DIM, H_DIM);

    // out = LN(y) * gamma + beta
    ln_kernel<<<Brows, 256>>>(gamma, beta, out);
}

// round 4
// speedup vs baseline: 1.6826x; 1.6235x over previous
#include <cuda_runtime.h>
#include <cuda_bf16.h>
#include <cstdint>

#define BATCH   16384
#define D_DIM   768
#define H_DIM   256
#define NQ      8
#define NL      2

// ---------------- scratch (device globals; no runtime allocation) -----------
__device__ float  g_h[BATCH * H_DIM];   // gelu(x@W1+b1)
__device__ float  g_e[BATCH * H_DIM];   // gelu(z@W3+b3)
__device__ float  g_y[BATCH * D_DIM];   // x + e@W4 + b4 (pre-LN)
__device__ float2 g_C[NL][NQ][4];       // variational 2x2 complex per (layer,wire)

// ---------------- helpers ----------------------------------------------------
__device__ __forceinline__ float2 cmul(float2 a, float2 b) {
    return make_float2(a.x * b.x - a.y * b.y, a.x * b.y + a.y * b.x);
}
__device__ __forceinline__ float2 cadd(float2 a, float2 b) {
    return make_float2(a.x + b.x, a.y + b.y);
}
__device__ __forceinline__ float gelu_exact(float v) {
    return 0.5f * v * (1.0f + erff(v * 0.70710678118654752f));
}
__device__ __forceinline__ uint32_t smem_to_u32(const void* p) {
    uint32_t a;
    asm("{ .reg .u64 t; cvta.to.shared.u64 t, %1; cvt.u32.u64 %0, t; }"
        : "=r"(a) : "l"(p));
    return a;
}

// hi/lo bf16 split of a float4, packed as 4+4 bf16 (8 bytes each)
__device__ __forceinline__ void cvt4_hilo(float4 v, uint2& hi, uint2& lo) {
    __nv_bfloat16 h0 = __float2bfloat16(v.x), h1 = __float2bfloat16(v.y);
    __nv_bfloat16 h2 = __float2bfloat16(v.z), h3 = __float2bfloat16(v.w);
    __nv_bfloat16 l0 = __float2bfloat16(v.x - __bfloat162float(h0));
    __nv_bfloat16 l1 = __float2bfloat16(v.y - __bfloat162float(h1));
    __nv_bfloat16 l2 = __float2bfloat16(v.z - __bfloat162float(h2));
    __nv_bfloat16 l3 = __float2bfloat16(v.w - __bfloat162float(h3));
    hi.x = (uint32_t)__bfloat16_as_ushort(h0) | ((uint32_t)__bfloat16_as_ushort(h1) << 16);
    hi.y = (uint32_t)__bfloat16_as_ushort(h2) | ((uint32_t)__bfloat16_as_ushort(h3) << 16);
    lo.x = (uint32_t)__bfloat16_as_ushort(l0) | ((uint32_t)__bfloat16_as_ushort(l1) << 16);
    lo.y = (uint32_t)__bfloat16_as_ushort(l2) | ((uint32_t)__bfloat16_as_ushort(l3) << 16);
}

__device__ __forceinline__ void ldsm_x4(uint32_t addr, uint32_t* r) {
    asm volatile("ldmatrix.sync.aligned.m8n8.x4.shared.b16 {%0,%1,%2,%3}, [%4];"
        : "=r"(r[0]), "=r"(r[1]), "=r"(r[2]), "=r"(r[3]) : "r"(addr));
}
__device__ __forceinline__ void ldsm_x4t(uint32_t addr, uint32_t* r) {
    asm volatile("ldmatrix.sync.aligned.m8n8.x4.trans.shared.b16 {%0,%1,%2,%3}, [%4];"
        : "=r"(r[0]), "=r"(r[1]), "=r"(r[2]), "=r"(r[3]) : "r"(addr));
}
__device__ __forceinline__ void mma16816(float* d, const uint32_t* a,
                                         uint32_t b0, uint32_t b1) {
    asm volatile(
        "mma.sync.aligned.m16n8k16.row.col.f32.bf16.bf16.f32 "
        "{%0,%1,%2,%3}, {%4,%5,%6,%7}, {%8,%9}, {%0,%1,%2,%3};"
        : "+f"(d[0]), "+f"(d[1]), "+f"(d[2]), "+f"(d[3])
        : "r"(a[0]), "r"(a[1]), "r"(a[2]), "r"(a[3]), "r"(b0), "r"(b1));
}

// ---------------- K0: precompute C[l][i] -------------------------------------
__global__ void prep_gates(const float* __restrict__ qw) {
    int t = threadIdx.x;
    if (t >= NL * NQ) return;
    int l = t / NQ, i = t % NQ;
    float w0 = qw[(l * NQ + i) * 3 + 0];
    float w1 = qw[(l * NQ + i) * 3 + 1];
    float w2 = qw[(l * NQ + i) * 3 + 2];
    float c0 = cosf(0.5f * w0), s0 = sinf(0.5f * w0);
    float c1 = cosf(0.5f * w1), s1 = sinf(0.5f * w1);
    float c2 = cosf(0.5f * w2), s2 = sinf(0.5f * w2);
    float2 e0  = make_float2(c0, -s0);
    float2 e0c = make_float2(c0,  s0);
    float2 T00 = make_float2( c1 * e0.x,   c1 * e0.y);
    float2 T01 = make_float2(-s1 * e0c.x, -s1 * e0c.y);
    float2 T10 = make_float2( s1 * e0.x,   s1 * e0.y);
    float2 T11 = make_float2( c1 * e0c.x,  c1 * e0c.y);
    float2 e2  = make_float2(c2, -s2);
    float2 e2c = make_float2(c2,  s2);
    g_C[l][i][0] = cmul(e2,  T00);
    g_C[l][i][1] = cmul(e2,  T01);
    g_C[l][i][2] = cmul(e2c, T10);
    g_C[l][i][3] = cmul(e2c, T11);
}

// ---------------- bf16 hi/lo tensor-core GEMM --------------------------------
// CTA tile 128(M) x 128(N), K-chunk 32, double-buffered smem.
// EPI==0: C = gelu(A@B + bias)    -> g_h   (A = x)
// EPI==1: C = resid + A@B + bias  -> g_y   (A = g_e)
#define SM_AH 0
#define SM_AL 16384
#define SM_BH 32768
#define SM_BL 49152
#define SM_TOT 65536

template <int EPI>
__global__ __launch_bounds__(256) void mma_gemm(
    const float* __restrict__ A_in, const float* __restrict__ Bg,
    const float* __restrict__ bias, const float* __restrict__ resid,
    int Mtot, int N, int K)
{
    extern __shared__ char smem[];
    const float* A = (EPI == 1) ? (const float*)g_e : A_in;
    float* Cout    = (EPI == 1) ? g_y : g_h;

    uint32_t sb = smem_to_u32(smem);
    int t = threadIdx.x, wid = t >> 5, lane = t & 31;
    int brow = blockIdx.y * 128, bcol = blockIdx.x * 128;
    int warpM = (wid & 3) * 32, warpN = (wid >> 2) * 64;
    int g = lane >> 2, c2 = lane & 3;

    const float* Ag = A + (size_t)brow * K;
    const float* Bp = Bg + bcol;

    float acc[2][8][4];
#pragma unroll
    for (int i = 0; i < 2; ++i)
#pragma unroll
        for (int j = 0; j < 8; ++j)
#pragma unroll
            for (int k = 0; k < 4; ++k) acc[i][j][k] = 0.f;

    // per-thread fill coordinates
    int fa_m = t >> 3, fa_q = t & 7;     // A: m = i*32 + fa_m, kbyte = fa_q*8
    int fb_k = t >> 5, fb_n = t & 31;    // B: k = i*8 + fb_k, nbyte = fb_n*8

    float4 va[4], vb[4];
    int NC = K / 32;

    // ---- preload chunk 0 ----
#pragma unroll
    for (int i = 0; i < 4; ++i)
        va[i] = *(const float4*)(Ag + (size_t)(i * 32 + fa_m) * K + fa_q * 4);
#pragma unroll
    for (int i = 0; i < 4; ++i)
        vb[i] = *(const float4*)(Bp + (size_t)(i * 8 + fb_k) * N + fb_n * 4);
#pragma unroll
    for (int i = 0; i < 4; ++i) {
        int m = i * 32 + fa_m;
        uint2 hi, lo; cvt4_hilo(va[i], hi, lo);
        uint32_t off = (uint32_t)((m * 64 + fa_q * 8) ^ ((m & 7) << 4));
        *(uint2*)(smem + SM_AH + off) = hi;
        *(uint2*)(smem + SM_AL + off) = lo;
    }
#pragma unroll
    for (int i = 0; i < 4; ++i) {
        int k = i * 8 + fb_k;
        uint2 hi, lo; cvt4_hilo(vb[i], hi, lo);
        uint32_t off = (uint32_t)((k * 256 + fb_n * 8) ^ ((k & 7) << 4));
        *(uint2*)(smem + SM_BH + off) = hi;
        *(uint2*)(smem + SM_BL + off) = lo;
    }
    __syncthreads();

    for (int c = 0; c < NC; ++c) {
        int buf = c & 1;
        bool more = (c + 1) < NC;
        if (more) {
            int k0 = (c + 1) * 32;
#pragma unroll
            for (int i = 0; i < 4; ++i)
                va[i] = *(const float4*)(Ag + (size_t)(i * 32 + fa_m) * K + k0 + fa_q * 4);
#pragma unroll
            for (int i = 0; i < 4; ++i)
                vb[i] = *(const float4*)(Bp + (size_t)(k0 + i * 8 + fb_k) * N + fb_n * 4);
        }

        uint32_t abase_h = sb + SM_AH + buf * 8192;
        uint32_t abase_l = sb + SM_AL + buf * 8192;
        uint32_t bbase_h = sb + SM_BH + buf * 8192;
        uint32_t bbase_l = sb + SM_BL + buf * 8192;

#pragma unroll
        for (int s = 0; s < 2; ++s) {
            uint32_t ah[2][4], al[2][4];
#pragma unroll
            for (int mf = 0; mf < 2; ++mf) {
                int m = warpM + mf * 16 + (lane & 15);
                uint32_t kb = (uint32_t)(s * 32 + (lane >> 4) * 16);
                uint32_t off = (uint32_t)((m * 64 + kb) ^ ((m & 7) << 4));
                ldsm_x4(abase_h + off, ah[mf]);
                ldsm_x4(abase_l + off, al[mf]);
            }
#pragma unroll
            for (int n16 = 0; n16 < 4; ++n16) {
                uint32_t bh[4], bl[4];
                int kk = s * 16 + (lane & 15);
                uint32_t nb = (uint32_t)(warpN + n16 * 16 + (lane >> 4) * 8) * 2;
                uint32_t off = (uint32_t)((kk * 256 + nb) ^ ((kk & 7) << 4));
                ldsm_x4t(bbase_h + off, bh);
                ldsm_x4t(bbase_l + off, bl);
#pragma unroll
                for (int half = 0; half < 2; ++half) {
                    int nf = n16 * 2 + half;
#pragma unroll
                    for (int mf = 0; mf < 2; ++mf) {
                        mma16816(acc[mf][nf], ah[mf], bh[half * 2], bh[half * 2 + 1]);
                        mma16816(acc[mf][nf], ah[mf], bl[half * 2], bl[half * 2 + 1]);
                        mma16816(acc[mf][nf], al[mf], bh[half * 2], bh[half * 2 + 1]);
                    }
                }
            }
        }

        if (more) {
            int nbuf = buf ^ 1;
#pragma unroll
            for (int i = 0; i < 4; ++i) {
                int m = i * 32 + fa_m;
                uint2 hi, lo; cvt4_hilo(va[i], hi, lo);
                uint32_t off = (uint32_t)((m * 64 + fa_q * 8) ^ ((m & 7) << 4));
                *(uint2*)(smem + SM_AH + nbuf * 8192 + off) = hi;
                *(uint2*)(smem + SM_AL + nbuf * 8192 + off) = lo;
            }
#pragma unroll
            for (int i = 0; i < 4; ++i) {
                int k = i * 8 + fb_k;
                uint2 hi, lo; cvt4_hilo(vb[i], hi, lo);
                uint32_t off = (uint32_t)((k * 256 + fb_n * 8) ^ ((k & 7) << 4));
                *(uint2*)(smem + SM_BH + nbuf * 8192 + off) = hi;
                *(uint2*)(smem + SM_BL + nbuf * 8192 + off) = lo;
            }
            __syncthreads();
        }
    }

    // ---- epilogue ----
#pragma unroll
    for (int mf = 0; mf < 2; ++mf) {
        int r0 = brow + warpM + mf * 16 + g;
#pragma unroll
        for (int nf = 0; nf < 8; ++nf) {
            int col = bcol + warpN + nf * 8 + c2 * 2;
            float bv0 = bias[col], bv1 = bias[col + 1];
            float v0 = acc[mf][nf][0] + bv0;
            float v1 = acc[mf][nf][1] + bv1;
            float v2 = acc[mf][nf][2] + bv0;
            float v3 = acc[mf][nf][3] + bv1;
            size_t o0 = (size_t)r0 * N + col;
            size_t o1 = o0 + (size_t)8 * N;
            if (EPI == 0) {
                v0 = gelu_exact(v0); v1 = gelu_exact(v1);
                v2 = gelu_exact(v2); v3 = gelu_exact(v3);
            } else {
                float2 ra = *(const float2*)(resid + o0);
                float2 rb = *(const float2*)(resid + o1);
                v0 += ra.x; v1 += ra.y; v2 += rb.x; v3 += rb.y;
            }
            *(float2*)(Cout + o0) = make_float2(v0, v1);
            *(float2*)(Cout + o1) = make_float2(v2, v3);
        }
    }
}

// ---------------- K2: quantum bottleneck, one warp per row -------------------
#define QWARPS 4
__global__ __launch_bounds__(QWARPS * 32) void quantum_kernel(
    const float* __restrict__ W2, const float* __restrict__ b2,
    const float* __restrict__ W3, const float* __restrict__ b3,
    int Brows)
{
    __shared__ float2 st_s[QWARPS][256];
    int warp = threadIdx.x >> 5;
    int lane = threadIdx.x & 31;
    int row  = blockIdx.x * QWARPS + warp;
    if (row >= Brows) return;
    float2* st = st_s[warp];

    const float* hrow = g_h + (size_t)row * H_DIM;
    float fj[8] = {0, 0, 0, 0, 0, 0, 0, 0};
#pragma unroll
    for (int m = 0; m < 8; ++m) {
        int k = lane + 32 * m;
        float hv = hrow[k];
        const float4* w2p = (const float4*)(W2 + (size_t)k * 8);
        float4 wa = w2p[0], wb = w2p[1];
        fj[0] += hv * wa.x; fj[1] += hv * wa.y;
        fj[2] += hv * wa.z; fj[3] += hv * wa.w;
        fj[4] += hv * wb.x; fj[5] += hv * wb.y;
        fj[6] += hv * wb.z; fj[7] += hv * wb.w;
    }
#pragma unroll
    for (int j = 0; j < 8; ++j)
#pragma unroll
        for (int o = 16; o; o >>= 1)
            fj[j] += __shfl_xor_sync(0xffffffffu, fj[j], o);

    float cf[8], sf[8];
#pragma unroll
    for (int j = 0; j < 8; ++j) {
        float f = 0.5f * (fj[j] + b2[j]);
        cf[j] = cosf(f);
        sf[j] = sinf(f);
    }

#pragma unroll
    for (int r = 0; r < 8; ++r) st[lane + 32 * r] = make_float2(0.f, 0.f);
    __syncwarp();
    if (lane == 0) st[0] = make_float2(1.f, 0.f);
    __syncwarp();

    for (int l = 0; l < NL; ++l) {
#pragma unroll
        for (int i = 0; i < NQ; ++i) {
            float2 C00 = g_C[l][i][0], C01 = g_C[l][i][1];
            float2 C10 = g_C[l][i][2], C11 = g_C[l][i][3];
            float c = cf[i], s = sf[i];
            float2 U00 = make_float2(C00.x * c + C01.x * s, C00.y * c + C01.y * s);
            float2 U01 = make_float2(C01.x * c - C00.x * s, C01.y * c - C00.y * s);
            float2 U10 = make_float2(C10.x * c + C11.x * s, C10.y * c + C11.y * s);
            float2 U11 = make_float2(C11.x * c - C10.x * s, C11.y * c - C10.y * s);
            int sbit = 7 - i;
            int stride = 1 << sbit;
#pragma unroll
            for (int r = 0; r < 4; ++r) {
                int p  = lane + 32 * r;
                int i0 = ((p >> sbit) << (sbit + 1)) | (p & (stride - 1));
                int i1 = i0 | stride;
                float2 a = st[i0], b = st[i1];
                st[i0] = cadd(cmul(U00, a), cmul(U01, b));
                st[i1] = cadd(cmul(U10, a), cmul(U11, b));
            }
            __syncwarp();
        }
#pragma unroll
        for (int i = 0; i < NQ; ++i) {
            int tq = (i + 1) & 7;
            int cmask = 1 << (7 - i);
            int tmask = 1 << (7 - tq);
#pragma unroll
            for (int r = 0; r < 8; ++r) {
                int idx = lane + 32 * r;
                if ((idx & cmask) && !(idx & tmask)) {
                    float2 a = st[idx], b = st[idx | tmask];
                    st[idx] = b;
                    st[idx | tmask] = a;
                }
            }
            __syncwarp();
        }
    }

    float zf[8] = {0, 0, 0, 0, 0, 0, 0, 0};
#pragma unroll
    for (int r = 0; r < 8; ++r) {
        int idx = lane + 32 * r;
        float2 a = st[idx];
        float p = a.x * a.x + a.y * a.y;
#pragma unroll
        for (int i = 0; i < 8; ++i)
            zf[i] += ((idx >> (7 - i)) & 1) ? -p : p;
    }
#pragma unroll
    for (int j = 0; j < 8; ++j)
#pragma unroll
        for (int o = 16; o; o >>= 1)
            zf[j] += __shfl_xor_sync(0xffffffffu, zf[j], o);

    float* erow = g_e + (size_t)row * H_DIM;
#pragma unroll
    for (int m = 0; m < 8; ++m) {
        int k = lane + 32 * m;
        float acc = b3[k];
#pragma unroll
        for (int j = 0; j < 8; ++j) acc += zf[j] * W3[j * H_DIM + k];
        erow[k] = gelu_exact(acc);
    }
}

// ---------------- K4: LayerNorm over D=768 -----------------------------------
__global__ __launch_bounds__(256) void ln_kernel(
    const float* __restrict__ gamma, const float* __restrict__ beta,
    float* __restrict__ out)
{
    int row = blockIdx.x;
    const float* yr = g_y + (size_t)row * D_DIM;
    int tid = threadIdx.x;

    float v[3];
    float sum = 0.f, sq = 0.f;
#pragma unroll
    for (int m = 0; m < 3; ++m) {
        v[m] = yr[tid + 256 * m];
        sum += v[m];
        sq  += v[m] * v[m];
    }
#pragma unroll
    for (int o = 16; o; o >>= 1) {
        sum += __shfl_xor_sync(0xffffffffu, sum, o);
        sq  += __shfl_xor_sync(0xffffffffu, sq,  o);
    }
    __shared__ float red[2][8];
    int w = tid >> 5;
    if ((tid & 31) == 0) { red[0][w] = sum; red[1][w] = sq; }
    __syncthreads();
    sum = 0.f; sq = 0.f;
#pragma unroll
    for (int i = 0; i < 8; ++i) { sum += red[0][i]; sq += red[1][i]; }

    float mu  = sum * (1.0f / D_DIM);
    float var = sq * (1.0f / D_DIM) - mu * mu;
    float inv = rsqrtf(var + 1e-5f);

    float* orow = out + (size_t)row * D_DIM;
#pragma unroll
    for (int m = 0; m < 3; ++m) {
        int k = tid + 256 * m;
        orow[k] = gamma[k] * (v[m] - mu) * inv + beta[k];
    }
}

// ---------------- launch ------------------------------------------------------
extern "C" void kernel_launch(void* const* d_in, const int* in_sizes, int n_in,
                              void* d_out, int out_size) {
    const float* x     = (const float*)d_in[0];
    const float* W1    = (const float*)d_in[1];
    const float* b1    = (const float*)d_in[2];
    const float* W2    = (const float*)d_in[3];
    const float* b2    = (const float*)d_in[4];
    const float* qw    = (const float*)d_in[5];
    const float* W3    = (const float*)d_in[6];
    const float* b3    = (const float*)d_in[7];
    const float* W4    = (const float*)d_in[8];
    const float* b4    = (const float*)d_in[9];
    const float* gamma = (const float*)d_in[10];
    const float* beta  = (const float*)d_in[11];
    float* out = (float*)d_out;

    int Brows = in_sizes[0] / D_DIM;   // 16384

    cudaFuncSetAttribute(mma_gemm<0>, cudaFuncAttributeMaxDynamicSharedMemorySize, SM_TOT);
    cudaFuncSetAttribute(mma_gemm<1>, cudaFuncAttributeMaxDynamicSharedMemorySize, SM_TOT);

    prep_gates<<<1, 32>>>(qw);

    // h = gelu(x @ W1 + b1)   [Brows x 256, K=768]
    dim3 g1(H_DIM / 128, Brows / 128);          // (2, 128)
    mma_gemm<0><<<g1, 256, SM_TOT>>>(x, W1, b1, nullptr, Brows, H_DIM, D_DIM);

    // quantum bottleneck -> e  [Brows x 256]
    quantum_kernel<<<Brows / QWARPS, QWARPS * 32>>>(W2, b2, W3, b3, Brows);

    // y = x + e @ W4 + b4     [Brows x 768, K=256]
    dim3 g2(D_DIM / 128, Brows / 128);          // (6, 128)
    mma_gemm<1><<<g2, 256, SM_TOT>>>(nullptr, W4, b4, x, Brows, D_DIM, H_DIM);

    // out = LN(y) * gamma + beta
    ln_kernel<<<Brows, 256>>>(gamma, beta, out);
}

// round 5
// speedup vs baseline: 1.9581x; 1.1637x over previous
#include <cuda_runtime.h>
#include <cuda_bf16.h>
#include <cstdint>

#define BATCH   16384
#define D_DIM   768
#define H_DIM   256
#define NQ      8
#define NL      2

// ---------------- scratch (device globals; no runtime allocation) -----------
__device__ __align__(256) float  g_h[BATCH * H_DIM];   // gelu(x@W1+b1)
__device__ __align__(256) float  g_y[BATCH * D_DIM];   // x + e@W4 + b4 (pre-LN)
__device__ float2 g_C[NL][NQ][4];

// bf16 hi/lo split operands
__device__ __align__(256) __nv_bfloat16 g_xh[BATCH * D_DIM];
__device__ __align__(256) __nv_bfloat16 g_xl[BATCH * D_DIM];
__device__ __align__(256) __nv_bfloat16 g_w1h[D_DIM * H_DIM];
__device__ __align__(256) __nv_bfloat16 g_w1l[D_DIM * H_DIM];
__device__ __align__(256) __nv_bfloat16 g_w4h[H_DIM * D_DIM];
__device__ __align__(256) __nv_bfloat16 g_w4l[H_DIM * D_DIM];
__device__ __align__(256) __nv_bfloat16 g_eh[BATCH * H_DIM];
__device__ __align__(256) __nv_bfloat16 g_el[BATCH * H_DIM];

// ---------------- helpers ----------------------------------------------------
__device__ __forceinline__ float2 cmul(float2 a, float2 b) {
    return make_float2(a.x * b.x - a.y * b.y, a.x * b.y + a.y * b.x);
}
__device__ __forceinline__ float2 cadd(float2 a, float2 b) {
    return make_float2(a.x + b.x, a.y + b.y);
}
__device__ __forceinline__ float gelu_exact(float v) {
    return 0.5f * v * (1.0f + erff(v * 0.70710678118654752f));
}
__device__ __forceinline__ uint32_t smem_to_u32(const void* p) {
    uint32_t a;
    asm("{ .reg .u64 t; cvta.to.shared.u64 t, %1; cvt.u32.u64 %0, t; }"
        : "=r"(a) : "l"(p));
    return a;
}
__device__ __forceinline__ void cvt4_hilo(float4 v, uint2& hi, uint2& lo) {
    __nv_bfloat16 h0 = __float2bfloat16(v.x), h1 = __float2bfloat16(v.y);
    __nv_bfloat16 h2 = __float2bfloat16(v.z), h3 = __float2bfloat16(v.w);
    __nv_bfloat16 l0 = __float2bfloat16(v.x - __bfloat162float(h0));
    __nv_bfloat16 l1 = __float2bfloat16(v.y - __bfloat162float(h1));
    __nv_bfloat16 l2 = __float2bfloat16(v.z - __bfloat162float(h2));
    __nv_bfloat16 l3 = __float2bfloat16(v.w - __bfloat162float(h3));
    hi.x = (uint32_t)__bfloat16_as_ushort(h0) | ((uint32_t)__bfloat16_as_ushort(h1) << 16);
    hi.y = (uint32_t)__bfloat16_as_ushort(h2) | ((uint32_t)__bfloat16_as_ushort(h3) << 16);
    lo.x = (uint32_t)__bfloat16_as_ushort(l0) | ((uint32_t)__bfloat16_as_ushort(l1) << 16);
    lo.y = (uint32_t)__bfloat16_as_ushort(l2) | ((uint32_t)__bfloat16_as_ushort(l3) << 16);
}

__device__ __forceinline__ void ldsm_x4(uint32_t addr, uint32_t* r) {
    asm volatile("ldmatrix.sync.aligned.m8n8.x4.shared.b16 {%0,%1,%2,%3}, [%4];"
        : "=r"(r[0]), "=r"(r[1]), "=r"(r[2]), "=r"(r[3]) : "r"(addr));
}
__device__ __forceinline__ void ldsm_x4t(uint32_t addr, uint32_t* r) {
    asm volatile("ldmatrix.sync.aligned.m8n8.x4.trans.shared.b16 {%0,%1,%2,%3}, [%4];"
        : "=r"(r[0]), "=r"(r[1]), "=r"(r[2]), "=r"(r[3]) : "r"(addr));
}
__device__ __forceinline__ void mma16816(float* d, const uint32_t* a,
                                         uint32_t b0, uint32_t b1) {
    asm volatile(
        "mma.sync.aligned.m16n8k16.row.col.f32.bf16.bf16.f32 "
        "{%0,%1,%2,%3}, {%4,%5,%6,%7}, {%8,%9}, {%0,%1,%2,%3};"
        : "+f"(d[0]), "+f"(d[1]), "+f"(d[2]), "+f"(d[3])
        : "r"(a[0]), "r"(a[1]), "r"(a[2]), "r"(a[3]), "r"(b0), "r"(b1));
}
__device__ __forceinline__ void cp16(uint32_t saddr, const void* g) {
    asm volatile("cp.async.cg.shared.global [%0], [%1], 16;"
        :: "r"(saddr), "l"(g) : "memory");
}
#define CP_COMMIT() asm volatile("cp.async.commit_group;" ::: "memory")
#define CP_WAIT(n)  asm volatile("cp.async.wait_group %0;" :: "n"(n) : "memory")

// ---------------- K0: precompute C[l][i] -------------------------------------
__global__ void prep_gates(const float* __restrict__ qw) {
    int t = threadIdx.x;
    if (t >= NL * NQ) return;
    int l = t / NQ, i = t % NQ;
    float w0 = qw[(l * NQ + i) * 3 + 0];
    float w1 = qw[(l * NQ + i) * 3 + 1];
    float w2 = qw[(l * NQ + i) * 3 + 2];
    float c0 = cosf(0.5f * w0), s0 = sinf(0.5f * w0);
    float c1 = cosf(0.5f * w1), s1 = sinf(0.5f * w1);
    float c2 = cosf(0.5f * w2), s2 = sinf(0.5f * w2);
    float2 e0  = make_float2(c0, -s0);
    float2 e0c = make_float2(c0,  s0);
    float2 T00 = make_float2( c1 * e0.x,   c1 * e0.y);
    float2 T01 = make_float2(-s1 * e0c.x, -s1 * e0c.y);
    float2 T10 = make_float2( s1 * e0.x,   s1 * e0.y);
    float2 T11 = make_float2( c1 * e0c.x,  c1 * e0c.y);
    float2 e2  = make_float2(c2, -s2);
    float2 e2c = make_float2(c2,  s2);
    g_C[l][i][0] = cmul(e2,  T00);
    g_C[l][i][1] = cmul(e2,  T01);
    g_C[l][i][2] = cmul(e2c, T10);
    g_C[l][i][3] = cmul(e2c, T11);
}

// ---------------- prepass: fp32 -> bf16 hi/lo split --------------------------
__global__ __launch_bounds__(256) void conv_split(
    const float4* __restrict__ src, uint2* __restrict__ hi,
    uint2* __restrict__ lo, int n4)
{
    int i = blockIdx.x * 256 + threadIdx.x;
    if (i >= n4) return;
    float4 v = src[i];
    uint2 h, l; cvt4_hilo(v, h, l);
    hi[i] = h; lo[i] = l;
}

// ---------------- bf16 hi/lo tensor-core GEMM, cp.async 3-stage --------------
// EPI==0: g_h = gelu(x@W1 + b1)        (A = g_xh/g_xl, B = g_w1h/l)
// EPI==1: g_y = resid + e@W4 + bias    (A = g_eh/g_el, B = g_w4h/l)
#define STAGES 3
#define STAGE_BYTES 32768
#define SM_TOT (STAGES * STAGE_BYTES)

template <int EPI>
__global__ __launch_bounds__(256, 2) void mma_gemm(
    const float* __restrict__ bias, const float* __restrict__ resid,
    int N, int K)
{
    extern __shared__ char smem[];
    const __nv_bfloat16* Ah = (EPI == 1) ? g_eh : g_xh;
    const __nv_bfloat16* Al = (EPI == 1) ? g_el : g_xl;
    const __nv_bfloat16* Bh = (EPI == 1) ? g_w4h : g_w1h;
    const __nv_bfloat16* Bl = (EPI == 1) ? g_w4l : g_w1l;
    float* Cout = (EPI == 1) ? g_y : g_h;

    uint32_t sb = smem_to_u32(smem);
    int t = threadIdx.x, wid = t >> 5, lane = t & 31;
    int brow = blockIdx.y * 128, bcol = blockIdx.x * 128;
    int warpM = (wid & 3) * 32, warpN = (wid >> 2) * 64;
    int grp = lane >> 2, qc = lane & 3;

    float acc[2][8][4];
#pragma unroll
    for (int i = 0; i < 2; ++i)
#pragma unroll
        for (int j = 0; j < 8; ++j)
#pragma unroll
            for (int k = 0; k < 4; ++k) acc[i][j][k] = 0.f;

    int NC = K / 32;

    // per-thread copy coordinates
    int a_row0 = t >> 2, a_kseg = t & 3;        // + i*64 rows
    int b_kr0  = t >> 4, b_nseg = t & 15;       // + i*16 k-rows

    auto issue_stage = [&](int ck, int stg) {
        uint32_t base = sb + stg * STAGE_BYTES;
        int k0 = ck * 32;
#pragma unroll
        for (int i = 0; i < 2; ++i) {
            int row = a_row0 + i * 64;
            uint32_t off = (uint32_t)((row * 64 + a_kseg * 16) ^ ((row & 7) << 4));
            size_t gidx = (size_t)(brow + row) * K + k0 + a_kseg * 8;
            cp16(base + off, Ah + gidx);
            cp16(base + 8192 + off, Al + gidx);
        }
#pragma unroll
        for (int i = 0; i < 2; ++i) {
            int kr = b_kr0 + i * 16;
            uint32_t off = (uint32_t)((kr * 256 + b_nseg * 16) ^ ((kr & 7) << 4));
            size_t gidx = (size_t)(k0 + kr) * N + bcol + b_nseg * 8;
            cp16(base + 16384 + off, Bh + gidx);
            cp16(base + 24576 + off, Bl + gidx);
        }
    };

    // prologue: stages 0..STAGES-2
#pragma unroll
    for (int p = 0; p < STAGES - 1; ++p) {
        if (p < NC) issue_stage(p, p);
        CP_COMMIT();
    }

    for (int ck = 0; ck < NC; ++ck) {
        CP_WAIT(STAGES - 2);
        __syncthreads();

        int stg = ck % STAGES;
        uint32_t abase_h = sb + stg * STAGE_BYTES;
        uint32_t abase_l = abase_h + 8192;
        uint32_t bbase_h = abase_h + 16384;
        uint32_t bbase_l = abase_h + 24576;

#pragma unroll
        for (int s = 0; s < 2; ++s) {
            uint32_t ah[2][4], al[2][4];
#pragma unroll
            for (int mf = 0; mf < 2; ++mf) {
                int m = warpM + mf * 16 + (lane & 15);
                uint32_t kb = (uint32_t)(s * 32 + (lane >> 4) * 16);
                uint32_t off = (uint32_t)((m * 64 + kb) ^ ((m & 7) << 4));
                ldsm_x4(abase_h + off, ah[mf]);
                ldsm_x4(abase_l + off, al[mf]);
            }
#pragma unroll
            for (int n16 = 0; n16 < 4; ++n16) {
                uint32_t bh[4], bl[4];
                int kk = s * 16 + (lane & 15);
                uint32_t nb = (uint32_t)(warpN + n16 * 16 + (lane >> 4) * 8) * 2;
                uint32_t off = (uint32_t)((kk * 256 + nb) ^ ((kk & 7) << 4));
                ldsm_x4t(bbase_h + off, bh);
                ldsm_x4t(bbase_l + off, bl);
#pragma unroll
                for (int half = 0; half < 2; ++half) {
                    int nf = n16 * 2 + half;
#pragma unroll
                    for (int mf = 0; mf < 2; ++mf) {
                        mma16816(acc[mf][nf], ah[mf], bh[half * 2], bh[half * 2 + 1]);
                        mma16816(acc[mf][nf], ah[mf], bl[half * 2], bl[half * 2 + 1]);
                        mma16816(acc[mf][nf], al[mf], bh[half * 2], bh[half * 2 + 1]);
                    }
                }
            }
        }
        __syncthreads();

        int nx = ck + STAGES - 1;
        if (nx < NC) issue_stage(nx, nx % STAGES);
        CP_COMMIT();
    }

    // ---- epilogue ----
#pragma unroll
    for (int mf = 0; mf < 2; ++mf) {
        int r0 = brow + warpM + mf * 16 + grp;
#pragma unroll
        for (int nf = 0; nf < 8; ++nf) {
            int col = bcol + warpN + nf * 8 + qc * 2;
            float bv0 = bias[col], bv1 = bias[col + 1];
            float v0 = acc[mf][nf][0] + bv0;
            float v1 = acc[mf][nf][1] + bv1;
            float v2 = acc[mf][nf][2] + bv0;
            float v3 = acc[mf][nf][3] + bv1;
            size_t o0 = (size_t)r0 * N + col;
            size_t o1 = o0 + (size_t)8 * N;
            if (EPI == 0) {
                v0 = gelu_exact(v0); v1 = gelu_exact(v1);
                v2 = gelu_exact(v2); v3 = gelu_exact(v3);
            } else {
                float2 ra = *(const float2*)(resid + o0);
                float2 rb = *(const float2*)(resid + o1);
                v0 += ra.x; v1 += ra.y; v2 += rb.x; v3 += rb.y;
            }
            *(float2*)(Cout + o0) = make_float2(v0, v1);
            *(float2*)(Cout + o1) = make_float2(v2, v3);
        }
    }
}

// ---------------- K2: quantum bottleneck, one warp per row -------------------
#define QWARPS 4
__global__ __launch_bounds__(QWARPS * 32) void quantum_kernel(
    const float* __restrict__ W2, const float* __restrict__ b2,
    const float* __restrict__ W3, const float* __restrict__ b3,
    int Brows)
{
    __shared__ float2 st_s[QWARPS][256];
    int warp = threadIdx.x >> 5;
    int lane = threadIdx.x & 31;
    int row  = blockIdx.x * QWARPS + warp;
    if (row >= Brows) return;
    float2* st = st_s[warp];

    const float* hrow = g_h + (size_t)row * H_DIM;
    float fj[8] = {0, 0, 0, 0, 0, 0, 0, 0};
#pragma unroll
    for (int m = 0; m < 8; ++m) {
        int k = lane + 32 * m;
        float hv = hrow[k];
        const float4* w2p = (const float4*)(W2 + (size_t)k * 8);
        float4 wa = w2p[0], wb = w2p[1];
        fj[0] += hv * wa.x; fj[1] += hv * wa.y;
        fj[2] += hv * wa.z; fj[3] += hv * wa.w;
        fj[4] += hv * wb.x; fj[5] += hv * wb.y;
        fj[6] += hv * wb.z; fj[7] += hv * wb.w;
    }
#pragma unroll
    for (int j = 0; j < 8; ++j)
#pragma unroll
        for (int o = 16; o; o >>= 1)
            fj[j] += __shfl_xor_sync(0xffffffffu, fj[j], o);

    float cf[8], sf[8];
#pragma unroll
    for (int j = 0; j < 8; ++j) {
        float f = 0.5f * (fj[j] + b2[j]);
        cf[j] = cosf(f);
        sf[j] = sinf(f);
    }

#pragma unroll
    for (int r = 0; r < 8; ++r) st[lane + 32 * r] = make_float2(0.f, 0.f);
    __syncwarp();
    if (lane == 0) st[0] = make_float2(1.f, 0.f);
    __syncwarp();

    for (int l = 0; l < NL; ++l) {
#pragma unroll
        for (int i = 0; i < NQ; ++i) {
            float2 C00 = g_C[l][i][0], C01 = g_C[l][i][1];
            float2 C10 = g_C[l][i][2], C11 = g_C[l][i][3];
            float c = cf[i], s = sf[i];
            float2 U00 = make_float2(C00.x * c + C01.x * s, C00.y * c + C01.y * s);
            float2 U01 = make_float2(C01.x * c - C00.x * s, C01.y * c - C00.y * s);
            float2 U10 = make_float2(C10.x * c + C11.x * s, C10.y * c + C11.y * s);
            float2 U11 = make_float2(C11.x * c - C10.x * s, C11.y * c - C10.y * s);
            int sbit = 7 - i;
            int stride = 1 << sbit;
#pragma unroll
            for (int r = 0; r < 4; ++r) {
                int p  = lane + 32 * r;
                int i0 = ((p >> sbit) << (sbit + 1)) | (p & (stride - 1));
                int i1 = i0 | stride;
                float2 a = st[i0], b = st[i1];
                st[i0] = cadd(cmul(U00, a), cmul(U01, b));
                st[i1] = cadd(cmul(U10, a), cmul(U11, b));
            }
            __syncwarp();
        }
#pragma unroll
        for (int i = 0; i < NQ; ++i) {
            int tq = (i + 1) & 7;
            int cmask = 1 << (7 - i);
            int tmask = 1 << (7 - tq);
#pragma unroll
            for (int r = 0; r < 8; ++r) {
                int idx = lane + 32 * r;
                if ((idx & cmask) && !(idx & tmask)) {
                    float2 a = st[idx], b = st[idx | tmask];
                    st[idx] = b;
                    st[idx | tmask] = a;
                }
            }
            __syncwarp();
        }
    }

    float zf[8] = {0, 0, 0, 0, 0, 0, 0, 0};
#pragma unroll
    for (int r = 0; r < 8; ++r) {
        int idx = lane + 32 * r;
        float2 a = st[idx];
        float p = a.x * a.x + a.y * a.y;
#pragma unroll
        for (int i = 0; i < 8; ++i)
            zf[i] += ((idx >> (7 - i)) & 1) ? -p : p;
    }
#pragma unroll
    for (int j = 0; j < 8; ++j)
#pragma unroll
        for (int o = 16; o; o >>= 1)
            zf[j] += __shfl_xor_sync(0xffffffffu, zf[j], o);

    // e = gelu(z @ W3 + b3), emitted as bf16 hi/lo
    size_t ebase = (size_t)row * H_DIM;
#pragma unroll
    for (int m = 0; m < 8; ++m) {
        int k = lane + 32 * m;
        float acc = b3[k];
#pragma unroll
        for (int j = 0; j < 8; ++j) acc += zf[j] * W3[j * H_DIM + k];
        float v = gelu_exact(acc);
        __nv_bfloat16 h = __float2bfloat16(v);
        g_eh[ebase + k] = h;
        g_el[ebase + k] = __float2bfloat16(v - __bfloat162float(h));
    }
}

// ---------------- K4: LayerNorm over D=768 -----------------------------------
__global__ __launch_bounds__(256) void ln_kernel(
    const float* __restrict__ gamma, const float* __restrict__ beta,
    float* __restrict__ out)
{
    int row = blockIdx.x;
    const float* yr = g_y + (size_t)row * D_DIM;
    int tid = threadIdx.x;

    float v[3];
    float sum = 0.f, sq = 0.f;
#pragma unroll
    for (int m = 0; m < 3; ++m) {
        v[m] = yr[tid + 256 * m];
        sum += v[m];
        sq  += v[m] * v[m];
    }
#pragma unroll
    for (int o = 16; o; o >>= 1) {
        sum += __shfl_xor_sync(0xffffffffu, sum, o);
        sq  += __shfl_xor_sync(0xffffffffu, sq,  o);
    }
    __shared__ float red[2][8];
    int w = tid >> 5;
    if ((tid & 31) == 0) { red[0][w] = sum; red[1][w] = sq; }
    __syncthreads();
    sum = 0.f; sq = 0.f;
#pragma unroll
    for (int i = 0; i < 8; ++i) { sum += red[0][i]; sq += red[1][i]; }

    float mu  = sum * (1.0f / D_DIM);
    float var = sq * (1.0f / D_DIM) - mu * mu;
    float inv = rsqrtf(var + 1e-5f);

    float* orow = out + (size_t)row * D_DIM;
#pragma unroll
    for (int m = 0; m < 3; ++m) {
        int k = tid + 256 * m;
        orow[k] = gamma[k] * (v[m] - mu) * inv + beta[k];
    }
}

// ---------------- launch ------------------------------------------------------
extern "C" void kernel_launch(void* const* d_in, const int* in_sizes, int n_in,
                              void* d_out, int out_size) {
    const float* x     = (const float*)d_in[0];
    const float* b1    = (const float*)d_in[2];
    const float* W2    = (const float*)d_in[3];
    const float* b2    = (const float*)d_in[4];
    const float* qw    = (const float*)d_in[5];
    const float* W3    = (const float*)d_in[6];
    const float* b3    = (const float*)d_in[7];
    const float* b4    = (const float*)d_in[9];
    const float* gamma = (const float*)d_in[10];
    const float* beta  = (const float*)d_in[11];
    const float* W1    = (const float*)d_in[1];
    const float* W4    = (const float*)d_in[8];
    float* out = (float*)d_out;

    int Brows = in_sizes[0] / D_DIM;   // 16384

    cudaFuncSetAttribute(mma_gemm<0>, cudaFuncAttributeMaxDynamicSharedMemorySize, SM_TOT);
    cudaFuncSetAttribute(mma_gemm<1>, cudaFuncAttributeMaxDynamicSharedMemorySize, SM_TOT);

    // symbol addresses for prepass outputs
    void *pxh, *pxl, *pw1h, *pw1l, *pw4h, *pw4l;
    cudaGetSymbolAddress(&pxh, g_xh);   cudaGetSymbolAddress(&pxl, g_xl);
    cudaGetSymbolAddress(&pw1h, g_w1h); cudaGetSymbolAddress(&pw1l, g_w1l);
    cudaGetSymbolAddress(&pw4h, g_w4h); cudaGetSymbolAddress(&pw4l, g_w4l);

    prep_gates<<<1, 32>>>(qw);

    // split x, W1, W4 into bf16 hi/lo
    int nx4 = (Brows * D_DIM) / 4;
    conv_split<<<(nx4 + 255) / 256, 256>>>((const float4*)x, (uint2*)pxh, (uint2*)pxl, nx4);
    int nw4 = (D_DIM * H_DIM) / 4;
    conv_split<<<(nw4 + 255) / 256, 256>>>((const float4*)W1, (uint2*)pw1h, (uint2*)pw1l, nw4);
    conv_split<<<(nw4 + 255) / 256, 256>>>((const float4*)W4, (uint2*)pw4h, (uint2*)pw4l, nw4);

    // h = gelu(x @ W1 + b1)   [Brows x 256, K=768]
    dim3 g1(H_DIM / 128, Brows / 128);          // (2, 128)
    mma_gemm<0><<<g1, 256, SM_TOT>>>(b1, nullptr, H_DIM, D_DIM);

    // quantum bottleneck -> e (bf16 hi/lo)
    quantum_kernel<<<Brows / QWARPS, QWARPS * 32>>>(W2, b2, W3, b3, Brows);

    // y = x + e @ W4 + b4     [Brows x 768, K=256]
    dim3 g2(D_DIM / 128, Brows / 128);          // (6, 128)
    mma_gemm<1><<<g2, 256, SM_TOT>>>(b4, x, D_DIM, H_DIM);

    // out = LN(y) * gamma + beta
    ln_kernel<<<Brows, 256>>>(gamma, beta, out);
}

// round 6
// speedup vs baseline: 2.2131x; 1.1302x over previous
#include <cuda_runtime.h>
#include <cuda_bf16.h>
#include <cstdint>

#define BATCH   16384
#define D_DIM   768
#define H_DIM   256
#define NQ      8
#define NL      2

// ---------------- scratch (device globals; no runtime allocation) -----------
__device__ __align__(256) float  g_h[BATCH * H_DIM];   // gelu(x@W1+b1)
__device__ __align__(256) float  g_y[BATCH * D_DIM];   // x + e@W4 + b4 (pre-LN)
__device__ float2 g_C[NL][NQ][4];

// bf16 hi/lo split operands
__device__ __align__(256) __nv_bfloat16 g_xh[BATCH * D_DIM];
__device__ __align__(256) __nv_bfloat16 g_xl[BATCH * D_DIM];
__device__ __align__(256) __nv_bfloat16 g_w1h[D_DIM * H_DIM];
__device__ __align__(256) __nv_bfloat16 g_w1l[D_DIM * H_DIM];
__device__ __align__(256) __nv_bfloat16 g_w4h[H_DIM * D_DIM];
__device__ __align__(256) __nv_bfloat16 g_w4l[H_DIM * D_DIM];
__device__ __align__(256) __nv_bfloat16 g_eh[BATCH * H_DIM];
__device__ __align__(256) __nv_bfloat16 g_el[BATCH * H_DIM];

// ---------------- helpers ----------------------------------------------------
__device__ __forceinline__ float2 cmul(float2 a, float2 b) {
    return make_float2(a.x * b.x - a.y * b.y, a.x * b.y + a.y * b.x);
}
__device__ __forceinline__ float2 cadd(float2 a, float2 b) {
    return make_float2(a.x + b.x, a.y + b.y);
}
__device__ __forceinline__ float gelu_exact(float v) {
    return 0.5f * v * (1.0f + erff(v * 0.70710678118654752f));
}
__device__ __forceinline__ uint32_t smem_to_u32(const void* p) {
    uint32_t a;
    asm("{ .reg .u64 t; cvta.to.shared.u64 t, %1; cvt.u32.u64 %0, t; }"
        : "=r"(a) : "l"(p));
    return a;
}
__device__ __forceinline__ void cvt4_hilo(float4 v, uint2& hi, uint2& lo) {
    __nv_bfloat16 h0 = __float2bfloat16(v.x), h1 = __float2bfloat16(v.y);
    __nv_bfloat16 h2 = __float2bfloat16(v.z), h3 = __float2bfloat16(v.w);
    __nv_bfloat16 l0 = __float2bfloat16(v.x - __bfloat162float(h0));
    __nv_bfloat16 l1 = __float2bfloat16(v.y - __bfloat162float(h1));
    __nv_bfloat16 l2 = __float2bfloat16(v.z - __bfloat162float(h2));
    __nv_bfloat16 l3 = __float2bfloat16(v.w - __bfloat162float(h3));
    hi.x = (uint32_t)__bfloat16_as_ushort(h0) | ((uint32_t)__bfloat16_as_ushort(h1) << 16);
    hi.y = (uint32_t)__bfloat16_as_ushort(h2) | ((uint32_t)__bfloat16_as_ushort(h3) << 16);
    lo.x = (uint32_t)__bfloat16_as_ushort(l0) | ((uint32_t)__bfloat16_as_ushort(l1) << 16);
    lo.y = (uint32_t)__bfloat16_as_ushort(l2) | ((uint32_t)__bfloat16_as_ushort(l3) << 16);
}
__device__ __forceinline__ float2 shfl2(float2 v, int mask) {
    v.x = __shfl_xor_sync(0xffffffffu, v.x, mask);
    v.y = __shfl_xor_sync(0xffffffffu, v.y, mask);
    return v;
}

__device__ __forceinline__ void ldsm_x4(uint32_t addr, uint32_t* r) {
    asm volatile("ldmatrix.sync.aligned.m8n8.x4.shared.b16 {%0,%1,%2,%3}, [%4];"
        : "=r"(r[0]), "=r"(r[1]), "=r"(r[2]), "=r"(r[3]) : "r"(addr));
}
__device__ __forceinline__ void ldsm_x4t(uint32_t addr, uint32_t* r) {
    asm volatile("ldmatrix.sync.aligned.m8n8.x4.trans.shared.b16 {%0,%1,%2,%3}, [%4];"
        : "=r"(r[0]), "=r"(r[1]), "=r"(r[2]), "=r"(r[3]) : "r"(addr));
}
__device__ __forceinline__ void mma16816(float* d, const uint32_t* a,
                                         uint32_t b0, uint32_t b1) {
    asm volatile(
        "mma.sync.aligned.m16n8k16.row.col.f32.bf16.bf16.f32 "
        "{%0,%1,%2,%3}, {%4,%5,%6,%7}, {%8,%9}, {%0,%1,%2,%3};"
        : "+f"(d[0]), "+f"(d[1]), "+f"(d[2]), "+f"(d[3])
        : "r"(a[0]), "r"(a[1]), "r"(a[2]), "r"(a[3]), "r"(b0), "r"(b1));
}
__device__ __forceinline__ void cp16(uint32_t saddr, const void* g) {
    asm volatile("cp.async.cg.shared.global [%0], [%1], 16;"
        :: "r"(saddr), "l"(g) : "memory");
}
#define CP_COMMIT() asm volatile("cp.async.commit_group;" ::: "memory")
#define CP_WAIT(n)  asm volatile("cp.async.wait_group %0;" :: "n"(n) : "memory")

// ---------------- K0: precompute C[l][i] -------------------------------------
__global__ void prep_gates(const float* __restrict__ qw) {
    int t = threadIdx.x;
    if (t >= NL * NQ) return;
    int l = t / NQ, i = t % NQ;
    float w0 = qw[(l * NQ + i) * 3 + 0];
    float w1 = qw[(l * NQ + i) * 3 + 1];
    float w2 = qw[(l * NQ + i) * 3 + 2];
    float c0 = cosf(0.5f * w0), s0 = sinf(0.5f * w0);
    float c1 = cosf(0.5f * w1), s1 = sinf(0.5f * w1);
    float c2 = cosf(0.5f * w2), s2 = sinf(0.5f * w2);
    float2 e0  = make_float2(c0, -s0);
    float2 e0c = make_float2(c0,  s0);
    float2 T00 = make_float2( c1 * e0.x,   c1 * e0.y);
    float2 T01 = make_float2(-s1 * e0c.x, -s1 * e0c.y);
    float2 T10 = make_float2( s1 * e0.x,   s1 * e0.y);
    float2 T11 = make_float2( c1 * e0c.x,  c1 * e0c.y);
    float2 e2  = make_float2(c2, -s2);
    float2 e2c = make_float2(c2,  s2);
    g_C[l][i][0] = cmul(e2,  T00);
    g_C[l][i][1] = cmul(e2,  T01);
    g_C[l][i][2] = cmul(e2c, T10);
    g_C[l][i][3] = cmul(e2c, T11);
}

// ---------------- prepass: fp32 -> bf16 hi/lo split --------------------------
__global__ __launch_bounds__(256) void conv_split(
    const float4* __restrict__ src, uint2* __restrict__ hi,
    uint2* __restrict__ lo, int n4)
{
    int i = blockIdx.x * 256 + threadIdx.x;
    if (i >= n4) return;
    float4 v = src[i];
    uint2 h, l; cvt4_hilo(v, h, l);
    hi[i] = h; lo[i] = l;
}
// both weight matrices in one launch (each 768*256/4 = 49152 float4)
__global__ __launch_bounds__(256) void conv_split_w(
    const float4* __restrict__ w1, const float4* __restrict__ w4,
    uint2* __restrict__ w1h, uint2* __restrict__ w1l,
    uint2* __restrict__ w4h, uint2* __restrict__ w4l, int n4)
{
    int i = blockIdx.x * 256 + threadIdx.x;
    if (i >= 2 * n4) return;
    const float4* s = (i < n4) ? w1 : w4;
    int j = (i < n4) ? i : i - n4;
    float4 v = s[j];
    uint2 h, l; cvt4_hilo(v, h, l);
    if (i < n4) { w1h[j] = h; w1l[j] = l; }
    else        { w4h[j] = h; w4l[j] = l; }
}

// ---------------- bf16 hi/lo tensor-core GEMM, cp.async 3-stage --------------
#define STAGES 3
#define STAGE_BYTES 32768
#define SM_TOT (STAGES * STAGE_BYTES)

template <int EPI>
__global__ __launch_bounds__(256, 2) void mma_gemm(
    const float* __restrict__ bias, const float* __restrict__ resid,
    int N, int K)
{
    extern __shared__ char smem[];
    const __nv_bfloat16* Ah = (EPI == 1) ? g_eh : g_xh;
    const __nv_bfloat16* Al = (EPI == 1) ? g_el : g_xl;
    const __nv_bfloat16* Bh = (EPI == 1) ? g_w4h : g_w1h;
    const __nv_bfloat16* Bl = (EPI == 1) ? g_w4l : g_w1l;
    float* Cout = (EPI == 1) ? g_y : g_h;

    uint32_t sb = smem_to_u32(smem);
    int t = threadIdx.x, wid = t >> 5, lane = t & 31;
    int brow = blockIdx.y * 128, bcol = blockIdx.x * 128;
    int warpM = (wid & 3) * 32, warpN = (wid >> 2) * 64;
    int grp = lane >> 2, qc = lane & 3;

    float acc[2][8][4];
#pragma unroll
    for (int i = 0; i < 2; ++i)
#pragma unroll
        for (int j = 0; j < 8; ++j)
#pragma unroll
            for (int k = 0; k < 4; ++k) acc[i][j][k] = 0.f;

    int NC = K / 32;
    int a_row0 = t >> 2, a_kseg = t & 3;
    int b_kr0  = t >> 4, b_nseg = t & 15;

    auto issue_stage = [&](int ck, int stg) {
        uint32_t base = sb + stg * STAGE_BYTES;
        int k0 = ck * 32;
#pragma unroll
        for (int i = 0; i < 2; ++i) {
            int row = a_row0 + i * 64;
            uint32_t off = (uint32_t)((row * 64 + a_kseg * 16) ^ ((row & 7) << 4));
            size_t gidx = (size_t)(brow + row) * K + k0 + a_kseg * 8;
            cp16(base + off, Ah + gidx);
            cp16(base + 8192 + off, Al + gidx);
        }
#pragma unroll
        for (int i = 0; i < 2; ++i) {
            int kr = b_kr0 + i * 16;
            uint32_t off = (uint32_t)((kr * 256 + b_nseg * 16) ^ ((kr & 7) << 4));
            size_t gidx = (size_t)(k0 + kr) * N + bcol + b_nseg * 8;
            cp16(base + 16384 + off, Bh + gidx);
            cp16(base + 24576 + off, Bl + gidx);
        }
    };

#pragma unroll
    for (int p = 0; p < STAGES - 1; ++p) {
        if (p < NC) issue_stage(p, p);
        CP_COMMIT();
    }

    for (int ck = 0; ck < NC; ++ck) {
        CP_WAIT(STAGES - 2);
        __syncthreads();

        int stg = ck % STAGES;
        uint32_t abase_h = sb + stg * STAGE_BYTES;
        uint32_t abase_l = abase_h + 8192;
        uint32_t bbase_h = abase_h + 16384;
        uint32_t bbase_l = abase_h + 24576;

#pragma unroll
        for (int s = 0; s < 2; ++s) {
            uint32_t ah[2][4], al[2][4];
#pragma unroll
            for (int mf = 0; mf < 2; ++mf) {
                int m = warpM + mf * 16 + (lane & 15);
                uint32_t kb = (uint32_t)(s * 32 + (lane >> 4) * 16);
                uint32_t off = (uint32_t)((m * 64 + kb) ^ ((m & 7) << 4));
                ldsm_x4(abase_h + off, ah[mf]);
                ldsm_x4(abase_l + off, al[mf]);
            }
#pragma unroll
            for (int n16 = 0; n16 < 4; ++n16) {
                uint32_t bh[4], bl[4];
                int kk = s * 16 + (lane & 15);
                uint32_t nb = (uint32_t)(warpN + n16 * 16 + (lane >> 4) * 8) * 2;
                uint32_t off = (uint32_t)((kk * 256 + nb) ^ ((kk & 7) << 4));
                ldsm_x4t(bbase_h + off, bh);
                ldsm_x4t(bbase_l + off, bl);
#pragma unroll
                for (int half = 0; half < 2; ++half) {
                    int nf = n16 * 2 + half;
#pragma unroll
                    for (int mf = 0; mf < 2; ++mf) {
                        mma16816(acc[mf][nf], ah[mf], bh[half * 2], bh[half * 2 + 1]);
                        mma16816(acc[mf][nf], ah[mf], bl[half * 2], bl[half * 2 + 1]);
                        mma16816(acc[mf][nf], al[mf], bh[half * 2], bh[half * 2 + 1]);
                    }
                }
            }
        }
        __syncthreads();

        int nx = ck + STAGES - 1;
        if (nx < NC) issue_stage(nx, nx % STAGES);
        CP_COMMIT();
    }

#pragma unroll
    for (int mf = 0; mf < 2; ++mf) {
        int r0 = brow + warpM + mf * 16 + grp;
#pragma unroll
        for (int nf = 0; nf < 8; ++nf) {
            int col = bcol + warpN + nf * 8 + qc * 2;
            float bv0 = bias[col], bv1 = bias[col + 1];
            float v0 = acc[mf][nf][0] + bv0;
            float v1 = acc[mf][nf][1] + bv1;
            float v2 = acc[mf][nf][2] + bv0;
            float v3 = acc[mf][nf][3] + bv1;
            size_t o0 = (size_t)r0 * N + col;
            size_t o1 = o0 + (size_t)8 * N;
            if (EPI == 0) {
                v0 = gelu_exact(v0); v1 = gelu_exact(v1);
                v2 = gelu_exact(v2); v3 = gelu_exact(v3);
            } else {
                float2 ra = *(const float2*)(resid + o0);
                float2 rb = *(const float2*)(resid + o1);
                v0 += ra.x; v1 += ra.y; v2 += rb.x; v3 += rb.y;
            }
            *(float2*)(Cout + o0) = make_float2(v0, v1);
            *(float2*)(Cout + o1) = make_float2(v2, v3);
        }
    }
}

// ---------------- K2: quantum bottleneck, register statevector ---------------
// state idx = (r << 5) | lane : bits 7..5 = register, bits 4..0 = lane.
#define QWARPS 8
__global__ __launch_bounds__(QWARPS * 32) void quantum_kernel(
    const float* __restrict__ W2, const float* __restrict__ b2,
    const float* __restrict__ W3, const float* __restrict__ b3,
    int Brows)
{
    int warp = threadIdx.x >> 5;
    int lane = threadIdx.x & 31;
    int row  = blockIdx.x * QWARPS + warp;
    if (row >= Brows) return;

    // ---- feats_j = h_row . W2[:,j] + b2[j] ----
    const float* hrow = g_h + (size_t)row * H_DIM;
    float fj[8] = {0, 0, 0, 0, 0, 0, 0, 0};
#pragma unroll
    for (int m = 0; m < 8; ++m) {
        int k = lane + 32 * m;
        float hv = hrow[k];
        const float4* w2p = (const float4*)(W2 + (size_t)k * 8);
        float4 wa = w2p[0], wb = w2p[1];
        fj[0] += hv * wa.x; fj[1] += hv * wa.y;
        fj[2] += hv * wa.z; fj[3] += hv * wa.w;
        fj[4] += hv * wb.x; fj[5] += hv * wb.y;
        fj[6] += hv * wb.z; fj[7] += hv * wb.w;
    }
#pragma unroll
    for (int j = 0; j < 8; ++j)
#pragma unroll
        for (int o = 16; o; o >>= 1)
            fj[j] += __shfl_xor_sync(0xffffffffu, fj[j], o);

    float cf[8], sf[8];
#pragma unroll
    for (int j = 0; j < 8; ++j) {
        float f = 0.5f * (fj[j] + b2[j]);
        cf[j] = cosf(f);
        sf[j] = sinf(f);
    }

    // ---- init |0..0> ----
    float2 amp[8];
#pragma unroll
    for (int r = 0; r < 8; ++r) amp[r] = make_float2(0.f, 0.f);
    if (lane == 0) amp[0] = make_float2(1.f, 0.f);

#pragma unroll
    for (int l = 0; l < NL; ++l) {
        // ---- 1q gates ----
#pragma unroll
        for (int i = 0; i < NQ; ++i) {
            float2 C00 = g_C[l][i][0], C01 = g_C[l][i][1];
            float2 C10 = g_C[l][i][2], C11 = g_C[l][i][3];
            float c = cf[i], s = sf[i];
            float2 U00 = make_float2(C00.x * c + C01.x * s, C00.y * c + C01.y * s);
            float2 U01 = make_float2(C01.x * c - C00.x * s, C01.y * c - C00.y * s);
            float2 U10 = make_float2(C10.x * c + C11.x * s, C10.y * c + C11.y * s);
            float2 U11 = make_float2(C11.x * c - C10.x * s, C11.y * c - C10.y * s);
            const int sbit = 7 - i;
            if (sbit >= 5) {                     // register pairing
                const int rb = 1 << (sbit - 5);
#pragma unroll
                for (int r0 = 0; r0 < 8; ++r0) {
                    if (r0 & rb) continue;
                    float2 a = amp[r0], b = amp[r0 | rb];
                    amp[r0]      = cadd(cmul(U00, a), cmul(U01, b));
                    amp[r0 | rb] = cadd(cmul(U10, a), cmul(U11, b));
                }
            } else {                             // lane pairing via shuffle
                const int lb = 1 << sbit;
                bool hi = (lane >> sbit) & 1;
#pragma unroll
                for (int r = 0; r < 8; ++r) {
                    float2 o = shfl2(amp[r], lb);
                    float2 lo_v = cadd(cmul(U00, amp[r]), cmul(U01, o));
                    float2 hi_v = cadd(cmul(U10, o), cmul(U11, amp[r]));
                    amp[r] = hi ? hi_v : lo_v;
                }
            }
        }
        // ---- CNOT ring ----
#pragma unroll
        for (int i = 0; i < NQ; ++i) {
            const int cb = 7 - i;
            const int tb = 7 - ((i + 1) & 7);
            if (tb >= 5) {                       // target is a register bit
                const int rb = 1 << (tb - 5);
                if (cb >= 5) {                   // control is a register bit
                    const int crb = 1 << (cb - 5);
#pragma unroll
                    for (int r0 = 0; r0 < 8; ++r0) {
                        if ((r0 & rb) || !(r0 & crb)) continue;
                        float2 tmp = amp[r0];
                        amp[r0] = amp[r0 | rb];
                        amp[r0 | rb] = tmp;
                    }
                } else {                         // control is a lane bit
                    bool cset = (lane >> cb) & 1;
#pragma unroll
                    for (int r0 = 0; r0 < 8; ++r0) {
                        if (r0 & rb) continue;
                        float2 a = amp[r0], b = amp[r0 | rb];
                        amp[r0]      = cset ? b : a;
                        amp[r0 | rb] = cset ? a : b;
                    }
                }
            } else {                             // target is a lane bit
                const int lb = 1 << tb;
#pragma unroll
                for (int r = 0; r < 8; ++r) {
                    float2 o = shfl2(amp[r], lb);
                    bool cset = (cb >= 5) ? ((r >> (cb - 5)) & 1)
                                          : ((lane >> cb) & 1);
                    amp[r] = cset ? o : amp[r];
                }
            }
        }
    }

    // ---- z_i from probabilities ----
    float zf[8] = {0, 0, 0, 0, 0, 0, 0, 0};
#pragma unroll
    for (int r = 0; r < 8; ++r) {
        int idx = (r << 5) | lane;
        float p = amp[r].x * amp[r].x + amp[r].y * amp[r].y;
#pragma unroll
        for (int i = 0; i < 8; ++i)
            zf[i] += ((idx >> (7 - i)) & 1) ? -p : p;
    }
#pragma unroll
    for (int j = 0; j < 8; ++j)
#pragma unroll
        for (int o = 16; o; o >>= 1)
            zf[j] += __shfl_xor_sync(0xffffffffu, zf[j], o);

    // ---- e = gelu(z @ W3 + b3), bf16 hi/lo ----
    size_t ebase = (size_t)row * H_DIM;
#pragma unroll
    for (int m = 0; m < 8; ++m) {
        int k = lane + 32 * m;
        float acc = b3[k];
#pragma unroll
        for (int j = 0; j < 8; ++j) acc += zf[j] * W3[j * H_DIM + k];
        float v = gelu_exact(acc);
        __nv_bfloat16 h = __float2bfloat16(v);
        g_eh[ebase + k] = h;
        g_el[ebase + k] = __float2bfloat16(v - __bfloat162float(h));
    }
}

// ---------------- K4: LayerNorm over D=768 -----------------------------------
__global__ __launch_bounds__(256) void ln_kernel(
    const float* __restrict__ gamma, const float* __restrict__ beta,
    float* __restrict__ out)
{
    int row = blockIdx.x;
    const float* yr = g_y + (size_t)row * D_DIM;
    int tid = threadIdx.x;

    float v[3];
    float sum = 0.f, sq = 0.f;
#pragma unroll
    for (int m = 0; m < 3; ++m) {
        v[m] = yr[tid + 256 * m];
        sum += v[m];
        sq  += v[m] * v[m];
    }
#pragma unroll
    for (int o = 16; o; o >>= 1) {
        sum += __shfl_xor_sync(0xffffffffu, sum, o);
        sq  += __shfl_xor_sync(0xffffffffu, sq,  o);
    }
    __shared__ float red[2][8];
    int w = tid >> 5;
    if ((tid & 31) == 0) { red[0][w] = sum; red[1][w] = sq; }
    __syncthreads();
    sum = 0.f; sq = 0.f;
#pragma unroll
    for (int i = 0; i < 8; ++i) { sum += red[0][i]; sq += red[1][i]; }

    float mu  = sum * (1.0f / D_DIM);
    float var = sq * (1.0f / D_DIM) - mu * mu;
    float inv = rsqrtf(var + 1e-5f);

    float* orow = out + (size_t)row * D_DIM;
#pragma unroll
    for (int m = 0; m < 3; ++m) {
        int k = tid + 256 * m;
        orow[k] = gamma[k] * (v[m] - mu) * inv + beta[k];
    }
}

// ---------------- launch ------------------------------------------------------
extern "C" void kernel_launch(void* const* d_in, const int* in_sizes, int n_in,
                              void* d_out, int out_size) {
    const float* x     = (const float*)d_in[0];
    const float* W1    = (const float*)d_in[1];
    const float* b1    = (const float*)d_in[2];
    const float* W2    = (const float*)d_in[3];
    const float* b2    = (const float*)d_in[4];
    const float* qw    = (const float*)d_in[5];
    const float* W3    = (const float*)d_in[6];
    const float* b3    = (const float*)d_in[7];
    const float* W4    = (const float*)d_in[8];
    const float* b4    = (const float*)d_in[9];
    const float* gamma = (const float*)d_in[10];
    const float* beta  = (const float*)d_in[11];
    float* out = (float*)d_out;

    int Brows = in_sizes[0] / D_DIM;   // 16384

    cudaFuncSetAttribute(mma_gemm<0>, cudaFuncAttributeMaxDynamicSharedMemorySize, SM_TOT);
    cudaFuncSetAttribute(mma_gemm<1>, cudaFuncAttributeMaxDynamicSharedMemorySize, SM_TOT);

    void *pxh, *pxl, *pw1h, *pw1l, *pw4h, *pw4l;
    cudaGetSymbolAddress(&pxh, g_xh);   cudaGetSymbolAddress(&pxl, g_xl);
    cudaGetSymbolAddress(&pw1h, g_w1h); cudaGetSymbolAddress(&pw1l, g_w1l);
    cudaGetSymbolAddress(&pw4h, g_w4h); cudaGetSymbolAddress(&pw4l, g_w4l);

    prep_gates<<<1, 32>>>(qw);

    int nx4 = (Brows * D_DIM) / 4;
    conv_split<<<(nx4 + 255) / 256, 256>>>((const float4*)x, (uint2*)pxh, (uint2*)pxl, nx4);
    int nw4 = (D_DIM * H_DIM) / 4;
    conv_split_w<<<(2 * nw4 + 255) / 256, 256>>>(
        (const float4*)W1, (const float4*)W4,
        (uint2*)pw1h, (uint2*)pw1l, (uint2*)pw4h, (uint2*)pw4l, nw4);

    // h = gelu(x @ W1 + b1)
    dim3 g1(H_DIM / 128, Brows / 128);
    mma_gemm<0><<<g1, 256, SM_TOT>>>(b1, nullptr, H_DIM, D_DIM);

    // quantum bottleneck -> e (bf16 hi/lo)
    quantum_kernel<<<Brows / QWARPS, QWARPS * 32>>>(W2, b2, W3, b3, Brows);

    // y = x + e @ W4 + b4
    dim3 g2(D_DIM / 128, Brows / 128);
    mma_gemm<1><<<g2, 256, SM_TOT>>>(b4, x, D_DIM, H_DIM);

    // out = LN(y) * gamma + beta
    ln_kernel<<<Brows, 256>>>(gamma, beta, out);
}

// round 7
// speedup vs baseline: 2.2327x; 1.0089x over previous
#include <cuda_runtime.h>
#include <cuda_bf16.h>
#include <cstdint>

#define BATCH   16384
#define D_DIM   768
#define H_DIM   256
#define NQ      8
#define NL      2

// ---------------- scratch (device globals; no runtime allocation) -----------
__device__ __align__(256) float  g_h[BATCH * H_DIM];   // gelu(x@W1+b1)
__device__ __align__(256) float  g_y[BATCH * D_DIM];   // x + e@W4 + b4 (pre-LN)
__device__ float2 g_C[NL][NQ][4];

// bf16 hi/lo split operands
__device__ __align__(256) __nv_bfloat16 g_xh[BATCH * D_DIM];
__device__ __align__(256) __nv_bfloat16 g_xl[BATCH * D_DIM];
__device__ __align__(256) __nv_bfloat16 g_w1h[D_DIM * H_DIM];
__device__ __align__(256) __nv_bfloat16 g_w1l[D_DIM * H_DIM];
__device__ __align__(256) __nv_bfloat16 g_w4h[H_DIM * D_DIM];
__device__ __align__(256) __nv_bfloat16 g_w4l[H_DIM * D_DIM];
__device__ __align__(256) __nv_bfloat16 g_eh[BATCH * H_DIM];
__device__ __align__(256) __nv_bfloat16 g_el[BATCH * H_DIM];

// ---------------- helpers ----------------------------------------------------
__device__ __forceinline__ float2 cmul(float2 a, float2 b) {
    return make_float2(a.x * b.x - a.y * b.y, a.x * b.y + a.y * b.x);
}
__device__ __forceinline__ float2 cadd(float2 a, float2 b) {
    return make_float2(a.x + b.x, a.y + b.y);
}
__device__ __forceinline__ float gelu_exact(float v) {
    return 0.5f * v * (1.0f + erff(v * 0.70710678118654752f));
}
__device__ __forceinline__ uint32_t smem_to_u32(const void* p) {
    uint32_t a;
    asm("{ .reg .u64 t; cvta.to.shared.u64 t, %1; cvt.u32.u64 %0, t; }"
        : "=r"(a) : "l"(p));
    return a;
}
__device__ __forceinline__ void cvt4_hilo(float4 v, uint2& hi, uint2& lo) {
    __nv_bfloat16 h0 = __float2bfloat16(v.x), h1 = __float2bfloat16(v.y);
    __nv_bfloat16 h2 = __float2bfloat16(v.z), h3 = __float2bfloat16(v.w);
    __nv_bfloat16 l0 = __float2bfloat16(v.x - __bfloat162float(h0));
    __nv_bfloat16 l1 = __float2bfloat16(v.y - __bfloat162float(h1));
    __nv_bfloat16 l2 = __float2bfloat16(v.z - __bfloat162float(h2));
    __nv_bfloat16 l3 = __float2bfloat16(v.w - __bfloat162float(h3));
    hi.x = (uint32_t)__bfloat16_as_ushort(h0) | ((uint32_t)__bfloat16_as_ushort(h1) << 16);
    hi.y = (uint32_t)__bfloat16_as_ushort(h2) | ((uint32_t)__bfloat16_as_ushort(h3) << 16);
    lo.x = (uint32_t)__bfloat16_as_ushort(l0) | ((uint32_t)__bfloat16_as_ushort(l1) << 16);
    lo.y = (uint32_t)__bfloat16_as_ushort(l2) | ((uint32_t)__bfloat16_as_ushort(l3) << 16);
}
__device__ __forceinline__ float2 shfl2(float2 v, int mask) {
    v.x = __shfl_xor_sync(0xffffffffu, v.x, mask);
    v.y = __shfl_xor_sync(0xffffffffu, v.y, mask);
    return v;
}

__device__ __forceinline__ void ldsm_x4(uint32_t addr, uint32_t* r) {
    asm volatile("ldmatrix.sync.aligned.m8n8.x4.shared.b16 {%0,%1,%2,%3}, [%4];"
        : "=r"(r[0]), "=r"(r[1]), "=r"(r[2]), "=r"(r[3]) : "r"(addr));
}
__device__ __forceinline__ void ldsm_x4t(uint32_t addr, uint32_t* r) {
    asm volatile("ldmatrix.sync.aligned.m8n8.x4.trans.shared.b16 {%0,%1,%2,%3}, [%4];"
        : "=r"(r[0]), "=r"(r[1]), "=r"(r[2]), "=r"(r[3]) : "r"(addr));
}
__device__ __forceinline__ void mma16816(float* d, const uint32_t* a,
                                         uint32_t b0, uint32_t b1) {
    asm volatile(
        "mma.sync.aligned.m16n8k16.row.col.f32.bf16.bf16.f32 "
        "{%0,%1,%2,%3}, {%4,%5,%6,%7}, {%8,%9}, {%0,%1,%2,%3};"
        : "+f"(d[0]), "+f"(d[1]), "+f"(d[2]), "+f"(d[3])
        : "r"(a[0]), "r"(a[1]), "r"(a[2]), "r"(a[3]), "r"(b0), "r"(b1));
}
__device__ __forceinline__ void cp16(uint32_t saddr, const void* g) {
    asm volatile("cp.async.cg.shared.global [%0], [%1], 16;"
        :: "r"(saddr), "l"(g) : "memory");
}
#define CP_COMMIT() asm volatile("cp.async.commit_group;" ::: "memory")
#define CP_WAIT(n)  asm volatile("cp.async.wait_group %0;" :: "n"(n) : "memory")

// ---------------- K0: precompute C[l][i] -------------------------------------
__global__ void prep_gates(const float* __restrict__ qw) {
    int t = threadIdx.x;
    if (t >= NL * NQ) return;
    int l = t / NQ, i = t % NQ;
    float w0 = qw[(l * NQ + i) * 3 + 0];
    float w1 = qw[(l * NQ + i) * 3 + 1];
    float w2 = qw[(l * NQ + i) * 3 + 2];
    float c0 = cosf(0.5f * w0), s0 = sinf(0.5f * w0);
    float c1 = cosf(0.5f * w1), s1 = sinf(0.5f * w1);
    float c2 = cosf(0.5f * w2), s2 = sinf(0.5f * w2);
    float2 e0  = make_float2(c0, -s0);
    float2 e0c = make_float2(c0,  s0);
    float2 T00 = make_float2( c1 * e0.x,   c1 * e0.y);
    float2 T01 = make_float2(-s1 * e0c.x, -s1 * e0c.y);
    float2 T10 = make_float2( s1 * e0.x,   s1 * e0.y);
    float2 T11 = make_float2( c1 * e0c.x,  c1 * e0c.y);
    float2 e2  = make_float2(c2, -s2);
    float2 e2c = make_float2(c2,  s2);
    g_C[l][i][0] = cmul(e2,  T00);
    g_C[l][i][1] = cmul(e2,  T01);
    g_C[l][i][2] = cmul(e2c, T10);
    g_C[l][i][3] = cmul(e2c, T11);
}

// ---------------- prepass: fp32 -> bf16 hi/lo split --------------------------
__global__ __launch_bounds__(256) void conv_split(
    const float4* __restrict__ src, uint2* __restrict__ hi,
    uint2* __restrict__ lo, int n4)
{
    int i = blockIdx.x * 256 + threadIdx.x;
    if (i >= n4) return;
    float4 v = src[i];
    uint2 h, l; cvt4_hilo(v, h, l);
    hi[i] = h; lo[i] = l;
}
__global__ __launch_bounds__(256) void conv_split_w(
    const float4* __restrict__ w1, const float4* __restrict__ w4,
    uint2* __restrict__ w1h, uint2* __restrict__ w1l,
    uint2* __restrict__ w4h, uint2* __restrict__ w4l, int n4)
{
    int i = blockIdx.x * 256 + threadIdx.x;
    if (i >= 2 * n4) return;
    const float4* s = (i < n4) ? w1 : w4;
    int j = (i < n4) ? i : i - n4;
    float4 v = s[j];
    uint2 h, l; cvt4_hilo(v, h, l);
    if (i < n4) { w1h[j] = h; w1l[j] = l; }
    else        { w4h[j] = h; w4l[j] = l; }
}

// ---------------- bf16 hi/lo tensor-core GEMM, cp.async 3-stage --------------
#define STAGES 3
#define STAGE_BYTES 32768
#define SM_TOT (STAGES * STAGE_BYTES)

template <int EPI>
__global__ __launch_bounds__(256, 2) void mma_gemm(
    const float* __restrict__ bias, const float* __restrict__ resid,
    int N, int K)
{
    extern __shared__ char smem[];
    const __nv_bfloat16* Ah = (EPI == 1) ? g_eh : g_xh;
    const __nv_bfloat16* Al = (EPI == 1) ? g_el : g_xl;
    const __nv_bfloat16* Bh = (EPI == 1) ? g_w4h : g_w1h;
    const __nv_bfloat16* Bl = (EPI == 1) ? g_w4l : g_w1l;
    float* Cout = (EPI == 1) ? g_y : g_h;

    uint32_t sb = smem_to_u32(smem);
    int t = threadIdx.x, wid = t >> 5, lane = t & 31;
    int brow = blockIdx.y * 128, bcol = blockIdx.x * 128;
    int warpM = (wid & 3) * 32, warpN = (wid >> 2) * 64;
    int grp = lane >> 2, qc = lane & 3;

    float acc[2][8][4];
#pragma unroll
    for (int i = 0; i < 2; ++i)
#pragma unroll
        for (int j = 0; j < 8; ++j)
#pragma unroll
            for (int k = 0; k < 4; ++k) acc[i][j][k] = 0.f;

    int NC = K / 32;
    int a_row0 = t >> 2, a_kseg = t & 3;
    int b_kr0  = t >> 4, b_nseg = t & 15;

    // ---- hoisted ldmatrix base offsets (s enters via XOR 32 / +4096) ----
    uint32_t aoff[2], boff[4];
#pragma unroll
    for (int mf = 0; mf < 2; ++mf) {
        int m = warpM + mf * 16 + (lane & 15);
        aoff[mf] = (uint32_t)((m * 64 + (lane >> 4) * 16) ^ ((m & 7) << 4));
    }
#pragma unroll
    for (int n16 = 0; n16 < 4; ++n16) {
        uint32_t nb = (uint32_t)(warpN + n16 * 16 + (lane >> 4) * 8) * 2;
        boff[n16] = (uint32_t)((lane & 15) * 256) + (nb ^ (uint32_t)((lane & 7) << 4));
    }

    auto issue_stage = [&](int ck, int stg) {
        uint32_t base = sb + stg * STAGE_BYTES;
        int k0 = ck * 32;
#pragma unroll
        for (int i = 0; i < 2; ++i) {
            int row = a_row0 + i * 64;
            uint32_t off = (uint32_t)((row * 64 + a_kseg * 16) ^ ((row & 7) << 4));
            size_t gidx = (size_t)(brow + row) * K + k0 + a_kseg * 8;
            cp16(base + off, Ah + gidx);
            cp16(base + 8192 + off, Al + gidx);
        }
#pragma unroll
        for (int i = 0; i < 2; ++i) {
            int kr = b_kr0 + i * 16;
            uint32_t off = (uint32_t)((kr * 256 + b_nseg * 16) ^ ((kr & 7) << 4));
            size_t gidx = (size_t)(k0 + kr) * N + bcol + b_nseg * 8;
            cp16(base + 16384 + off, Bh + gidx);
            cp16(base + 24576 + off, Bl + gidx);
        }
    };

    // prologue: stages 0..STAGES-2
#pragma unroll
    for (int p = 0; p < STAGES - 1; ++p) {
        if (p < NC) issue_stage(p, p);
        CP_COMMIT();
    }

    for (int ck = 0; ck < NC; ++ck) {
        CP_WAIT(STAGES - 2);
        __syncthreads();               // all warps done with stage ck-1; stage ck ready

        int nx = ck + STAGES - 1;      // overwrite slot (ck-1)%S — safe post-barrier
        if (nx < NC) issue_stage(nx, nx % STAGES);
        CP_COMMIT();

        uint32_t base = sb + (uint32_t)((ck % STAGES) * STAGE_BYTES);
        uint32_t abase_h = base, abase_l = base + 8192;
        uint32_t bbase_h = base + 16384, bbase_l = base + 24576;

#pragma unroll
        for (int s = 0; s < 2; ++s) {
            uint32_t sa = (uint32_t)(s << 5);      // XOR into A offset (bit 5)
            uint32_t sbo = (uint32_t)(s * 4096);   // add into B offset
            uint32_t ah[2][4], al[2][4];
#pragma unroll
            for (int mf = 0; mf < 2; ++mf) {
                uint32_t off = aoff[mf] ^ sa;
                ldsm_x4(abase_h + off, ah[mf]);
                ldsm_x4(abase_l + off, al[mf]);
            }
#pragma unroll
            for (int n16 = 0; n16 < 4; ++n16) {
                uint32_t bh[4], bl[4];
                uint32_t off = boff[n16] + sbo;
                ldsm_x4t(bbase_h + off, bh);
                ldsm_x4t(bbase_l + off, bl);
#pragma unroll
                for (int half = 0; half < 2; ++half) {
                    int nf = n16 * 2 + half;
#pragma unroll
                    for (int mf = 0; mf < 2; ++mf) {
                        mma16816(acc[mf][nf], ah[mf], bh[half * 2], bh[half * 2 + 1]);
                        mma16816(acc[mf][nf], ah[mf], bl[half * 2], bl[half * 2 + 1]);
                        mma16816(acc[mf][nf], al[mf], bh[half * 2], bh[half * 2 + 1]);
                    }
                }
            }
        }
    }

    // ---- epilogue ----
#pragma unroll
    for (int mf = 0; mf < 2; ++mf) {
        int r0 = brow + warpM + mf * 16 + grp;
#pragma unroll
        for (int nf = 0; nf < 8; ++nf) {
            int col = bcol + warpN + nf * 8 + qc * 2;
            float bv0 = bias[col], bv1 = bias[col + 1];
            float v0 = acc[mf][nf][0] + bv0;
            float v1 = acc[mf][nf][1] + bv1;
            float v2 = acc[mf][nf][2] + bv0;
            float v3 = acc[mf][nf][3] + bv1;
            size_t o0 = (size_t)r0 * N + col;
            size_t o1 = o0 + (size_t)8 * N;
            if (EPI == 0) {
                v0 = gelu_exact(v0); v1 = gelu_exact(v1);
                v2 = gelu_exact(v2); v3 = gelu_exact(v3);
            } else {
                float2 ra = *(const float2*)(resid + o0);
                float2 rb = *(const float2*)(resid + o1);
                v0 += ra.x; v1 += ra.y; v2 += rb.x; v3 += rb.y;
            }
            *(float2*)(Cout + o0) = make_float2(v0, v1);
            *(float2*)(Cout + o1) = make_float2(v2, v3);
        }
    }
}

// ---------------- K2: quantum bottleneck, register statevector ---------------
#define QWARPS 8
__global__ __launch_bounds__(QWARPS * 32) void quantum_kernel(
    const float* __restrict__ W2, const float* __restrict__ b2,
    const float* __restrict__ W3, const float* __restrict__ b3,
    int Brows)
{
    int warp = threadIdx.x >> 5;
    int lane = threadIdx.x & 31;
    int row  = blockIdx.x * QWARPS + warp;
    if (row >= Brows) return;

    const float* hrow = g_h + (size_t)row * H_DIM;
    float fj[8] = {0, 0, 0, 0, 0, 0, 0, 0};
#pragma unroll
    for (int m = 0; m < 8; ++m) {
        int k = lane + 32 * m;
        float hv = hrow[k];
        const float4* w2p = (const float4*)(W2 + (size_t)k * 8);
        float4 wa = w2p[0], wb = w2p[1];
        fj[0] += hv * wa.x; fj[1] += hv * wa.y;
        fj[2] += hv * wa.z; fj[3] += hv * wa.w;
        fj[4] += hv * wb.x; fj[5] += hv * wb.y;
        fj[6] += hv * wb.z; fj[7] += hv * wb.w;
    }
#pragma unroll
    for (int j = 0; j < 8; ++j)
#pragma unroll
        for (int o = 16; o; o >>= 1)
            fj[j] += __shfl_xor_sync(0xffffffffu, fj[j], o);

    float cf[8], sf[8];
#pragma unroll
    for (int j = 0; j < 8; ++j) {
        float f = 0.5f * (fj[j] + b2[j]);
        cf[j] = cosf(f);
        sf[j] = sinf(f);
    }

    float2 amp[8];
#pragma unroll
    for (int r = 0; r < 8; ++r) amp[r] = make_float2(0.f, 0.f);
    if (lane == 0) amp[0] = make_float2(1.f, 0.f);

#pragma unroll
    for (int l = 0; l < NL; ++l) {
#pragma unroll
        for (int i = 0; i < NQ; ++i) {
            float2 C00 = g_C[l][i][0], C01 = g_C[l][i][1];
            float2 C10 = g_C[l][i][2], C11 = g_C[l][i][3];
            float c = cf[i], s = sf[i];
            float2 U00 = make_float2(C00.x * c + C01.x * s, C00.y * c + C01.y * s);
            float2 U01 = make_float2(C01.x * c - C00.x * s, C01.y * c - C00.y * s);
            float2 U10 = make_float2(C10.x * c + C11.x * s, C10.y * c + C11.y * s);
            float2 U11 = make_float2(C11.x * c - C10.x * s, C11.y * c - C10.y * s);
            const int sbit = 7 - i;
            if (sbit >= 5) {
                const int rb = 1 << (sbit - 5);
#pragma unroll
                for (int r0 = 0; r0 < 8; ++r0) {
                    if (r0 & rb) continue;
                    float2 a = amp[r0], b = amp[r0 | rb];
                    amp[r0]      = cadd(cmul(U00, a), cmul(U01, b));
                    amp[r0 | rb] = cadd(cmul(U10, a), cmul(U11, b));
                }
            } else {
                const int lb = 1 << sbit;
                bool hi = (lane >> sbit) & 1;
#pragma unroll
                for (int r = 0; r < 8; ++r) {
                    float2 o = shfl2(amp[r], lb);
                    float2 lo_v = cadd(cmul(U00, amp[r]), cmul(U01, o));
                    float2 hi_v = cadd(cmul(U10, o), cmul(U11, amp[r]));
                    amp[r] = hi ? hi_v : lo_v;
                }
            }
        }
#pragma unroll
        for (int i = 0; i < NQ; ++i) {
            const int cb = 7 - i;
            const int tb = 7 - ((i + 1) & 7);
            if (tb >= 5) {
                const int rb = 1 << (tb - 5);
                if (cb >= 5) {
                    const int crb = 1 << (cb - 5);
#pragma unroll
                    for (int r0 = 0; r0 < 8; ++r0) {
                        if ((r0 & rb) || !(r0 & crb)) continue;
                        float2 tmp = amp[r0];
                        amp[r0] = amp[r0 | rb];
                        amp[r0 | rb] = tmp;
                    }
                } else {
                    bool cset = (lane >> cb) & 1;
#pragma unroll
                    for (int r0 = 0; r0 < 8; ++r0) {
                        if (r0 & rb) continue;
                        float2 a = amp[r0], b = amp[r0 | rb];
                        amp[r0]      = cset ? b : a;
                        amp[r0 | rb] = cset ? a : b;
                    }
                }
            } else {
                const int lb = 1 << tb;
#pragma unroll
                for (int r = 0; r < 8; ++r) {
                    float2 o = shfl2(amp[r], lb);
                    bool cset = (cb >= 5) ? ((r >> (cb - 5)) & 1)
                                          : ((lane >> cb) & 1);
                    amp[r] = cset ? o : amp[r];
                }
            }
        }
    }

    float zf[8] = {0, 0, 0, 0, 0, 0, 0, 0};
#pragma unroll
    for (int r = 0; r < 8; ++r) {
        int idx = (r << 5) | lane;
        float p = amp[r].x * amp[r].x + amp[r].y * amp[r].y;
#pragma unroll
        for (int i = 0; i < 8; ++i)
            zf[i] += ((idx >> (7 - i)) & 1) ? -p : p;
    }
#pragma unroll
    for (int j = 0; j < 8; ++j)
#pragma unroll
        for (int o = 16; o; o >>= 1)
            zf[j] += __shfl_xor_sync(0xffffffffu, zf[j], o);

    size_t ebase = (size_t)row * H_DIM;
#pragma unroll
    for (int m = 0; m < 8; ++m) {
        int k = lane + 32 * m;
        float acc = b3[k];
#pragma unroll
        for (int j = 0; j < 8; ++j) acc += zf[j] * W3[j * H_DIM + k];
        float v = gelu_exact(acc);
        __nv_bfloat16 h = __float2bfloat16(v);
        g_eh[ebase + k] = h;
        g_el[ebase + k] = __float2bfloat16(v - __bfloat162float(h));
    }
}

// ---------------- K4: LayerNorm over D=768 -----------------------------------
__global__ __launch_bounds__(256) void ln_kernel(
    const float* __restrict__ gamma, const float* __restrict__ beta,
    float* __restrict__ out)
{
    int row = blockIdx.x;
    const float* yr = g_y + (size_t)row * D_DIM;
    int tid = threadIdx.x;

    float v[3];
    float sum = 0.f, sq = 0.f;
#pragma unroll
    for (int m = 0; m < 3; ++m) {
        v[m] = yr[tid + 256 * m];
        sum += v[m];
        sq  += v[m] * v[m];
    }
#pragma unroll
    for (int o = 16; o; o >>= 1) {
        sum += __shfl_xor_sync(0xffffffffu, sum, o);
        sq  += __shfl_xor_sync(0xffffffffu, sq,  o);
    }
    __shared__ float red[2][8];
    int w = tid >> 5;
    if ((tid & 31) == 0) { red[0][w] = sum; red[1][w] = sq; }
    __syncthreads();
    sum = 0.f; sq = 0.f;
#pragma unroll
    for (int i = 0; i < 8; ++i) { sum += red[0][i]; sq += red[1][i]; }

    float mu  = sum * (1.0f / D_DIM);
    float var = sq * (1.0f / D_DIM) - mu * mu;
    float inv = rsqrtf(var + 1e-5f);

    float* orow = out + (size_t)row * D_DIM;
#pragma unroll
    for (int m = 0; m < 3; ++m) {
        int k = tid + 256 * m;
        orow[k] = gamma[k] * (v[m] - mu) * inv + beta[k];
    }
}

// ---------------- launch ------------------------------------------------------
extern "C" void kernel_launch(void* const* d_in, const int* in_sizes, int n_in,
                              void* d_out, int out_size) {
    const float* x     = (const float*)d_in[0];
    const float* W1    = (const float*)d_in[1];
    const float* b1    = (const float*)d_in[2];
    const float* W2    = (const float*)d_in[3];
    const float* b2    = (const float*)d_in[4];
    const float* qw    = (const float*)d_in[5];
    const float* W3    = (const float*)d_in[6];
    const float* b3    = (const float*)d_in[7];
    const float* W4    = (const float*)d_in[8];
    const float* b4    = (const float*)d_in[9];
    const float* gamma = (const float*)d_in[10];
    const float* beta  = (const float*)d_in[11];
    float* out = (float*)d_out;

    int Brows = in_sizes[0] / D_DIM;   // 16384

    cudaFuncSetAttribute(mma_gemm<0>, cudaFuncAttributeMaxDynamicSharedMemorySize, SM_TOT);
    cudaFuncSetAttribute(mma_gemm<1>, cudaFuncAttributeMaxDynamicSharedMemorySize, SM_TOT);

    void *pxh, *pxl, *pw1h, *pw1l, *pw4h, *pw4l;
    cudaGetSymbolAddress(&pxh, g_xh);   cudaGetSymbolAddress(&pxl, g_xl);
    cudaGetSymbolAddress(&pw1h, g_w1h); cudaGetSymbolAddress(&pw1l, g_w1l);
    cudaGetSymbolAddress(&pw4h, g_w4h); cudaGetSymbolAddress(&pw4l, g_w4l);

    prep_gates<<<1, 32>>>(qw);

    int nx4 = (Brows * D_DIM) / 4;
    conv_split<<<(nx4 + 255) / 256, 256>>>((const float4*)x, (uint2*)pxh, (uint2*)pxl, nx4);
    int nw4 = (D_DIM * H_DIM) / 4;
    conv_split_w<<<(2 * nw4 + 255) / 256, 256>>>(
        (const float4*)W1, (const float4*)W4,
        (uint2*)pw1h, (uint2*)pw1l, (uint2*)pw4h, (uint2*)pw4l, nw4);

    // h = gelu(x @ W1 + b1)
    dim3 g1(H_DIM / 128, Brows / 128);
    mma_gemm<0><<<g1, 256, SM_TOT>>>(b1, nullptr, H_DIM, D_DIM);

    // quantum bottleneck -> e (bf16 hi/lo)
    quantum_kernel<<<Brows / QWARPS, QWARPS * 32>>>(W2, b2, W3, b3, Brows);

    // y = x + e @ W4 + b4
    dim3 g2(D_DIM / 128, Brows / 128);
    mma_gemm<1><<<g2, 256, SM_TOT>>>(b4, x, D_DIM, H_DIM);

    // out = LN(y) * gamma + beta
    ln_kernel<<<Brows, 256>>>(gamma, beta, out);
}

// round 8
// speedup vs baseline: 2.9441x; 1.3186x over previous
#include <cuda_runtime.h>
#include <cuda_fp16.h>
#include <cstdint>

#define BATCH   16384
#define D_DIM   768
#define H_DIM   256
#define NQ      8
#define NL      2

// ---------------- scratch (device globals; no runtime allocation) -----------
__device__ __align__(256) float  g_h[BATCH * H_DIM];   // gelu(x@W1+b1)
__device__ __align__(256) float  g_y[BATCH * D_DIM];   // x + e@W4 + b4 (pre-LN)
__device__ float2 g_C[NL][NQ][4];

// fp16 operands
__device__ __align__(256) __half g_xf[BATCH * D_DIM];
__device__ __align__(256) __half g_w1f[D_DIM * H_DIM];
__device__ __align__(256) __half g_w4f[H_DIM * D_DIM];
__device__ __align__(256) __half g_ef[BATCH * H_DIM];

// ---------------- helpers ----------------------------------------------------
__device__ __forceinline__ float2 cmul(float2 a, float2 b) {
    return make_float2(a.x * b.x - a.y * b.y, a.x * b.y + a.y * b.x);
}
__device__ __forceinline__ float2 cadd(float2 a, float2 b) {
    return make_float2(a.x + b.x, a.y + b.y);
}
__device__ __forceinline__ float gelu_exact(float v) {
    return 0.5f * v * (1.0f + erff(v * 0.70710678118654752f));
}
__device__ __forceinline__ uint32_t smem_to_u32(const void* p) {
    uint32_t a;
    asm("{ .reg .u64 t; cvta.to.shared.u64 t, %1; cvt.u32.u64 %0, t; }"
        : "=r"(a) : "l"(p));
    return a;
}
__device__ __forceinline__ uint2 cvt4_f16(float4 v) {
    __half2 p0 = __floats2half2_rn(v.x, v.y);
    __half2 p1 = __floats2half2_rn(v.z, v.w);
    uint2 o;
    o.x = *reinterpret_cast<uint32_t*>(&p0);
    o.y = *reinterpret_cast<uint32_t*>(&p1);
    return o;
}
__device__ __forceinline__ float2 shfl2(float2 v, int mask) {
    v.x = __shfl_xor_sync(0xffffffffu, v.x, mask);
    v.y = __shfl_xor_sync(0xffffffffu, v.y, mask);
    return v;
}

__device__ __forceinline__ void ldsm_x4(uint32_t addr, uint32_t* r) {
    asm volatile("ldmatrix.sync.aligned.m8n8.x4.shared.b16 {%0,%1,%2,%3}, [%4];"
        : "=r"(r[0]), "=r"(r[1]), "=r"(r[2]), "=r"(r[3]) : "r"(addr));
}
__device__ __forceinline__ void ldsm_x4t(uint32_t addr, uint32_t* r) {
    asm volatile("ldmatrix.sync.aligned.m8n8.x4.trans.shared.b16 {%0,%1,%2,%3}, [%4];"
        : "=r"(r[0]), "=r"(r[1]), "=r"(r[2]), "=r"(r[3]) : "r"(addr));
}
__device__ __forceinline__ void mma16816(float* d, const uint32_t* a,
                                         uint32_t b0, uint32_t b1) {
    asm volatile(
        "mma.sync.aligned.m16n8k16.row.col.f32.f16.f16.f32 "
        "{%0,%1,%2,%3}, {%4,%5,%6,%7}, {%8,%9}, {%0,%1,%2,%3};"
        : "+f"(d[0]), "+f"(d[1]), "+f"(d[2]), "+f"(d[3])
        : "r"(a[0]), "r"(a[1]), "r"(a[2]), "r"(a[3]), "r"(b0), "r"(b1));
}
__device__ __forceinline__ void cp16(uint32_t saddr, const void* g) {
    asm volatile("cp.async.cg.shared.global [%0], [%1], 16;"
        :: "r"(saddr), "l"(g) : "memory");
}
#define CP_COMMIT() asm volatile("cp.async.commit_group;" ::: "memory")
#define CP_WAIT(n)  asm volatile("cp.async.wait_group %0;" :: "n"(n) : "memory")

// ---------------- K0: precompute C[l][i] -------------------------------------
__global__ void prep_gates(const float* __restrict__ qw) {
    int t = threadIdx.x;
    if (t >= NL * NQ) return;
    int l = t / NQ, i = t % NQ;
    float w0 = qw[(l * NQ + i) * 3 + 0];
    float w1 = qw[(l * NQ + i) * 3 + 1];
    float w2 = qw[(l * NQ + i) * 3 + 2];
    float c0 = cosf(0.5f * w0), s0 = sinf(0.5f * w0);
    float c1 = cosf(0.5f * w1), s1 = sinf(0.5f * w1);
    float c2 = cosf(0.5f * w2), s2 = sinf(0.5f * w2);
    float2 e0  = make_float2(c0, -s0);
    float2 e0c = make_float2(c0,  s0);
    float2 T00 = make_float2( c1 * e0.x,   c1 * e0.y);
    float2 T01 = make_float2(-s1 * e0c.x, -s1 * e0c.y);
    float2 T10 = make_float2( s1 * e0.x,   s1 * e0.y);
    float2 T11 = make_float2( c1 * e0c.x,  c1 * e0c.y);
    float2 e2  = make_float2(c2, -s2);
    float2 e2c = make_float2(c2,  s2);
    g_C[l][i][0] = cmul(e2,  T00);
    g_C[l][i][1] = cmul(e2,  T01);
    g_C[l][i][2] = cmul(e2c, T10);
    g_C[l][i][3] = cmul(e2c, T11);
}

// ---------------- prepass: fp32 -> fp16 --------------------------------------
__global__ __launch_bounds__(256) void conv_half(
    const float4* __restrict__ src, uint2* __restrict__ dst, int n4)
{
    int i = blockIdx.x * 256 + threadIdx.x;
    if (i >= n4) return;
    dst[i] = cvt4_f16(src[i]);
}
__global__ __launch_bounds__(256) void conv_half_w(
    const float4* __restrict__ w1, const float4* __restrict__ w4,
    uint2* __restrict__ w1f, uint2* __restrict__ w4f, int n4)
{
    int i = blockIdx.x * 256 + threadIdx.x;
    if (i >= 2 * n4) return;
    if (i < n4) w1f[i] = cvt4_f16(w1[i]);
    else        w4f[i - n4] = cvt4_f16(w4[i - n4]);
}

// ---------------- fp16 tensor-core GEMM, cp.async 4-stage --------------------
// EPI==0: g_h = gelu(x@W1 + b1)
// EPI==1: g_y = resid + e@W4 + bias
#define STAGES 4
#define STAGE_BYTES 16384
#define SM_TOT (STAGES * STAGE_BYTES)

template <int EPI>
__global__ __launch_bounds__(256, 2) void mma_gemm(
    const float* __restrict__ bias, const float* __restrict__ resid,
    int N, int K)
{
    extern __shared__ char smem[];
    const __half* Af = (EPI == 1) ? g_ef : g_xf;
    const __half* Bf = (EPI == 1) ? g_w4f : g_w1f;
    float* Cout = (EPI == 1) ? g_y : g_h;

    uint32_t sb = smem_to_u32(smem);
    int t = threadIdx.x, wid = t >> 5, lane = t & 31;
    int brow = blockIdx.y * 128, bcol = blockIdx.x * 128;
    int warpM = (wid & 3) * 32, warpN = (wid >> 2) * 64;
    int grp = lane >> 2, qc = lane & 3;

    float acc[2][8][4];
#pragma unroll
    for (int i = 0; i < 2; ++i)
#pragma unroll
        for (int j = 0; j < 8; ++j)
#pragma unroll
            for (int k = 0; k < 4; ++k) acc[i][j][k] = 0.f;

    int NC = K / 32;
    int a_row0 = t >> 2, a_kseg = t & 3;
    int b_kr0  = t >> 4, b_nseg = t & 15;

    // hoisted ldmatrix base offsets
    uint32_t aoff[2], boff[4];
#pragma unroll
    for (int mf = 0; mf < 2; ++mf) {
        int m = warpM + mf * 16 + (lane & 15);
        aoff[mf] = (uint32_t)((m * 64 + (lane >> 4) * 16) ^ ((m & 7) << 4));
    }
#pragma unroll
    for (int n16 = 0; n16 < 4; ++n16) {
        uint32_t nb = (uint32_t)(warpN + n16 * 16 + (lane >> 4) * 8) * 2;
        boff[n16] = (uint32_t)((lane & 15) * 256) + (nb ^ (uint32_t)((lane & 7) << 4));
    }

    auto issue_stage = [&](int ck, int stg) {
        uint32_t base = sb + stg * STAGE_BYTES;
        int k0 = ck * 32;
#pragma unroll
        for (int i = 0; i < 2; ++i) {
            int row = a_row0 + i * 64;
            uint32_t off = (uint32_t)((row * 64 + a_kseg * 16) ^ ((row & 7) << 4));
            cp16(base + off, Af + (size_t)(brow + row) * K + k0 + a_kseg * 8);
        }
#pragma unroll
        for (int i = 0; i < 2; ++i) {
            int kr = b_kr0 + i * 16;
            uint32_t off = (uint32_t)((kr * 256 + b_nseg * 16) ^ ((kr & 7) << 4));
            cp16(base + 8192 + off, Bf + (size_t)(k0 + kr) * N + bcol + b_nseg * 8);
        }
    };

    // prologue: stages 0..STAGES-2
#pragma unroll
    for (int p = 0; p < STAGES - 1; ++p) {
        if (p < NC) issue_stage(p, p);
        CP_COMMIT();
    }

    for (int ck = 0; ck < NC; ++ck) {
        CP_WAIT(STAGES - 2);
        __syncthreads();

        int nx = ck + STAGES - 1;
        if (nx < NC) issue_stage(nx, nx % STAGES);
        CP_COMMIT();

        uint32_t base = sb + (uint32_t)((ck % STAGES) * STAGE_BYTES);
        uint32_t bbase = base + 8192;

#pragma unroll
        for (int s = 0; s < 2; ++s) {
            uint32_t sa = (uint32_t)(s << 5);
            uint32_t sbo = (uint32_t)(s * 4096);
            uint32_t ah[2][4];
#pragma unroll
            for (int mf = 0; mf < 2; ++mf)
                ldsm_x4(base + (aoff[mf] ^ sa), ah[mf]);
#pragma unroll
            for (int n16 = 0; n16 < 4; ++n16) {
                uint32_t bh[4];
                ldsm_x4t(bbase + boff[n16] + sbo, bh);
#pragma unroll
                for (int half = 0; half < 2; ++half) {
                    int nf = n16 * 2 + half;
#pragma unroll
                    for (int mf = 0; mf < 2; ++mf)
                        mma16816(acc[mf][nf], ah[mf], bh[half * 2], bh[half * 2 + 1]);
                }
            }
        }
    }

    // ---- epilogue ----
#pragma unroll
    for (int mf = 0; mf < 2; ++mf) {
        int r0 = brow + warpM + mf * 16 + grp;
#pragma unroll
        for (int nf = 0; nf < 8; ++nf) {
            int col = bcol + warpN + nf * 8 + qc * 2;
            float bv0 = bias[col], bv1 = bias[col + 1];
            float v0 = acc[mf][nf][0] + bv0;
            float v1 = acc[mf][nf][1] + bv1;
            float v2 = acc[mf][nf][2] + bv0;
            float v3 = acc[mf][nf][3] + bv1;
            size_t o0 = (size_t)r0 * N + col;
            size_t o1 = o0 + (size_t)8 * N;
            if (EPI == 0) {
                v0 = gelu_exact(v0); v1 = gelu_exact(v1);
                v2 = gelu_exact(v2); v3 = gelu_exact(v3);
            } else {
                float2 ra = *(const float2*)(resid + o0);
                float2 rb = *(const float2*)(resid + o1);
                v0 += ra.x; v1 += ra.y; v2 += rb.x; v3 += rb.y;
            }
            *(float2*)(Cout + o0) = make_float2(v0, v1);
            *(float2*)(Cout + o1) = make_float2(v2, v3);
        }
    }
}

// ---------------- K2: quantum bottleneck, register statevector ---------------
#define QWARPS 8
__global__ __launch_bounds__(QWARPS * 32) void quantum_kernel(
    const float* __restrict__ W2, const float* __restrict__ b2,
    const float* __restrict__ W3, const float* __restrict__ b3,
    int Brows)
{
    int warp = threadIdx.x >> 5;
    int lane = threadIdx.x & 31;
    int row  = blockIdx.x * QWARPS + warp;
    if (row >= Brows) return;

    const float* hrow = g_h + (size_t)row * H_DIM;
    float fj[8] = {0, 0, 0, 0, 0, 0, 0, 0};
#pragma unroll
    for (int m = 0; m < 8; ++m) {
        int k = lane + 32 * m;
        float hv = hrow[k];
        const float4* w2p = (const float4*)(W2 + (size_t)k * 8);
        float4 wa = w2p[0], wb = w2p[1];
        fj[0] += hv * wa.x; fj[1] += hv * wa.y;
        fj[2] += hv * wa.z; fj[3] += hv * wa.w;
        fj[4] += hv * wb.x; fj[5] += hv * wb.y;
        fj[6] += hv * wb.z; fj[7] += hv * wb.w;
    }
#pragma unroll
    for (int j = 0; j < 8; ++j)
#pragma unroll
        for (int o = 16; o; o >>= 1)
            fj[j] += __shfl_xor_sync(0xffffffffu, fj[j], o);

    float cf[8], sf[8];
#pragma unroll
    for (int j = 0; j < 8; ++j) {
        float f = 0.5f * (fj[j] + b2[j]);
        cf[j] = cosf(f);
        sf[j] = sinf(f);
    }

    float2 amp[8];
#pragma unroll
    for (int r = 0; r < 8; ++r) amp[r] = make_float2(0.f, 0.f);
    if (lane == 0) amp[0] = make_float2(1.f, 0.f);

#pragma unroll
    for (int l = 0; l < NL; ++l) {
#pragma unroll
        for (int i = 0; i < NQ; ++i) {
            float2 C00 = g_C[l][i][0], C01 = g_C[l][i][1];
            float2 C10 = g_C[l][i][2], C11 = g_C[l][i][3];
            float c = cf[i], s = sf[i];
            float2 U00 = make_float2(C00.x * c + C01.x * s, C00.y * c + C01.y * s);
            float2 U01 = make_float2(C01.x * c - C00.x * s, C01.y * c - C00.y * s);
            float2 U10 = make_float2(C10.x * c + C11.x * s, C10.y * c + C11.y * s);
            float2 U11 = make_float2(C11.x * c - C10.x * s, C11.y * c - C10.y * s);
            const int sbit = 7 - i;
            if (sbit >= 5) {
                const int rb = 1 << (sbit - 5);
#pragma unroll
                for (int r0 = 0; r0 < 8; ++r0) {
                    if (r0 & rb) continue;
                    float2 a = amp[r0], b = amp[r0 | rb];
                    amp[r0]      = cadd(cmul(U00, a), cmul(U01, b));
                    amp[r0 | rb] = cadd(cmul(U10, a), cmul(U11, b));
                }
            } else {
                const int lb = 1 << sbit;
                bool hi = (lane >> sbit) & 1;
#pragma unroll
                for (int r = 0; r < 8; ++r) {
                    float2 o = shfl2(amp[r], lb);
                    float2 lo_v = cadd(cmul(U00, amp[r]), cmul(U01, o));
                    float2 hi_v = cadd(cmul(U10, o), cmul(U11, amp[r]));
                    amp[r] = hi ? hi_v : lo_v;
                }
            }
        }
#pragma unroll
        for (int i = 0; i < NQ; ++i) {
            const int cb = 7 - i;
            const int tb = 7 - ((i + 1) & 7);
            if (tb >= 5) {
                const int rb = 1 << (tb - 5);
                if (cb >= 5) {
                    const int crb = 1 << (cb - 5);
#pragma unroll
                    for (int r0 = 0; r0 < 8; ++r0) {
                        if ((r0 & rb) || !(r0 & crb)) continue;
                        float2 tmp = amp[r0];
                        amp[r0] = amp[r0 | rb];
                        amp[r0 | rb] = tmp;
                    }
                } else {
                    bool cset = (lane >> cb) & 1;
#pragma unroll
                    for (int r0 = 0; r0 < 8; ++r0) {
                        if (r0 & rb) continue;
                        float2 a = amp[r0], b = amp[r0 | rb];
                        amp[r0]      = cset ? b : a;
                        amp[r0 | rb] = cset ? a : b;
                    }
                }
            } else {
                const int lb = 1 << tb;
#pragma unroll
                for (int r = 0; r < 8; ++r) {
                    float2 o = shfl2(amp[r], lb);
                    bool cset = (cb >= 5) ? ((r >> (cb - 5)) & 1)
                                          : ((lane >> cb) & 1);
                    amp[r] = cset ? o : amp[r];
                }
            }
        }
    }

    float zf[8] = {0, 0, 0, 0, 0, 0, 0, 0};
#pragma unroll
    for (int r = 0; r < 8; ++r) {
        int idx = (r << 5) | lane;
        float p = amp[r].x * amp[r].x + amp[r].y * amp[r].y;
#pragma unroll
        for (int i = 0; i < 8; ++i)
            zf[i] += ((idx >> (7 - i)) & 1) ? -p : p;
    }
#pragma unroll
    for (int j = 0; j < 8; ++j)
#pragma unroll
        for (int o = 16; o; o >>= 1)
            zf[j] += __shfl_xor_sync(0xffffffffu, zf[j], o);

    size_t ebase = (size_t)row * H_DIM;
#pragma unroll
    for (int m = 0; m < 8; ++m) {
        int k = lane + 32 * m;
        float acc = b3[k];
#pragma unroll
        for (int j = 0; j < 8; ++j) acc += zf[j] * W3[j * H_DIM + k];
        g_ef[ebase + k] = __float2half(gelu_exact(acc));
    }
}

// ---------------- K4: LayerNorm over D=768 -----------------------------------
__global__ __launch_bounds__(256) void ln_kernel(
    const float* __restrict__ gamma, const float* __restrict__ beta,
    float* __restrict__ out)
{
    int row = blockIdx.x;
    const float* yr = g_y + (size_t)row * D_DIM;
    int tid = threadIdx.x;

    float v[3];
    float sum = 0.f, sq = 0.f;
#pragma unroll
    for (int m = 0; m < 3; ++m) {
        v[m] = yr[tid + 256 * m];
        sum += v[m];
        sq  += v[m] * v[m];
    }
#pragma unroll
    for (int o = 16; o; o >>= 1) {
        sum += __shfl_xor_sync(0xffffffffu, sum, o);
        sq  += __shfl_xor_sync(0xffffffffu, sq,  o);
    }
    __shared__ float red[2][8];
    int w = tid >> 5;
    if ((tid & 31) == 0) { red[0][w] = sum; red[1][w] = sq; }
    __syncthreads();
    sum = 0.f; sq = 0.f;
#pragma unroll
    for (int i = 0; i < 8; ++i) { sum += red[0][i]; sq += red[1][i]; }

    float mu  = sum * (1.0f / D_DIM);
    float var = sq * (1.0f / D_DIM) - mu * mu;
    float inv = rsqrtf(var + 1e-5f);

    float* orow = out + (size_t)row * D_DIM;
#pragma unroll
    for (int m = 0; m < 3; ++m) {
        int k = tid + 256 * m;
        orow[k] = gamma[k] * (v[m] - mu) * inv + beta[k];
    }
}

// ---------------- launch ------------------------------------------------------
extern "C" void kernel_launch(void* const* d_in, const int* in_sizes, int n_in,
                              void* d_out, int out_size) {
    const float* x     = (const float*)d_in[0];
    const float* W1    = (const float*)d_in[1];
    const float* b1    = (const float*)d_in[2];
    const float* W2    = (const float*)d_in[3];
    const float* b2    = (const float*)d_in[4];
    const float* qw    = (const float*)d_in[5];
    const float* W3    = (const float*)d_in[6];
    const float* b3    = (const float*)d_in[7];
    const float* W4    = (const float*)d_in[8];
    const float* b4    = (const float*)d_in[9];
    const float* gamma = (const float*)d_in[10];
    const float* beta  = (const float*)d_in[11];
    float* out = (float*)d_out;

    int Brows = in_sizes[0] / D_DIM;   // 16384

    cudaFuncSetAttribute(mma_gemm<0>, cudaFuncAttributeMaxDynamicSharedMemorySize, SM_TOT);
    cudaFuncSetAttribute(mma_gemm<1>, cudaFuncAttributeMaxDynamicSharedMemorySize, SM_TOT);

    void *pxf, *pw1f, *pw4f;
    cudaGetSymbolAddress(&pxf, g_xf);
    cudaGetSymbolAddress(&pw1f, g_w1f);
    cudaGetSymbolAddress(&pw4f, g_w4f);

    prep_gates<<<1, 32>>>(qw);

    int nx4 = (Brows * D_DIM) / 4;
    conv_half<<<(nx4 + 255) / 256, 256>>>((const float4*)x, (uint2*)pxf, nx4);
    int nw4 = (D_DIM * H_DIM) / 4;
    conv_half_w<<<(2 * nw4 + 255) / 256, 256>>>(
        (const float4*)W1, (const float4*)W4, (uint2*)pw1f, (uint2*)pw4f, nw4);

    // h = gelu(x @ W1 + b1)
    dim3 g1(H_DIM / 128, Brows / 128);
    mma_gemm<0><<<g1, 256, SM_TOT>>>(b1, nullptr, H_DIM, D_DIM);

    // quantum bottleneck -> e (fp16)
    quantum_kernel<<<Brows / QWARPS, QWARPS * 32>>>(W2, b2, W3, b3, Brows);

    // y = x + e @ W4 + b4
    dim3 g2(D_DIM / 128, Brows / 128);
    mma_gemm<1><<<g2, 256, SM_TOT>>>(b4, x, D_DIM, H_DIM);

    // out = LN(y) * gamma + beta
    ln_kernel<<<Brows, 256>>>(gamma, beta, out);
}

// round 9
// speedup vs baseline: 3.1202x; 1.0598x over previous
#include <cuda_runtime.h>
#include <cuda_fp16.h>
#include <cstdint>

#define BATCH   16384
#define D_DIM   768
#define H_DIM   256
#define NQ      8
#define NL      2

// ---------------- scratch (device globals; no runtime allocation) -----------
__device__ __align__(256) float  g_h[BATCH * H_DIM];   // gelu(x@W1+b1)
__device__ __align__(256) float  g_y[BATCH * D_DIM];   // x + e@W4 + b4 (pre-LN)
__device__ float2 g_C[NL][NQ][4];

// fp16 operands
__device__ __align__(256) __half g_xf[BATCH * D_DIM];
__device__ __align__(256) __half g_w1f[D_DIM * H_DIM];
__device__ __align__(256) __half g_w4f[H_DIM * D_DIM];
__device__ __align__(256) __half g_ef[BATCH * H_DIM];

// ---------------- helpers ----------------------------------------------------
__device__ __forceinline__ float2 cmul(float2 a, float2 b) {
    return make_float2(a.x * b.x - a.y * b.y, a.x * b.y + a.y * b.x);
}
__device__ __forceinline__ float2 cadd(float2 a, float2 b) {
    return make_float2(a.x + b.x, a.y + b.y);
}
__device__ __forceinline__ float gelu_exact(float v) {
    return 0.5f * v * (1.0f + erff(v * 0.70710678118654752f));
}
__device__ __forceinline__ uint32_t smem_to_u32(const void* p) {
    uint32_t a;
    asm("{ .reg .u64 t; cvta.to.shared.u64 t, %1; cvt.u32.u64 %0, t; }"
        : "=r"(a) : "l"(p));
    return a;
}
__device__ __forceinline__ uint2 cvt4_f16(float4 v) {
    __half2 p0 = __floats2half2_rn(v.x, v.y);
    __half2 p1 = __floats2half2_rn(v.z, v.w);
    uint2 o;
    o.x = *reinterpret_cast<uint32_t*>(&p0);
    o.y = *reinterpret_cast<uint32_t*>(&p1);
    return o;
}
__device__ __forceinline__ float2 shfl2(float2 v, int mask) {
    v.x = __shfl_xor_sync(0xffffffffu, v.x, mask);
    v.y = __shfl_xor_sync(0xffffffffu, v.y, mask);
    return v;
}

__device__ __forceinline__ void ldsm_x4(uint32_t addr, uint32_t* r) {
    asm volatile("ldmatrix.sync.aligned.m8n8.x4.shared.b16 {%0,%1,%2,%3}, [%4];"
        : "=r"(r[0]), "=r"(r[1]), "=r"(r[2]), "=r"(r[3]) : "r"(addr));
}
__device__ __forceinline__ void ldsm_x4t(uint32_t addr, uint32_t* r) {
    asm volatile("ldmatrix.sync.aligned.m8n8.x4.trans.shared.b16 {%0,%1,%2,%3}, [%4];"
        : "=r"(r[0]), "=r"(r[1]), "=r"(r[2]), "=r"(r[3]) : "r"(addr));
}
__device__ __forceinline__ void mma16816(float* d, const uint32_t* a,
                                         uint32_t b0, uint32_t b1) {
    asm volatile(
        "mma.sync.aligned.m16n8k16.row.col.f32.f16.f16.f32 "
        "{%0,%1,%2,%3}, {%4,%5,%6,%7}, {%8,%9}, {%0,%1,%2,%3};"
        : "+f"(d[0]), "+f"(d[1]), "+f"(d[2]), "+f"(d[3])
        : "r"(a[0]), "r"(a[1]), "r"(a[2]), "r"(a[3]), "r"(b0), "r"(b1));
}
__device__ __forceinline__ void cp16(uint32_t saddr, const void* g) {
    asm volatile("cp.async.cg.shared.global [%0], [%1], 16;"
        :: "r"(saddr), "l"(g) : "memory");
}
#define CP_COMMIT() asm volatile("cp.async.commit_group;" ::: "memory")
#define CP_WAIT(n)  asm volatile("cp.async.wait_group %0;" :: "n"(n) : "memory")

// ---------------- K0: precompute C[l][i] -------------------------------------
__global__ void prep_gates(const float* __restrict__ qw) {
    int t = threadIdx.x;
    if (t >= NL * NQ) return;
    int l = t / NQ, i = t % NQ;
    float w0 = qw[(l * NQ + i) * 3 + 0];
    float w1 = qw[(l * NQ + i) * 3 + 1];
    float w2 = qw[(l * NQ + i) * 3 + 2];
    float c0 = cosf(0.5f * w0), s0 = sinf(0.5f * w0);
    float c1 = cosf(0.5f * w1), s1 = sinf(0.5f * w1);
    float c2 = cosf(0.5f * w2), s2 = sinf(0.5f * w2);
    float2 e0  = make_float2(c0, -s0);
    float2 e0c = make_float2(c0,  s0);
    float2 T00 = make_float2( c1 * e0.x,   c1 * e0.y);
    float2 T01 = make_float2(-s1 * e0c.x, -s1 * e0c.y);
    float2 T10 = make_float2( s1 * e0.x,   s1 * e0.y);
    float2 T11 = make_float2( c1 * e0c.x,  c1 * e0c.y);
    float2 e2  = make_float2(c2, -s2);
    float2 e2c = make_float2(c2,  s2);
    g_C[l][i][0] = cmul(e2,  T00);
    g_C[l][i][1] = cmul(e2,  T01);
    g_C[l][i][2] = cmul(e2c, T10);
    g_C[l][i][3] = cmul(e2c, T11);
}

// ---------------- prepass: fp32 -> fp16 --------------------------------------
__global__ __launch_bounds__(256) void conv_half(
    const float4* __restrict__ src, uint2* __restrict__ dst, int n4)
{
    int i = blockIdx.x * 256 + threadIdx.x;
    if (i >= n4) return;
    dst[i] = cvt4_f16(src[i]);
}
__global__ __launch_bounds__(256) void conv_half_w(
    const float4* __restrict__ w1, const float4* __restrict__ w4,
    uint2* __restrict__ w1f, uint2* __restrict__ w4f, int n4)
{
    int i = blockIdx.x * 256 + threadIdx.x;
    if (i >= 2 * n4) return;
    if (i < n4) w1f[i] = cvt4_f16(w1[i]);
    else        w4f[i - n4] = cvt4_f16(w4[i - n4]);
}

// ---------------- fp16 tensor-core GEMM, cp.async 4-stage --------------------
#define STAGES 4
#define STAGE_BYTES 16384
#define SM_TOT (STAGES * STAGE_BYTES)

template <int EPI>
__global__ __launch_bounds__(256, 2) void mma_gemm(
    const float* __restrict__ bias, const float* __restrict__ resid,
    int N, int K)
{
    extern __shared__ char smem[];
    const __half* Af = (EPI == 1) ? g_ef : g_xf;
    const __half* Bf = (EPI == 1) ? g_w4f : g_w1f;
    float* Cout = (EPI == 1) ? g_y : g_h;

    uint32_t sb = smem_to_u32(smem);
    int t = threadIdx.x, wid = t >> 5, lane = t & 31;
    int brow = blockIdx.y * 128, bcol = blockIdx.x * 128;
    int warpM = (wid & 3) * 32, warpN = (wid >> 2) * 64;
    int grp = lane >> 2, qc = lane & 3;

    float acc[2][8][4];
#pragma unroll
    for (int i = 0; i < 2; ++i)
#pragma unroll
        for (int j = 0; j < 8; ++j)
#pragma unroll
            for (int k = 0; k < 4; ++k) acc[i][j][k] = 0.f;

    int NC = K / 32;
    int a_row0 = t >> 2, a_kseg = t & 3;
    int b_kr0  = t >> 4, b_nseg = t & 15;

    uint32_t aoff[2], boff[4];
#pragma unroll
    for (int mf = 0; mf < 2; ++mf) {
        int m = warpM + mf * 16 + (lane & 15);
        aoff[mf] = (uint32_t)((m * 64 + (lane >> 4) * 16) ^ ((m & 7) << 4));
    }
#pragma unroll
    for (int n16 = 0; n16 < 4; ++n16) {
        uint32_t nb = (uint32_t)(warpN + n16 * 16 + (lane >> 4) * 8) * 2;
        boff[n16] = (uint32_t)((lane & 15) * 256) + (nb ^ (uint32_t)((lane & 7) << 4));
    }

    auto issue_stage = [&](int ck, int stg) {
        uint32_t base = sb + stg * STAGE_BYTES;
        int k0 = ck * 32;
#pragma unroll
        for (int i = 0; i < 2; ++i) {
            int row = a_row0 + i * 64;
            uint32_t off = (uint32_t)((row * 64 + a_kseg * 16) ^ ((row & 7) << 4));
            cp16(base + off, Af + (size_t)(brow + row) * K + k0 + a_kseg * 8);
        }
#pragma unroll
        for (int i = 0; i < 2; ++i) {
            int kr = b_kr0 + i * 16;
            uint32_t off = (uint32_t)((kr * 256 + b_nseg * 16) ^ ((kr & 7) << 4));
            cp16(base + 8192 + off, Bf + (size_t)(k0 + kr) * N + bcol + b_nseg * 8);
        }
    };

#pragma unroll
    for (int p = 0; p < STAGES - 1; ++p) {
        if (p < NC) issue_stage(p, p);
        CP_COMMIT();
    }

    for (int ck = 0; ck < NC; ++ck) {
        CP_WAIT(STAGES - 2);
        __syncthreads();

        int nx = ck + STAGES - 1;
        if (nx < NC) issue_stage(nx, nx % STAGES);
        CP_COMMIT();

        uint32_t base = sb + (uint32_t)((ck % STAGES) * STAGE_BYTES);
        uint32_t bbase = base + 8192;

#pragma unroll
        for (int s = 0; s < 2; ++s) {
            uint32_t sa = (uint32_t)(s << 5);
            uint32_t sbo = (uint32_t)(s * 4096);
            uint32_t ah[2][4];
#pragma unroll
            for (int mf = 0; mf < 2; ++mf)
                ldsm_x4(base + (aoff[mf] ^ sa), ah[mf]);
#pragma unroll
            for (int n16 = 0; n16 < 4; ++n16) {
                uint32_t bh[4];
                ldsm_x4t(bbase + boff[n16] + sbo, bh);
#pragma unroll
                for (int half = 0; half < 2; ++half) {
                    int nf = n16 * 2 + half;
#pragma unroll
                    for (int mf = 0; mf < 2; ++mf)
                        mma16816(acc[mf][nf], ah[mf], bh[half * 2], bh[half * 2 + 1]);
                }
            }
        }
    }

#pragma unroll
    for (int mf = 0; mf < 2; ++mf) {
        int r0 = brow + warpM + mf * 16 + grp;
#pragma unroll
        for (int nf = 0; nf < 8; ++nf) {
            int col = bcol + warpN + nf * 8 + qc * 2;
            float bv0 = bias[col], bv1 = bias[col + 1];
            float v0 = acc[mf][nf][0] + bv0;
            float v1 = acc[mf][nf][1] + bv1;
            float v2 = acc[mf][nf][2] + bv0;
            float v3 = acc[mf][nf][3] + bv1;
            size_t o0 = (size_t)r0 * N + col;
            size_t o1 = o0 + (size_t)8 * N;
            if (EPI == 0) {
                v0 = gelu_exact(v0); v1 = gelu_exact(v1);
                v2 = gelu_exact(v2); v3 = gelu_exact(v3);
            } else {
                float2 ra = *(const float2*)(resid + o0);
                float2 rb = *(const float2*)(resid + o1);
                v0 += ra.x; v1 += ra.y; v2 += rb.x; v3 += rb.y;
            }
            *(float2*)(Cout + o0) = make_float2(v0, v1);
            *(float2*)(Cout + o1) = make_float2(v2, v3);
        }
    }
}

// ---------------- K2: quantum bottleneck --------------------------------------
// Register statevector: slot u = (r<<5)|lane (bit p of u: p=7-w for wire w).
// CNOT rings are bit-linear permutations tracked symbolically (zero cost):
//   layer-2 gate masks  m = Minv[7-j], predicates h = Mrow[7-j] (after ring 1)
//   measurement parity masks = rows of M after ring 2.
// All masks are compile-time constants (ring structure is fixed).

// generic pair-update gate with compile-time XOR mask M_ and predicate mask H_
template <int M_, int H_>
__device__ __forceinline__ void apply_gate(float2* amp, int lane,
    float2 U00, float2 U01, float2 U10, float2 U11)
{
    constexpr int mreg  = (M_ >> 5) & 7;
    constexpr int mlane = M_ & 31;
    constexpr int hreg  = (H_ >> 5) & 7;
    constexpr int hlane = H_ & 31;
    bool lp = (__popc(lane & hlane) & 1) != 0;
    if (mreg == 0) {
#pragma unroll
        for (int r = 0; r < 8; ++r) {
            constexpr_parity:;
            bool hi = lp ^ ((__popc(r & hreg) & 1) != 0);
            float2 o = shfl2(amp[r], mlane);
            float2 lo_v = cadd(cmul(U00, amp[r]), cmul(U01, o));
            float2 hi_v = cadd(cmul(U10, o), cmul(U11, amp[r]));
            amp[r] = hi ? hi_v : lo_v;
        }
    } else {
#pragma unroll
        for (int r = 0; r < 8; ++r) {
            constexpr int pr_static = 0;  // placeholder (loop var math below)
            (void)pr_static;
            int pr = r ^ mreg;
            if (r < pr) {
                float2 a = amp[r], b = amp[pr];
                float2 ash = (mlane != 0) ? shfl2(a, mlane) : a;
                float2 bsh = (mlane != 0) ? shfl2(b, mlane) : b;
                bool hi_r  = lp ^ ((__popc(r  & hreg) & 1) != 0);
                bool hi_pr = lp ^ ((__popc(pr & hreg) & 1) != 0);
                amp[r]  = hi_r  ? cadd(cmul(U10, bsh), cmul(U11, a))
                                : cadd(cmul(U00, a),   cmul(U01, bsh));
                amp[pr] = hi_pr ? cadd(cmul(U10, ash), cmul(U11, b))
                                : cadd(cmul(U00, b),   cmul(U01, ash));
            }
        }
    }
}

#define QWARPS 8
__global__ __launch_bounds__(QWARPS * 32) void quantum_kernel(
    const float* __restrict__ W2, const float* __restrict__ b2,
    const float* __restrict__ W3, const float* __restrict__ b3,
    int Brows)
{
    int warp = threadIdx.x >> 5;
    int lane = threadIdx.x & 31;
    int row  = blockIdx.x * QWARPS + warp;
    if (row >= Brows) return;

    // ---- feats_j = h_row . W2[:,j] + b2[j] ----
    const float* hrow = g_h + (size_t)row * H_DIM;
    float fj[8] = {0, 0, 0, 0, 0, 0, 0, 0};
#pragma unroll
    for (int m = 0; m < 8; ++m) {
        int k = lane + 32 * m;
        float hv = hrow[k];
        const float4* w2p = (const float4*)(W2 + (size_t)k * 8);
        float4 wa = w2p[0], wb = w2p[1];
        fj[0] += hv * wa.x; fj[1] += hv * wa.y;
        fj[2] += hv * wa.z; fj[3] += hv * wa.w;
        fj[4] += hv * wb.x; fj[5] += hv * wb.y;
        fj[6] += hv * wb.z; fj[7] += hv * wb.w;
    }
#pragma unroll
    for (int j = 0; j < 8; ++j)
#pragma unroll
        for (int o = 16; o; o >>= 1)
            fj[j] += __shfl_xor_sync(0xffffffffu, fj[j], o);

    float cf[8], sf[8];
#pragma unroll
    for (int j = 0; j < 8; ++j) {
        float f = 0.5f * (fj[j] + b2[j]);
        cf[j] = cosf(f);
        sf[j] = sinf(f);
    }

    // ---- layer 1 as direct product state: amp[u] = prod_w Uw|0>(bit_w(u)) ----
    // Uw|0> = (C00*c + C01*s, C10*c + C11*s)
    float2 v0[8], v1[8];
#pragma unroll
    for (int w = 0; w < 8; ++w) {
        float2 C00 = g_C[0][w][0], C01 = g_C[0][w][1];
        float2 C10 = g_C[0][w][2], C11 = g_C[0][w][3];
        v0[w] = make_float2(C00.x * cf[w] + C01.x * sf[w], C00.y * cf[w] + C01.y * sf[w]);
        v1[w] = make_float2(C10.x * cf[w] + C11.x * sf[w], C10.y * cf[w] + C11.y * sf[w]);
    }
    // lane part: wires 3..7 at lane bits 4..0
    float2 pl = (lane & 16) ? v1[3] : v0[3];
    pl = cmul(pl, (lane & 8) ? v1[4] : v0[4]);
    pl = cmul(pl, (lane & 4) ? v1[5] : v0[5]);
    pl = cmul(pl, (lane & 2) ? v1[6] : v0[6]);
    pl = cmul(pl, (lane & 1) ? v1[7] : v0[7]);
    // register part: wires 0..2 at r bits 2,1,0 (shared subproducts)
    float2 p01[4];
    p01[0] = cmul(v0[0], v0[1]); p01[1] = cmul(v0[0], v1[1]);
    p01[2] = cmul(v1[0], v0[1]); p01[3] = cmul(v1[0], v1[1]);
    float2 amp[8];
#pragma unroll
    for (int r = 0; r < 8; ++r)
        amp[r] = cmul(cmul(p01[r >> 1], (r & 1) ? v1[2] : v0[2]), pl);

    // ---- ring 1: free (bookkeeping only). layer-2 gates in permuted frame ----
    float2 U00[8], U01[8], U10[8], U11[8];
#pragma unroll
    for (int w = 0; w < 8; ++w) {
        float2 C00 = g_C[1][w][0], C01 = g_C[1][w][1];
        float2 C10 = g_C[1][w][2], C11 = g_C[1][w][3];
        float c = cf[w], s = sf[w];
        U00[w] = make_float2(C00.x * c + C01.x * s, C00.y * c + C01.y * s);
        U01[w] = make_float2(C01.x * c - C00.x * s, C01.y * c - C00.y * s);
        U10[w] = make_float2(C10.x * c + C11.x * s, C10.y * c + C11.y * s);
        U11[w] = make_float2(C11.x * c - C10.x * s, C11.y * c - C10.y * s);
    }
    // masks (compile-time): wire j -> (m, h)
    apply_gate<0xC0, 0x7F>(amp, lane, U00[0], U01[0], U10[0], U11[0]);
    apply_gate<0x60, 0xC0>(amp, lane, U00[1], U01[1], U10[1], U11[1]);
    apply_gate<0x30, 0xE0>(amp, lane, U00[2], U01[2], U10[2], U11[2]);
    apply_gate<0x18, 0xF0>(amp, lane, U00[3], U01[3], U10[3], U11[3]);
    apply_gate<0x0C, 0xF8>(amp, lane, U00[4], U01[4], U10[4], U11[4]);
    apply_gate<0x06, 0xFC>(amp, lane, U00[5], U01[5], U10[5], U11[5]);
    apply_gate<0x03, 0xFE>(amp, lane, U00[6], U01[6], U10[6], U11[6]);
    apply_gate<0xC1, 0xFF>(amp, lane, U00[7], U01[7], U10[7], U11[7]);

    // ---- ring 2: free. measurement with parity masks of final M ----
    // meas[i] for wires 0..7: D5 BF 5F AF 57 AB 55 AA
    const int measm[8] = {0xD5, 0xBF, 0x5F, 0xAF, 0x57, 0xAB, 0x55, 0xAA};
    bool lpar[8];
#pragma unroll
    for (int i = 0; i < 8; ++i)
        lpar[i] = (__popc(lane & (measm[i] & 31)) & 1) != 0;

    float zf[8] = {0, 0, 0, 0, 0, 0, 0, 0};
#pragma unroll
    for (int r = 0; r < 8; ++r) {
        float p = amp[r].x * amp[r].x + amp[r].y * amp[r].y;
#pragma unroll
        for (int i = 0; i < 8; ++i) {
            bool neg = lpar[i] ^ ((__popc(r & (measm[i] >> 5)) & 1) != 0);
            zf[i] += neg ? -p : p;
        }
    }
#pragma unroll
    for (int j = 0; j < 8; ++j)
#pragma unroll
        for (int o = 16; o; o >>= 1)
            zf[j] += __shfl_xor_sync(0xffffffffu, zf[j], o);

    // ---- e = gelu(z @ W3 + b3), fp16 ----
    size_t ebase = (size_t)row * H_DIM;
#pragma unroll
    for (int m = 0; m < 8; ++m) {
        int k = lane + 32 * m;
        float acc = b3[k];
#pragma unroll
        for (int j = 0; j < 8; ++j) acc += zf[j] * W3[j * H_DIM + k];
        g_ef[ebase + k] = __float2half(gelu_exact(acc));
    }
}

// ---------------- K4: LayerNorm over D=768 -----------------------------------
__global__ __launch_bounds__(256) void ln_kernel(
    const float* __restrict__ gamma, const float* __restrict__ beta,
    float* __restrict__ out)
{
    int row = blockIdx.x;
    const float* yr = g_y + (size_t)row * D_DIM;
    int tid = threadIdx.x;

    float v[3];
    float sum = 0.f, sq = 0.f;
#pragma unroll
    for (int m = 0; m < 3; ++m) {
        v[m] = yr[tid + 256 * m];
        sum += v[m];
        sq  += v[m] * v[m];
    }
#pragma unroll
    for (int o = 16; o; o >>= 1) {
        sum += __shfl_xor_sync(0xffffffffu, sum, o);
        sq  += __shfl_xor_sync(0xffffffffu, sq,  o);
    }
    __shared__ float red[2][8];
    int w = tid >> 5;
    if ((tid & 31) == 0) { red[0][w] = sum; red[1][w] = sq; }
    __syncthreads();
    sum = 0.f; sq = 0.f;
#pragma unroll
    for (int i = 0; i < 8; ++i) { sum += red[0][i]; sq += red[1][i]; }

    float mu  = sum * (1.0f / D_DIM);
    float var = sq * (1.0f / D_DIM) - mu * mu;
    float inv = rsqrtf(var + 1e-5f);

    float* orow = out + (size_t)row * D_DIM;
#pragma unroll
    for (int m = 0; m < 3; ++m) {
        int k = tid + 256 * m;
        orow[k] = gamma[k] * (v[m] - mu) * inv + beta[k];
    }
}

// ---------------- launch ------------------------------------------------------
extern "C" void kernel_launch(void* const* d_in, const int* in_sizes, int n_in,
                              void* d_out, int out_size) {
    const float* x     = (const float*)d_in[0];
    const float* W1    = (const float*)d_in[1];
    const float* b1    = (const float*)d_in[2];
    const float* W2    = (const float*)d_in[3];
    const float* b2    = (const float*)d_in[4];
    const float* qw    = (const float*)d_in[5];
    const float* W3    = (const float*)d_in[6];
    const float* b3    = (const float*)d_in[7];
    const float* W4    = (const float*)d_in[8];
    const float* b4    = (const float*)d_in[9];
    const float* gamma = (const float*)d_in[10];
    const float* beta  = (const float*)d_in[11];
    float* out = (float*)d_out;

    int Brows = in_sizes[0] / D_DIM;   // 16384

    cudaFuncSetAttribute(mma_gemm<0>, cudaFuncAttributeMaxDynamicSharedMemorySize, SM_TOT);
    cudaFuncSetAttribute(mma_gemm<1>, cudaFuncAttributeMaxDynamicSharedMemorySize, SM_TOT);

    void *pxf, *pw1f, *pw4f;
    cudaGetSymbolAddress(&pxf, g_xf);
    cudaGetSymbolAddress(&pw1f, g_w1f);
    cudaGetSymbolAddress(&pw4f, g_w4f);

    prep_gates<<<1, 32>>>(qw);

    int nx4 = (Brows * D_DIM) / 4;
    conv_half<<<(nx4 + 255) / 256, 256>>>((const float4*)x, (uint2*)pxf, nx4);
    int nw4 = (D_DIM * H_DIM) / 4;
    conv_half_w<<<(2 * nw4 + 255) / 256, 256>>>(
        (const float4*)W1, (const float4*)W4, (uint2*)pw1f, (uint2*)pw4f, nw4);

    // h = gelu(x @ W1 + b1)
    dim3 g1(H_DIM / 128, Brows / 128);
    mma_gemm<0><<<g1, 256, SM_TOT>>>(b1, nullptr, H_DIM, D_DIM);

    // quantum bottleneck -> e (fp16)
    quantum_kernel<<<Brows / QWARPS, QWARPS * 32>>>(W2, b2, W3, b3, Brows);

    // y = x + e @ W4 + b4
    dim3 g2(D_DIM / 128, Brows / 128);
    mma_gemm<1><<<g2, 256, SM_TOT>>>(b4, x, D_DIM, H_DIM);

    // out = LN(y) * gamma + beta
    ln_kernel<<<Brows, 256>>>(gamma, beta, out);
}

// round 10
// speedup vs baseline: 3.2296x; 1.0350x over previous
#include <cuda_runtime.h>
#include <cuda_fp16.h>
#include <cstdint>

#define BATCH   16384
#define D_DIM   768
#define H_DIM   256
#define NQ      8
#define NL      2

// ---------------- scratch -----------------------------------------------------
__device__ __align__(256) float  g_h[BATCH * H_DIM];   // gelu(x@W1+b1)
__device__ float2 g_C[NL][NQ][4];

__device__ __align__(256) __half g_xf[BATCH * D_DIM];
__device__ __align__(256) __half g_w1f[D_DIM * H_DIM];
__device__ __align__(256) __half g_w4f[H_DIM * D_DIM];
__device__ __align__(256) __half g_ef[BATCH * H_DIM];

// ---------------- helpers ------------------------------------------------------
__device__ __forceinline__ float2 cmul(float2 a, float2 b) {
    return make_float2(a.x * b.x - a.y * b.y, a.x * b.y + a.y * b.x);
}
__device__ __forceinline__ float2 cadd(float2 a, float2 b) {
    return make_float2(a.x + b.x, a.y + b.y);
}
__device__ __forceinline__ float gelu_exact(float v) {
    return 0.5f * v * (1.0f + erff(v * 0.70710678118654752f));
}
__device__ __forceinline__ uint32_t smem_to_u32(const void* p) {
    uint32_t a;
    asm("{ .reg .u64 t; cvta.to.shared.u64 t, %1; cvt.u32.u64 %0, t; }"
        : "=r"(a) : "l"(p));
    return a;
}
__device__ __forceinline__ uint2 cvt4_f16(float4 v) {
    __half2 p0 = __floats2half2_rn(v.x, v.y);
    __half2 p1 = __floats2half2_rn(v.z, v.w);
    uint2 o;
    o.x = *reinterpret_cast<uint32_t*>(&p0);
    o.y = *reinterpret_cast<uint32_t*>(&p1);
    return o;
}
__device__ __forceinline__ float2 shfl2(float2 v, int mask) {
    v.x = __shfl_xor_sync(0xffffffffu, v.x, mask);
    v.y = __shfl_xor_sync(0xffffffffu, v.y, mask);
    return v;
}

__device__ __forceinline__ void ldsm_x4(uint32_t addr, uint32_t* r) {
    asm volatile("ldmatrix.sync.aligned.m8n8.x4.shared.b16 {%0,%1,%2,%3}, [%4];"
        : "=r"(r[0]), "=r"(r[1]), "=r"(r[2]), "=r"(r[3]) : "r"(addr));
}
__device__ __forceinline__ void ldsm_x4t(uint32_t addr, uint32_t* r) {
    asm volatile("ldmatrix.sync.aligned.m8n8.x4.trans.shared.b16 {%0,%1,%2,%3}, [%4];"
        : "=r"(r[0]), "=r"(r[1]), "=r"(r[2]), "=r"(r[3]) : "r"(addr));
}
__device__ __forceinline__ void mma16816(float* d, const uint32_t* a,
                                         uint32_t b0, uint32_t b1) {
    asm volatile(
        "mma.sync.aligned.m16n8k16.row.col.f32.f16.f16.f32 "
        "{%0,%1,%2,%3}, {%4,%5,%6,%7}, {%8,%9}, {%0,%1,%2,%3};"
        : "+f"(d[0]), "+f"(d[1]), "+f"(d[2]), "+f"(d[3])
        : "r"(a[0]), "r"(a[1]), "r"(a[2]), "r"(a[3]), "r"(b0), "r"(b1));
}
__device__ __forceinline__ void cp16(uint32_t saddr, const void* g) {
    asm volatile("cp.async.cg.shared.global [%0], [%1], 16;"
        :: "r"(saddr), "l"(g) : "memory");
}
#define CP_COMMIT() asm volatile("cp.async.commit_group;" ::: "memory")
#define CP_WAIT(n)  asm volatile("cp.async.wait_group %0;" :: "n"(n) : "memory")

// ---------------- K0: precompute C[l][i] -------------------------------------
__global__ void prep_gates(const float* __restrict__ qw) {
    int t = threadIdx.x;
    if (t >= NL * NQ) return;
    int l = t / NQ, i = t % NQ;
    float w0 = qw[(l * NQ + i) * 3 + 0];
    float w1 = qw[(l * NQ + i) * 3 + 1];
    float w2 = qw[(l * NQ + i) * 3 + 2];
    float c0 = cosf(0.5f * w0), s0 = sinf(0.5f * w0);
    float c1 = cosf(0.5f * w1), s1 = sinf(0.5f * w1);
    float c2 = cosf(0.5f * w2), s2 = sinf(0.5f * w2);
    float2 e0  = make_float2(c0, -s0);
    float2 e0c = make_float2(c0,  s0);
    float2 T00 = make_float2( c1 * e0.x,   c1 * e0.y);
    float2 T01 = make_float2(-s1 * e0c.x, -s1 * e0c.y);
    float2 T10 = make_float2( s1 * e0.x,   s1 * e0.y);
    float2 T11 = make_float2( c1 * e0c.x,  c1 * e0c.y);
    float2 e2  = make_float2(c2, -s2);
    float2 e2c = make_float2(c2,  s2);
    g_C[l][i][0] = cmul(e2,  T00);
    g_C[l][i][1] = cmul(e2,  T01);
    g_C[l][i][2] = cmul(e2c, T10);
    g_C[l][i][3] = cmul(e2c, T11);
}

// ---------------- prepass: fp32 -> fp16 --------------------------------------
__global__ __launch_bounds__(256) void conv_half(
    const float4* __restrict__ src, uint2* __restrict__ dst, int n4)
{
    int i = blockIdx.x * 256 + threadIdx.x;
    if (i >= n4) return;
    dst[i] = cvt4_f16(src[i]);
}
__global__ __launch_bounds__(256) void conv_half_w(
    const float4* __restrict__ w1, const float4* __restrict__ w4,
    uint2* __restrict__ w1f, uint2* __restrict__ w4f, int n4)
{
    int i = blockIdx.x * 256 + threadIdx.x;
    if (i >= 2 * n4) return;
    if (i < n4) w1f[i] = cvt4_f16(w1[i]);
    else        w4f[i - n4] = cvt4_f16(w4[i - n4]);
}

// ---------------- GEMM-1: h = gelu(x@W1+b1), fp16 MMA, 4-stage ---------------
#define STAGES 4
#define STAGE_BYTES 16384
#define SM_TOT (STAGES * STAGE_BYTES)

__global__ __launch_bounds__(256, 2) void gemm_gelu(
    const float* __restrict__ bias, int N, int K)
{
    extern __shared__ char smem[];
    const __half* Af = g_xf;
    const __half* Bf = g_w1f;
    float* Cout = g_h;

    uint32_t sb = smem_to_u32(smem);
    int t = threadIdx.x, wid = t >> 5, lane = t & 31;
    int brow = blockIdx.y * 128, bcol = blockIdx.x * 128;
    int warpM = (wid & 3) * 32, warpN = (wid >> 2) * 64;
    int grp = lane >> 2, qc = lane & 3;

    float acc[2][8][4];
#pragma unroll
    for (int i = 0; i < 2; ++i)
#pragma unroll
        for (int j = 0; j < 8; ++j)
#pragma unroll
            for (int k = 0; k < 4; ++k) acc[i][j][k] = 0.f;

    int NC = K / 32;
    int a_row0 = t >> 2, a_kseg = t & 3;
    int b_kr0  = t >> 4, b_nseg = t & 15;

    uint32_t aoff[2], boff[4];
#pragma unroll
    for (int mf = 0; mf < 2; ++mf) {
        int m = warpM + mf * 16 + (lane & 15);
        aoff[mf] = (uint32_t)((m * 64 + (lane >> 4) * 16) ^ ((m & 7) << 4));
    }
#pragma unroll
    for (int n16 = 0; n16 < 4; ++n16) {
        uint32_t nb = (uint32_t)(warpN + n16 * 16 + (lane >> 4) * 8) * 2;
        boff[n16] = (uint32_t)((lane & 15) * 256) + (nb ^ (uint32_t)((lane & 7) << 4));
    }

    auto issue_stage = [&](int ck, int stg) {
        uint32_t base = sb + stg * STAGE_BYTES;
        int k0 = ck * 32;
#pragma unroll
        for (int i = 0; i < 2; ++i) {
            int row = a_row0 + i * 64;
            uint32_t off = (uint32_t)((row * 64 + a_kseg * 16) ^ ((row & 7) << 4));
            cp16(base + off, Af + (size_t)(brow + row) * K + k0 + a_kseg * 8);
        }
#pragma unroll
        for (int i = 0; i < 2; ++i) {
            int kr = b_kr0 + i * 16;
            uint32_t off = (uint32_t)((kr * 256 + b_nseg * 16) ^ ((kr & 7) << 4));
            cp16(base + 8192 + off, Bf + (size_t)(k0 + kr) * N + bcol + b_nseg * 8);
        }
    };

#pragma unroll
    for (int p = 0; p < STAGES - 1; ++p) {
        if (p < NC) issue_stage(p, p);
        CP_COMMIT();
    }

    for (int ck = 0; ck < NC; ++ck) {
        CP_WAIT(STAGES - 2);
        __syncthreads();

        int nx = ck + STAGES - 1;
        if (nx < NC) issue_stage(nx, nx % STAGES);
        CP_COMMIT();

        uint32_t base = sb + (uint32_t)((ck % STAGES) * STAGE_BYTES);
        uint32_t bbase = base + 8192;

#pragma unroll
        for (int s = 0; s < 2; ++s) {
            uint32_t sa = (uint32_t)(s << 5);
            uint32_t sbo = (uint32_t)(s * 4096);
            uint32_t ah[2][4];
#pragma unroll
            for (int mf = 0; mf < 2; ++mf)
                ldsm_x4(base + (aoff[mf] ^ sa), ah[mf]);
#pragma unroll
            for (int n16 = 0; n16 < 4; ++n16) {
                uint32_t bh[4];
                ldsm_x4t(bbase + boff[n16] + sbo, bh);
#pragma unroll
                for (int half = 0; half < 2; ++half) {
                    int nf = n16 * 2 + half;
#pragma unroll
                    for (int mf = 0; mf < 2; ++mf)
                        mma16816(acc[mf][nf], ah[mf], bh[half * 2], bh[half * 2 + 1]);
                }
            }
        }
    }

#pragma unroll
    for (int mf = 0; mf < 2; ++mf) {
        int r0 = brow + warpM + mf * 16 + grp;
#pragma unroll
        for (int nf = 0; nf < 8; ++nf) {
            int col = bcol + warpN + nf * 8 + qc * 2;
            float bv0 = bias[col], bv1 = bias[col + 1];
            float v0 = gelu_exact(acc[mf][nf][0] + bv0);
            float v1 = gelu_exact(acc[mf][nf][1] + bv1);
            float v2 = gelu_exact(acc[mf][nf][2] + bv0);
            float v3 = gelu_exact(acc[mf][nf][3] + bv1);
            size_t o0 = (size_t)r0 * N + col;
            size_t o1 = o0 + (size_t)8 * N;
            *(float2*)(Cout + o0) = make_float2(v0, v1);
            *(float2*)(Cout + o1) = make_float2(v2, v3);
        }
    }
}

// ---------------- GEMM-2 fused: out = LN(x + e@W4 + b4) ----------------------
// CTA tile: M=32 full-width rows (N=768), K=256. 8 warps x 96 cols.
#define LSTAGES 3
#define LA_BYTES 2048
#define LB_BYTES 49152
#define LSTAGE_BYTES (LA_BYTES + LB_BYTES)
#define SM_TOT2 (LSTAGES * LSTAGE_BYTES)

__global__ __launch_bounds__(256, 1) void gemm_resid_ln(
    const float* __restrict__ bias, const float* __restrict__ resid,
    const float* __restrict__ gamma, const float* __restrict__ beta,
    float* __restrict__ out)
{
    extern __shared__ char smem[];
    const __half* Af = g_ef;     // [B,256]
    const __half* Bf = g_w4f;    // [256,768]
    const int N = D_DIM, K = H_DIM;

    uint32_t sb = smem_to_u32(smem);
    int t = threadIdx.x, wid = t >> 5, lane = t & 31;
    int brow = blockIdx.x * 32;
    int grp = lane >> 2, qc = lane & 3;

    float acc[2][12][4];
#pragma unroll
    for (int i = 0; i < 2; ++i)
#pragma unroll
        for (int j = 0; j < 12; ++j)
#pragma unroll
            for (int k = 0; k < 4; ++k) acc[i][j][k] = 0.f;

    const int NC = K / 32;   // 8

    // A copy coords (threads 0..127): row = t>>2 (0..31), kseg = t&3
    int a_row = t >> 2, a_kseg = t & 3;
    // B copy coords: kr = t>>3 (0..31), nc0 = t&7; 12 iters cover nc 0..95
    int b_kr = t >> 3, b_nc0 = t & 7;

    // hoisted ldmatrix offsets
    uint32_t aoff[2], boff[6];
#pragma unroll
    for (int mf = 0; mf < 2; ++mf) {
        int m = mf * 16 + (lane & 15);
        aoff[mf] = (uint32_t)((m * 64 + (lane >> 4) * 16) ^ ((m & 7) << 4));
    }
#pragma unroll
    for (int n16 = 0; n16 < 6; ++n16) {
        uint32_t nb = (uint32_t)(wid * 96 + n16 * 16 + (lane >> 4) * 8) * 2;
        boff[n16] = (uint32_t)((lane & 15) * 1536) + (nb ^ (uint32_t)((lane & 7) << 4));
    }

    auto issue_stage = [&](int ck, int stg) {
        uint32_t base = sb + stg * LSTAGE_BYTES;
        int k0 = ck * 32;
        if (t < 128) {
            uint32_t off = (uint32_t)((a_row * 64 + a_kseg * 16) ^ ((a_row & 7) << 4));
            cp16(base + off, Af + (size_t)(brow + a_row) * K + k0 + a_kseg * 8);
        }
        uint32_t bb = base + LA_BYTES;
#pragma unroll
        for (int i = 0; i < 12; ++i) {
            int nc = b_nc0 + i * 8;
            uint32_t off = (uint32_t)(b_kr * 1536 + ((nc * 16) ^ ((b_kr & 7) << 4)));
            cp16(bb + off, Bf + (size_t)(k0 + b_kr) * N + nc * 8);
        }
    };

#pragma unroll
    for (int p = 0; p < LSTAGES - 1; ++p) {
        if (p < NC) issue_stage(p, p);
        CP_COMMIT();
    }

    for (int ck = 0; ck < NC; ++ck) {
        CP_WAIT(LSTAGES - 2);
        __syncthreads();

        int nx = ck + LSTAGES - 1;
        if (nx < NC) issue_stage(nx, nx % LSTAGES);
        CP_COMMIT();

        uint32_t base = sb + (uint32_t)((ck % LSTAGES) * LSTAGE_BYTES);
        uint32_t bbase = base + LA_BYTES;

#pragma unroll
        for (int s = 0; s < 2; ++s) {
            uint32_t sa = (uint32_t)(s << 5);
            uint32_t sbo = (uint32_t)(s * 16 * 1536);
            uint32_t ah[2][4];
#pragma unroll
            for (int mf = 0; mf < 2; ++mf)
                ldsm_x4(base + (aoff[mf] ^ sa), ah[mf]);
#pragma unroll
            for (int n16 = 0; n16 < 6; ++n16) {
                uint32_t bh[4];
                ldsm_x4t(bbase + boff[n16] + sbo, bh);
#pragma unroll
                for (int half = 0; half < 2; ++half) {
                    int nf = n16 * 2 + half;
#pragma unroll
                    for (int mf = 0; mf < 2; ++mf)
                        mma16816(acc[mf][nf], ah[mf], bh[half * 2], bh[half * 2 + 1]);
                }
            }
        }
    }

    // ---- fused epilogue: y = acc + bias + resid; LN over full row ----
    CP_WAIT(0);
    __syncthreads();
    float* red = (float*)smem;   // [2][32][8] = 2048 B

    float sums[4] = {0, 0, 0, 0}, sqs[4] = {0, 0, 0, 0};
#pragma unroll
    for (int mf = 0; mf < 2; ++mf) {
        size_t gr0 = (size_t)(brow + mf * 16 + grp) * N;
        size_t gr1 = gr0 + (size_t)8 * N;
#pragma unroll
        for (int nf = 0; nf < 12; ++nf) {
            int col = wid * 96 + nf * 8 + qc * 2;
            float2 bv = *(const float2*)(bias + col);
            float2 ra = *(const float2*)(resid + gr0 + col);
            float2 rb = *(const float2*)(resid + gr1 + col);
            float y0 = acc[mf][nf][0] + bv.x + ra.x;
            float y1 = acc[mf][nf][1] + bv.y + ra.y;
            float y2 = acc[mf][nf][2] + bv.x + rb.x;
            float y3 = acc[mf][nf][3] + bv.y + rb.y;
            acc[mf][nf][0] = y0; acc[mf][nf][1] = y1;
            acc[mf][nf][2] = y2; acc[mf][nf][3] = y3;
            sums[2 * mf]     += y0 + y1;
            sqs [2 * mf]     += y0 * y0 + y1 * y1;
            sums[2 * mf + 1] += y2 + y3;
            sqs [2 * mf + 1] += y2 * y2 + y3 * y3;
        }
    }
    // reduce across the 4 lanes of each quad (same rows)
#pragma unroll
    for (int off = 1; off <= 2; off <<= 1) {
#pragma unroll
        for (int i = 0; i < 4; ++i) {
            sums[i] += __shfl_xor_sync(0xffffffffu, sums[i], off);
            sqs[i]  += __shfl_xor_sync(0xffffffffu, sqs[i],  off);
        }
    }
    if (qc == 0) {
#pragma unroll
        for (int i = 0; i < 4; ++i) {
            int r = (i >> 1) * 16 + (i & 1) * 8 + grp;
            red[r * 8 + wid]       = sums[i];
            red[256 + r * 8 + wid] = sqs[i];
        }
    }
    __syncthreads();

    float mu[4], inv[4];
#pragma unroll
    for (int i = 0; i < 4; ++i) {
        int r = (i >> 1) * 16 + (i & 1) * 8 + grp;
        float s = 0.f, q = 0.f;
#pragma unroll
        for (int w = 0; w < 8; ++w) { s += red[r * 8 + w]; q += red[256 + r * 8 + w]; }
        float m = s * (1.0f / D_DIM);
        float var = q * (1.0f / D_DIM) - m * m;
        mu[i] = m;
        inv[i] = rsqrtf(var + 1e-5f);
    }

#pragma unroll
    for (int mf = 0; mf < 2; ++mf) {
        size_t gr0 = (size_t)(brow + mf * 16 + grp) * N;
        size_t gr1 = gr0 + (size_t)8 * N;
        float m0 = mu[2 * mf],     i0 = inv[2 * mf];
        float m1 = mu[2 * mf + 1], i1 = inv[2 * mf + 1];
#pragma unroll
        for (int nf = 0; nf < 12; ++nf) {
            int col = wid * 96 + nf * 8 + qc * 2;
            float2 gm = *(const float2*)(gamma + col);
            float2 bt = *(const float2*)(beta + col);
            float2 oA, oB;
            oA.x = gm.x * (acc[mf][nf][0] - m0) * i0 + bt.x;
            oA.y = gm.y * (acc[mf][nf][1] - m0) * i0 + bt.y;
            oB.x = gm.x * (acc[mf][nf][2] - m1) * i1 + bt.x;
            oB.y = gm.y * (acc[mf][nf][3] - m1) * i1 + bt.y;
            *(float2*)(out + gr0 + col) = oA;
            *(float2*)(out + gr1 + col) = oB;
        }
    }
}

// ---------------- K2: quantum bottleneck --------------------------------------
template <int M_, int H_>
__device__ __forceinline__ void apply_gate(float2* amp, int lane,
    float2 U00, float2 U01, float2 U10, float2 U11)
{
    constexpr int mreg  = (M_ >> 5) & 7;
    constexpr int mlane = M_ & 31;
    constexpr int hreg  = (H_ >> 5) & 7;
    constexpr int hlane = H_ & 31;
    bool lp = (__popc(lane & hlane) & 1) != 0;
    if (mreg == 0) {
#pragma unroll
        for (int r = 0; r < 8; ++r) {
            bool hi = lp ^ ((__popc(r & hreg) & 1) != 0);
            float2 o = shfl2(amp[r], mlane);
            float2 lo_v = cadd(cmul(U00, amp[r]), cmul(U01, o));
            float2 hi_v = cadd(cmul(U10, o), cmul(U11, amp[r]));
            amp[r] = hi ? hi_v : lo_v;
        }
    } else {
#pragma unroll
        for (int r = 0; r < 8; ++r) {
            int pr = r ^ mreg;
            if (r < pr) {
                float2 a = amp[r], b = amp[pr];
                float2 ash = (mlane != 0) ? shfl2(a, mlane) : a;
                float2 bsh = (mlane != 0) ? shfl2(b, mlane) : b;
                bool hi_r  = lp ^ ((__popc(r  & hreg) & 1) != 0);
                bool hi_pr = lp ^ ((__popc(pr & hreg) & 1) != 0);
                amp[r]  = hi_r  ? cadd(cmul(U10, bsh), cmul(U11, a))
                                : cadd(cmul(U00, a),   cmul(U01, bsh));
                amp[pr] = hi_pr ? cadd(cmul(U10, ash), cmul(U11, b))
                                : cadd(cmul(U00, b),   cmul(U01, ash));
            }
        }
    }
}

#define QWARPS 8
__global__ __launch_bounds__(QWARPS * 32) void quantum_kernel(
    const float* __restrict__ W2, const float* __restrict__ b2,
    const float* __restrict__ W3, const float* __restrict__ b3,
    int Brows)
{
    int warp = threadIdx.x >> 5;
    int lane = threadIdx.x & 31;
    int row  = blockIdx.x * QWARPS + warp;
    if (row >= Brows) return;

    const float* hrow = g_h + (size_t)row * H_DIM;
    float fj[8] = {0, 0, 0, 0, 0, 0, 0, 0};
#pragma unroll
    for (int m = 0; m < 8; ++m) {
        int k = lane + 32 * m;
        float hv = hrow[k];
        const float4* w2p = (const float4*)(W2 + (size_t)k * 8);
        float4 wa = w2p[0], wb = w2p[1];
        fj[0] += hv * wa.x; fj[1] += hv * wa.y;
        fj[2] += hv * wa.z; fj[3] += hv * wa.w;
        fj[4] += hv * wb.x; fj[5] += hv * wb.y;
        fj[6] += hv * wb.z; fj[7] += hv * wb.w;
    }
#pragma unroll
    for (int j = 0; j < 8; ++j)
#pragma unroll
        for (int o = 16; o; o >>= 1)
            fj[j] += __shfl_xor_sync(0xffffffffu, fj[j], o);

    float cf[8], sf[8];
#pragma unroll
    for (int j = 0; j < 8; ++j) {
        float f = 0.5f * (fj[j] + b2[j]);
        cf[j] = cosf(f);
        sf[j] = sinf(f);
    }

    float2 v0[8], v1[8];
#pragma unroll
    for (int w = 0; w < 8; ++w) {
        float2 C00 = g_C[0][w][0], C01 = g_C[0][w][1];
        float2 C10 = g_C[0][w][2], C11 = g_C[0][w][3];
        v0[w] = make_float2(C00.x * cf[w] + C01.x * sf[w], C00.y * cf[w] + C01.y * sf[w]);
        v1[w] = make_float2(C10.x * cf[w] + C11.x * sf[w], C10.y * cf[w] + C11.y * sf[w]);
    }
    float2 pl = (lane & 16) ? v1[3] : v0[3];
    pl = cmul(pl, (lane & 8) ? v1[4] : v0[4]);
    pl = cmul(pl, (lane & 4) ? v1[5] : v0[5]);
    pl = cmul(pl, (lane & 2) ? v1[6] : v0[6]);
    pl = cmul(pl, (lane & 1) ? v1[7] : v0[7]);
    float2 p01[4];
    p01[0] = cmul(v0[0], v0[1]); p01[1] = cmul(v0[0], v1[1]);
    p01[2] = cmul(v1[0], v0[1]); p01[3] = cmul(v1[0], v1[1]);
    float2 amp[8];
#pragma unroll
    for (int r = 0; r < 8; ++r)
        amp[r] = cmul(cmul(p01[r >> 1], (r & 1) ? v1[2] : v0[2]), pl);

    float2 U00[8], U01[8], U10[8], U11[8];
#pragma unroll
    for (int w = 0; w < 8; ++w) {
        float2 C00 = g_C[1][w][0], C01 = g_C[1][w][1];
        float2 C10 = g_C[1][w][2], C11 = g_C[1][w][3];
        float c = cf[w], s = sf[w];
        U00[w] = make_float2(C00.x * c + C01.x * s, C00.y * c + C01.y * s);
        U01[w] = make_float2(C01.x * c - C00.x * s, C01.y * c - C00.y * s);
        U10[w] = make_float2(C10.x * c + C11.x * s, C10.y * c + C11.y * s);
        U11[w] = make_float2(C11.x * c - C10.x * s, C11.y * c - C10.y * s);
    }
    apply_gate<0xC0, 0x7F>(amp, lane, U00[0], U01[0], U10[0], U11[0]);
    apply_gate<0x60, 0xC0>(amp, lane, U00[1], U01[1], U10[1], U11[1]);
    apply_gate<0x30, 0xE0>(amp, lane, U00[2], U01[2], U10[2], U11[2]);
    apply_gate<0x18, 0xF0>(amp, lane, U00[3], U01[3], U10[3], U11[3]);
    apply_gate<0x0C, 0xF8>(amp, lane, U00[4], U01[4], U10[4], U11[4]);
    apply_gate<0x06, 0xFC>(amp, lane, U00[5], U01[5], U10[5], U11[5]);
    apply_gate<0x03, 0xFE>(amp, lane, U00[6], U01[6], U10[6], U11[6]);
    apply_gate<0xC1, 0xFF>(amp, lane, U00[7], U01[7], U10[7], U11[7]);

    const int measm[8] = {0xD5, 0xBF, 0x5F, 0xAF, 0x57, 0xAB, 0x55, 0xAA};
    bool lpar[8];
#pragma unroll
    for (int i = 0; i < 8; ++i)
        lpar[i] = (__popc(lane & (measm[i] & 31)) & 1) != 0;

    float zf[8] = {0, 0, 0, 0, 0, 0, 0, 0};
#pragma unroll
    for (int r = 0; r < 8; ++r) {
        float p = amp[r].x * amp[r].x + amp[r].y * amp[r].y;
#pragma unroll
        for (int i = 0; i < 8; ++i) {
            bool neg = lpar[i] ^ ((__popc(r & (measm[i] >> 5)) & 1) != 0);
            zf[i] += neg ? -p : p;
        }
    }
#pragma unroll
    for (int j = 0; j < 8; ++j)
#pragma unroll
        for (int o = 16; o; o >>= 1)
            zf[j] += __shfl_xor_sync(0xffffffffu, zf[j], o);

    size_t ebase = (size_t)row * H_DIM;
#pragma unroll
    for (int m = 0; m < 8; ++m) {
        int k = lane + 32 * m;
        float acc = b3[k];
#pragma unroll
        for (int j = 0; j < 8; ++j) acc += zf[j] * W3[j * H_DIM + k];
        g_ef[ebase + k] = __float2half(gelu_exact(acc));
    }
}

// ---------------- launch ------------------------------------------------------
extern "C" void kernel_launch(void* const* d_in, const int* in_sizes, int n_in,
                              void* d_out, int out_size) {
    const float* x     = (const float*)d_in[0];
    const float* W1    = (const float*)d_in[1];
    const float* b1    = (const float*)d_in[2];
    const float* W2    = (const float*)d_in[3];
    const float* b2    = (const float*)d_in[4];
    const float* qw    = (const float*)d_in[5];
    const float* W3    = (const float*)d_in[6];
    const float* b3    = (const float*)d_in[7];
    const float* W4    = (const float*)d_in[8];
    const float* b4    = (const float*)d_in[9];
    const float* gamma = (const float*)d_in[10];
    const float* beta  = (const float*)d_in[11];
    float* out = (float*)d_out;

    int Brows = in_sizes[0] / D_DIM;   // 16384

    cudaFuncSetAttribute(gemm_gelu, cudaFuncAttributeMaxDynamicSharedMemorySize, SM_TOT);
    cudaFuncSetAttribute(gemm_resid_ln, cudaFuncAttributeMaxDynamicSharedMemorySize, SM_TOT2);

    void *pxf, *pw1f, *pw4f;
    cudaGetSymbolAddress(&pxf, g_xf);
    cudaGetSymbolAddress(&pw1f, g_w1f);
    cudaGetSymbolAddress(&pw4f, g_w4f);

    prep_gates<<<1, 32>>>(qw);

    int nx4 = (Brows * D_DIM) / 4;
    conv_half<<<(nx4 + 255) / 256, 256>>>((const float4*)x, (uint2*)pxf, nx4);
    int nw4 = (D_DIM * H_DIM) / 4;
    conv_half_w<<<(2 * nw4 + 255) / 256, 256>>>(
        (const float4*)W1, (const float4*)W4, (uint2*)pw1f, (uint2*)pw4f, nw4);

    // h = gelu(x @ W1 + b1)
    dim3 g1(H_DIM / 128, Brows / 128);
    gemm_gelu<<<g1, 256, SM_TOT>>>(b1, H_DIM, D_DIM);

    // quantum bottleneck -> e (fp16)
    quantum_kernel<<<Brows / QWARPS, QWARPS * 32>>>(W2, b2, W3, b3, Brows);

    // out = LN(x + e @ W4 + b4) — fully fused
    gemm_resid_ln<<<Brows / 32, 256, SM_TOT2>>>(b4, x, gamma, beta, out);
}

// round 11
// speedup vs baseline: 3.4949x; 1.0822x over previous
#include <cuda_runtime.h>
#include <cuda_fp16.h>
#include <cstdint>

#define BATCH   16384
#define D_DIM   768
#define H_DIM   256
#define NQ      8
#define NL      2

// ---------------- scratch -----------------------------------------------------
__device__ __align__(256) float  g_h[BATCH * H_DIM];   // gelu(x@W1+b1)
__device__ float2 g_C[NL][NQ][4];

__device__ __align__(256) __half g_xf[BATCH * D_DIM];
__device__ __align__(256) __half g_w1f[D_DIM * H_DIM];
__device__ __align__(256) __half g_w4f[H_DIM * D_DIM];
__device__ __align__(256) __half g_ef[BATCH * H_DIM];

// ---------------- helpers ------------------------------------------------------
__device__ __forceinline__ float2 cmul(float2 a, float2 b) {
    return make_float2(a.x * b.x - a.y * b.y, a.x * b.y + a.y * b.x);
}
__device__ __forceinline__ float2 cadd(float2 a, float2 b) {
    return make_float2(a.x + b.x, a.y + b.y);
}
__device__ __forceinline__ float gelu_exact(float v) {
    return 0.5f * v * (1.0f + erff(v * 0.70710678118654752f));
}
__device__ __forceinline__ uint32_t smem_to_u32(const void* p) {
    uint32_t a;
    asm("{ .reg .u64 t; cvta.to.shared.u64 t, %1; cvt.u32.u64 %0, t; }"
        : "=r"(a) : "l"(p));
    return a;
}
__device__ __forceinline__ uint2 cvt4_f16(float4 v) {
    __half2 p0 = __floats2half2_rn(v.x, v.y);
    __half2 p1 = __floats2half2_rn(v.z, v.w);
    uint2 o;
    o.x = *reinterpret_cast<uint32_t*>(&p0);
    o.y = *reinterpret_cast<uint32_t*>(&p1);
    return o;
}
__device__ __forceinline__ float2 shfl2(float2 v, int mask) {
    v.x = __shfl_xor_sync(0xffffffffu, v.x, mask);
    v.y = __shfl_xor_sync(0xffffffffu, v.y, mask);
    return v;
}

__device__ __forceinline__ void ldsm_x4(uint32_t addr, uint32_t* r) {
    asm volatile("ldmatrix.sync.aligned.m8n8.x4.shared.b16 {%0,%1,%2,%3}, [%4];"
        : "=r"(r[0]), "=r"(r[1]), "=r"(r[2]), "=r"(r[3]) : "r"(addr));
}
__device__ __forceinline__ void ldsm_x4t(uint32_t addr, uint32_t* r) {
    asm volatile("ldmatrix.sync.aligned.m8n8.x4.trans.shared.b16 {%0,%1,%2,%3}, [%4];"
        : "=r"(r[0]), "=r"(r[1]), "=r"(r[2]), "=r"(r[3]) : "r"(addr));
}
__device__ __forceinline__ void mma16816(float* d, const uint32_t* a,
                                         uint32_t b0, uint32_t b1) {
    asm volatile(
        "mma.sync.aligned.m16n8k16.row.col.f32.f16.f16.f32 "
        "{%0,%1,%2,%3}, {%4,%5,%6,%7}, {%8,%9}, {%0,%1,%2,%3};"
        : "+f"(d[0]), "+f"(d[1]), "+f"(d[2]), "+f"(d[3])
        : "r"(a[0]), "r"(a[1]), "r"(a[2]), "r"(a[3]), "r"(b0), "r"(b1));
}
__device__ __forceinline__ void cp16(uint32_t saddr, const void* g) {
    asm volatile("cp.async.cg.shared.global [%0], [%1], 16;"
        :: "r"(saddr), "l"(g) : "memory");
}
#define CP_COMMIT() asm volatile("cp.async.commit_group;" ::: "memory")
#define CP_WAIT(n)  asm volatile("cp.async.wait_group %0;" :: "n"(n) : "memory")

// ---------------- K0: precompute C[l][i] -------------------------------------
__global__ void prep_gates(const float* __restrict__ qw) {
    int t = threadIdx.x;
    if (t >= NL * NQ) return;
    int l = t / NQ, i = t % NQ;
    float w0 = qw[(l * NQ + i) * 3 + 0];
    float w1 = qw[(l * NQ + i) * 3 + 1];
    float w2 = qw[(l * NQ + i) * 3 + 2];
    float c0 = cosf(0.5f * w0), s0 = sinf(0.5f * w0);
    float c1 = cosf(0.5f * w1), s1 = sinf(0.5f * w1);
    float c2 = cosf(0.5f * w2), s2 = sinf(0.5f * w2);
    float2 e0  = make_float2(c0, -s0);
    float2 e0c = make_float2(c0,  s0);
    float2 T00 = make_float2( c1 * e0.x,   c1 * e0.y);
    float2 T01 = make_float2(-s1 * e0c.x, -s1 * e0c.y);
    float2 T10 = make_float2( s1 * e0.x,   s1 * e0.y);
    float2 T11 = make_float2( c1 * e0c.x,  c1 * e0c.y);
    float2 e2  = make_float2(c2, -s2);
    float2 e2c = make_float2(c2,  s2);
    g_C[l][i][0] = cmul(e2,  T00);
    g_C[l][i][1] = cmul(e2,  T01);
    g_C[l][i][2] = cmul(e2c, T10);
    g_C[l][i][3] = cmul(e2c, T11);
}

// ---------------- prepass: fp32 -> fp16 --------------------------------------
__global__ __launch_bounds__(256) void conv_half(
    const float4* __restrict__ src, uint2* __restrict__ dst, int n4)
{
    int i = blockIdx.x * 256 + threadIdx.x;
    if (i >= n4) return;
    dst[i] = cvt4_f16(src[i]);
}
__global__ __launch_bounds__(256) void conv_half_w(
    const float4* __restrict__ w1, const float4* __restrict__ w4,
    uint2* __restrict__ w1f, uint2* __restrict__ w4f, int n4)
{
    int i = blockIdx.x * 256 + threadIdx.x;
    if (i >= 2 * n4) return;
    if (i < n4) w1f[i] = cvt4_f16(w1[i]);
    else        w4f[i - n4] = cvt4_f16(w4[i - n4]);
}

// ---------------- GEMM-1: h = gelu(x@W1+b1), fp16 MMA, 4-stage ---------------
#define STAGES 4
#define STAGE_BYTES 16384
#define SM_TOT (STAGES * STAGE_BYTES)

__global__ __launch_bounds__(256, 2) void gemm_gelu(
    const float* __restrict__ bias, int N, int K)
{
    extern __shared__ char smem[];
    const __half* Af = g_xf;
    const __half* Bf = g_w1f;
    float* Cout = g_h;

    uint32_t sb = smem_to_u32(smem);
    int t = threadIdx.x, wid = t >> 5, lane = t & 31;
    int brow = blockIdx.y * 128, bcol = blockIdx.x * 128;
    int warpM = (wid & 3) * 32, warpN = (wid >> 2) * 64;
    int grp = lane >> 2, qc = lane & 3;

    float acc[2][8][4];
#pragma unroll
    for (int i = 0; i < 2; ++i)
#pragma unroll
        for (int j = 0; j < 8; ++j)
#pragma unroll
            for (int k = 0; k < 4; ++k) acc[i][j][k] = 0.f;

    int NC = K / 32;
    int a_row0 = t >> 2, a_kseg = t & 3;
    int b_kr0  = t >> 4, b_nseg = t & 15;

    uint32_t aoff[2], boff[4];
#pragma unroll
    for (int mf = 0; mf < 2; ++mf) {
        int m = warpM + mf * 16 + (lane & 15);
        aoff[mf] = (uint32_t)((m * 64 + (lane >> 4) * 16) ^ ((m & 7) << 4));
    }
#pragma unroll
    for (int n16 = 0; n16 < 4; ++n16) {
        uint32_t nb = (uint32_t)(warpN + n16 * 16 + (lane >> 4) * 8) * 2;
        boff[n16] = (uint32_t)((lane & 15) * 256) + (nb ^ (uint32_t)((lane & 7) << 4));
    }

    auto issue_stage = [&](int ck, int stg) {
        uint32_t base = sb + stg * STAGE_BYTES;
        int k0 = ck * 32;
#pragma unroll
        for (int i = 0; i < 2; ++i) {
            int row = a_row0 + i * 64;
            uint32_t off = (uint32_t)((row * 64 + a_kseg * 16) ^ ((row & 7) << 4));
            cp16(base + off, Af + (size_t)(brow + row) * K + k0 + a_kseg * 8);
        }
#pragma unroll
        for (int i = 0; i < 2; ++i) {
            int kr = b_kr0 + i * 16;
            uint32_t off = (uint32_t)((kr * 256 + b_nseg * 16) ^ ((kr & 7) << 4));
            cp16(base + 8192 + off, Bf + (size_t)(k0 + kr) * N + bcol + b_nseg * 8);
        }
    };

#pragma unroll
    for (int p = 0; p < STAGES - 1; ++p) {
        if (p < NC) issue_stage(p, p);
        CP_COMMIT();
    }

    for (int ck = 0; ck < NC; ++ck) {
        CP_WAIT(STAGES - 2);
        __syncthreads();

        int nx = ck + STAGES - 1;
        if (nx < NC) issue_stage(nx, nx % STAGES);
        CP_COMMIT();

        uint32_t base = sb + (uint32_t)((ck % STAGES) * STAGE_BYTES);
        uint32_t bbase = base + 8192;

#pragma unroll
        for (int s = 0; s < 2; ++s) {
            uint32_t sa = (uint32_t)(s << 5);
            uint32_t sbo = (uint32_t)(s * 4096);
            uint32_t ah[2][4];
#pragma unroll
            for (int mf = 0; mf < 2; ++mf)
                ldsm_x4(base + (aoff[mf] ^ sa), ah[mf]);
#pragma unroll
            for (int n16 = 0; n16 < 4; ++n16) {
                uint32_t bh[4];
                ldsm_x4t(bbase + boff[n16] + sbo, bh);
#pragma unroll
                for (int half = 0; half < 2; ++half) {
                    int nf = n16 * 2 + half;
#pragma unroll
                    for (int mf = 0; mf < 2; ++mf)
                        mma16816(acc[mf][nf], ah[mf], bh[half * 2], bh[half * 2 + 1]);
                }
            }
        }
    }

#pragma unroll
    for (int mf = 0; mf < 2; ++mf) {
        int r0 = brow + warpM + mf * 16 + grp;
#pragma unroll
        for (int nf = 0; nf < 8; ++nf) {
            int col = bcol + warpN + nf * 8 + qc * 2;
            float bv0 = bias[col], bv1 = bias[col + 1];
            float v0 = gelu_exact(acc[mf][nf][0] + bv0);
            float v1 = gelu_exact(acc[mf][nf][1] + bv1);
            float v2 = gelu_exact(acc[mf][nf][2] + bv0);
            float v3 = gelu_exact(acc[mf][nf][3] + bv1);
            size_t o0 = (size_t)r0 * N + col;
            size_t o1 = o0 + (size_t)8 * N;
            *(float2*)(Cout + o0) = make_float2(v0, v1);
            *(float2*)(Cout + o1) = make_float2(v2, v3);
        }
    }
}

// ---------------- GEMM-2 fused: out = LN(x + e@W4 + b4) ----------------------
// CTA: 512 threads (16 warps), M=32 rows, each warp 48 cols of N=768, K=256.
#define LSTAGES 3
#define LA_BYTES 2048
#define LB_BYTES 49152
#define LSTAGE_BYTES (LA_BYTES + LB_BYTES)
#define SM_TOT2 (LSTAGES * LSTAGE_BYTES)

__global__ __launch_bounds__(512, 1) void gemm_resid_ln(
    const float* __restrict__ bias, const float* __restrict__ resid,
    const float* __restrict__ gamma, const float* __restrict__ beta,
    float* __restrict__ out)
{
    extern __shared__ char smem[];
    const __half* Af = g_ef;     // [B,256]
    const __half* Bf = g_w4f;    // [256,768]
    const int N = D_DIM, K = H_DIM;

    uint32_t sb = smem_to_u32(smem);
    int t = threadIdx.x, wid = t >> 5, lane = t & 31;
    int brow = blockIdx.x * 32;
    int grp = lane >> 2, qc = lane & 3;

    float acc[2][6][4];
#pragma unroll
    for (int i = 0; i < 2; ++i)
#pragma unroll
        for (int j = 0; j < 6; ++j)
#pragma unroll
            for (int k = 0; k < 4; ++k) acc[i][j][k] = 0.f;

    const int NC = K / 32;   // 8

    // A copy coords (threads 0..127): row = t>>2 (0..31), kseg = t&3
    int a_row = t >> 2, a_kseg = t & 3;
    // B copy coords (512 thr): kr = t>>4 (0..31), nc0 = t&15; 6 iters -> nc 0..95
    int b_kr = t >> 4, b_nc0 = t & 15;

    uint32_t aoff[2], boff[3];
#pragma unroll
    for (int mf = 0; mf < 2; ++mf) {
        int m = mf * 16 + (lane & 15);
        aoff[mf] = (uint32_t)((m * 64 + (lane >> 4) * 16) ^ ((m & 7) << 4));
    }
#pragma unroll
    for (int n16 = 0; n16 < 3; ++n16) {
        uint32_t nb = (uint32_t)(wid * 48 + n16 * 16 + (lane >> 4) * 8) * 2;
        boff[n16] = (uint32_t)((lane & 15) * 1536) + (nb ^ (uint32_t)((lane & 7) << 4));
    }

    auto issue_stage = [&](int ck, int stg) {
        uint32_t base = sb + stg * LSTAGE_BYTES;
        int k0 = ck * 32;
        if (t < 128) {
            uint32_t off = (uint32_t)((a_row * 64 + a_kseg * 16) ^ ((a_row & 7) << 4));
            cp16(base + off, Af + (size_t)(brow + a_row) * K + k0 + a_kseg * 8);
        }
        uint32_t bb = base + LA_BYTES;
#pragma unroll
        for (int i = 0; i < 6; ++i) {
            int nc = b_nc0 + i * 16;
            uint32_t off = (uint32_t)(b_kr * 1536 + ((nc * 16) ^ ((b_kr & 7) << 4)));
            cp16(bb + off, Bf + (size_t)(k0 + b_kr) * N + nc * 8);
        }
    };

#pragma unroll
    for (int p = 0; p < LSTAGES - 1; ++p) {
        if (p < NC) issue_stage(p, p);
        CP_COMMIT();
    }

    for (int ck = 0; ck < NC; ++ck) {
        CP_WAIT(LSTAGES - 2);
        __syncthreads();

        int nx = ck + LSTAGES - 1;
        if (nx < NC) issue_stage(nx, nx % LSTAGES);
        CP_COMMIT();

        uint32_t base = sb + (uint32_t)((ck % LSTAGES) * LSTAGE_BYTES);
        uint32_t bbase = base + LA_BYTES;

#pragma unroll
        for (int s = 0; s < 2; ++s) {
            uint32_t sa = (uint32_t)(s << 5);
            uint32_t sbo = (uint32_t)(s * 16 * 1536);
            uint32_t ah[2][4];
#pragma unroll
            for (int mf = 0; mf < 2; ++mf)
                ldsm_x4(base + (aoff[mf] ^ sa), ah[mf]);
#pragma unroll
            for (int n16 = 0; n16 < 3; ++n16) {
                uint32_t bh[4];
                ldsm_x4t(bbase + boff[n16] + sbo, bh);
#pragma unroll
                for (int half = 0; half < 2; ++half) {
                    int nf = n16 * 2 + half;
#pragma unroll
                    for (int mf = 0; mf < 2; ++mf)
                        mma16816(acc[mf][nf], ah[mf], bh[half * 2], bh[half * 2 + 1]);
                }
            }
        }
    }

    // ---- fused epilogue: y = acc + bias + resid; LN over full row ----
    CP_WAIT(0);
    __syncthreads();
    float* red = (float*)smem;   // [2][32][16] = 4096 B

    float sums[4] = {0, 0, 0, 0}, sqs[4] = {0, 0, 0, 0};
#pragma unroll
    for (int mf = 0; mf < 2; ++mf) {
        size_t gr0 = (size_t)(brow + mf * 16 + grp) * N;
        size_t gr1 = gr0 + (size_t)8 * N;
#pragma unroll
        for (int nf = 0; nf < 6; ++nf) {
            int col = wid * 48 + nf * 8 + qc * 2;
            float2 bv = *(const float2*)(bias + col);
            float2 ra = *(const float2*)(resid + gr0 + col);
            float2 rb = *(const float2*)(resid + gr1 + col);
            float y0 = acc[mf][nf][0] + bv.x + ra.x;
            float y1 = acc[mf][nf][1] + bv.y + ra.y;
            float y2 = acc[mf][nf][2] + bv.x + rb.x;
            float y3 = acc[mf][nf][3] + bv.y + rb.y;
            acc[mf][nf][0] = y0; acc[mf][nf][1] = y1;
            acc[mf][nf][2] = y2; acc[mf][nf][3] = y3;
            sums[2 * mf]     += y0 + y1;
            sqs [2 * mf]     += y0 * y0 + y1 * y1;
            sums[2 * mf + 1] += y2 + y3;
            sqs [2 * mf + 1] += y2 * y2 + y3 * y3;
        }
    }
#pragma unroll
    for (int off = 1; off <= 2; off <<= 1) {
#pragma unroll
        for (int i = 0; i < 4; ++i) {
            sums[i] += __shfl_xor_sync(0xffffffffu, sums[i], off);
            sqs[i]  += __shfl_xor_sync(0xffffffffu, sqs[i],  off);
        }
    }
    if (qc == 0) {
#pragma unroll
        for (int i = 0; i < 4; ++i) {
            int r = (i >> 1) * 16 + (i & 1) * 8 + grp;
            red[r * 16 + wid]       = sums[i];
            red[512 + r * 16 + wid] = sqs[i];
        }
    }
    __syncthreads();

    float mu[4], inv[4];
#pragma unroll
    for (int i = 0; i < 4; ++i) {
        int r = (i >> 1) * 16 + (i & 1) * 8 + grp;
        float s = 0.f, q = 0.f;
#pragma unroll
        for (int w = 0; w < 16; ++w) { s += red[r * 16 + w]; q += red[512 + r * 16 + w]; }
        float m = s * (1.0f / D_DIM);
        float var = q * (1.0f / D_DIM) - m * m;
        mu[i] = m;
        inv[i] = rsqrtf(var + 1e-5f);
    }

#pragma unroll
    for (int mf = 0; mf < 2; ++mf) {
        size_t gr0 = (size_t)(brow + mf * 16 + grp) * N;
        size_t gr1 = gr0 + (size_t)8 * N;
        float m0 = mu[2 * mf],     i0 = inv[2 * mf];
        float m1 = mu[2 * mf + 1], i1 = inv[2 * mf + 1];
#pragma unroll
        for (int nf = 0; nf < 6; ++nf) {
            int col = wid * 48 + nf * 8 + qc * 2;
            float2 gm = *(const float2*)(gamma + col);
            float2 bt = *(const float2*)(beta + col);
            float2 oA, oB;
            oA.x = gm.x * (acc[mf][nf][0] - m0) * i0 + bt.x;
            oA.y = gm.y * (acc[mf][nf][1] - m0) * i0 + bt.y;
            oB.x = gm.x * (acc[mf][nf][2] - m1) * i1 + bt.x;
            oB.y = gm.y * (acc[mf][nf][3] - m1) * i1 + bt.y;
            *(float2*)(out + gr0 + col) = oA;
            *(float2*)(out + gr1 + col) = oB;
        }
    }
}

// ---------------- K2: quantum bottleneck (low register pressure) --------------
// On-the-fly gate matrices; amp in 8 float2 regs; CNOT rings algebraic.
template <int M_, int H_>
__device__ __forceinline__ void apply_gate(float2* amp, int lane,
    const float2* Cw, float c, float s)
{
    float2 C00 = Cw[0], C01 = Cw[1], C10 = Cw[2], C11 = Cw[3];
    float2 U00 = make_float2(C00.x * c + C01.x * s, C00.y * c + C01.y * s);
    float2 U01 = make_float2(C01.x * c - C00.x * s, C01.y * c - C00.y * s);
    float2 U10 = make_float2(C10.x * c + C11.x * s, C10.y * c + C11.y * s);
    float2 U11 = make_float2(C11.x * c - C10.x * s, C11.y * c - C10.y * s);

    constexpr int mreg  = (M_ >> 5) & 7;
    constexpr int mlane = M_ & 31;
    constexpr int hreg  = (H_ >> 5) & 7;
    constexpr int hlane = H_ & 31;
    bool lp = (__popc(lane & hlane) & 1) != 0;
    if (mreg == 0) {
#pragma unroll
        for (int r = 0; r < 8; ++r) {
            bool hi = lp ^ ((__popc(r & hreg) & 1) != 0);
            float2 o = shfl2(amp[r], mlane);
            float2 lo_v = cadd(cmul(U00, amp[r]), cmul(U01, o));
            float2 hi_v = cadd(cmul(U10, o), cmul(U11, amp[r]));
            amp[r] = hi ? hi_v : lo_v;
        }
    } else {
#pragma unroll
        for (int r = 0; r < 8; ++r) {
            int pr = r ^ mreg;
            if (r < pr) {
                float2 a = amp[r], b = amp[pr];
                float2 ash = (mlane != 0) ? shfl2(a, mlane) : a;
                float2 bsh = (mlane != 0) ? shfl2(b, mlane) : b;
                bool hi_r  = lp ^ ((__popc(r  & hreg) & 1) != 0);
                bool hi_pr = lp ^ ((__popc(pr & hreg) & 1) != 0);
                amp[r]  = hi_r  ? cadd(cmul(U10, bsh), cmul(U11, a))
                                : cadd(cmul(U00, a),   cmul(U01, bsh));
                amp[pr] = hi_pr ? cadd(cmul(U10, ash), cmul(U11, b))
                                : cadd(cmul(U00, b),   cmul(U01, ash));
            }
        }
    }
}

#define QWARPS 8
__global__ __launch_bounds__(QWARPS * 32) void quantum_kernel(
    const float* __restrict__ W2, const float* __restrict__ b2,
    const float* __restrict__ W3, const float* __restrict__ b3,
    int Brows)
{
    int warp = threadIdx.x >> 5;
    int lane = threadIdx.x & 31;
    int row  = blockIdx.x * QWARPS + warp;
    if (row >= Brows) return;

    const float* hrow = g_h + (size_t)row * H_DIM;
    float fj[8] = {0, 0, 0, 0, 0, 0, 0, 0};
#pragma unroll
    for (int m = 0; m < 8; ++m) {
        int k = lane + 32 * m;
        float hv = hrow[k];
        const float4* w2p = (const float4*)(W2 + (size_t)k * 8);
        float4 wa = w2p[0], wb = w2p[1];
        fj[0] += hv * wa.x; fj[1] += hv * wa.y;
        fj[2] += hv * wa.z; fj[3] += hv * wa.w;
        fj[4] += hv * wb.x; fj[5] += hv * wb.y;
        fj[6] += hv * wb.z; fj[7] += hv * wb.w;
    }
#pragma unroll
    for (int j = 0; j < 8; ++j)
#pragma unroll
        for (int o = 16; o; o >>= 1)
            fj[j] += __shfl_xor_sync(0xffffffffu, fj[j], o);

    float cf[8], sf[8];
#pragma unroll
    for (int j = 0; j < 8; ++j) {
        float f = 0.5f * (fj[j] + b2[j]);
        cf[j] = cosf(f);
        sf[j] = sinf(f);
    }

    // ---- layer 1 product state, built on the fly (no persistent v arrays) ----
    // Uw|0> = (C00*c + C01*s [bit=0], C10*c + C11*s [bit=1])
    auto vsel = [&](int w, bool b) -> float2 {
        float2 Ca = g_C[0][w][b ? 2 : 0];
        float2 Cb = g_C[0][w][b ? 3 : 1];
        return make_float2(Ca.x * cf[w] + Cb.x * sf[w], Ca.y * cf[w] + Cb.y * sf[w]);
    };
    float2 pl = vsel(3, (lane & 16) != 0);
    pl = cmul(pl, vsel(4, (lane & 8) != 0));
    pl = cmul(pl, vsel(5, (lane & 4) != 0));
    pl = cmul(pl, vsel(6, (lane & 2) != 0));
    pl = cmul(pl, vsel(7, (lane & 1) != 0));

    float2 amp[8];
    {
        float2 a0 = vsel(0, false), a1 = vsel(0, true);
        float2 b0 = vsel(1, false), b1 = vsel(1, true);
        float2 c0 = vsel(2, false), c1 = vsel(2, true);
        float2 p00 = cmul(a0, b0), p01v = cmul(a0, b1);
        float2 p10 = cmul(a1, b0), p11 = cmul(a1, b1);
        amp[0] = cmul(cmul(p00, c0), pl);
        amp[1] = cmul(cmul(p00, c1), pl);
        amp[2] = cmul(cmul(p01v, c0), pl);
        amp[3] = cmul(cmul(p01v, c1), pl);
        amp[4] = cmul(cmul(p10, c0), pl);
        amp[5] = cmul(cmul(p10, c1), pl);
        amp[6] = cmul(cmul(p11, c0), pl);
        amp[7] = cmul(cmul(p11, c1), pl);
    }

    // ---- layer 2 gates in ring-1 permuted frame (on-the-fly U) ----
    apply_gate<0xC0, 0x7F>(amp, lane, g_C[1][0], cf[0], sf[0]);
    apply_gate<0x60, 0xC0>(amp, lane, g_C[1][1], cf[1], sf[1]);
    apply_gate<0x30, 0xE0>(amp, lane, g_C[1][2], cf[2], sf[2]);
    apply_gate<0x18, 0xF0>(amp, lane, g_C[1][3], cf[3], sf[3]);
    apply_gate<0x0C, 0xF8>(amp, lane, g_C[1][4], cf[4], sf[4]);
    apply_gate<0x06, 0xFC>(amp, lane, g_C[1][5], cf[5], sf[5]);
    apply_gate<0x03, 0xFE>(amp, lane, g_C[1][6], cf[6], sf[6]);
    apply_gate<0xC1, 0xFF>(amp, lane, g_C[1][7], cf[7], sf[7]);

    // ---- measurement (ring-2 parity masks) ----
    const int measm[8] = {0xD5, 0xBF, 0x5F, 0xAF, 0x57, 0xAB, 0x55, 0xAA};
    float zf[8] = {0, 0, 0, 0, 0, 0, 0, 0};
#pragma unroll
    for (int r = 0; r < 8; ++r) {
        float p = amp[r].x * amp[r].x + amp[r].y * amp[r].y;
#pragma unroll
        for (int i = 0; i < 8; ++i) {
            bool neg = ((__popc(lane & (measm[i] & 31)) ^ __popc(r & (measm[i] >> 5))) & 1) != 0;
            zf[i] += neg ? -p : p;
        }
    }
#pragma unroll
    for (int j = 0; j < 8; ++j)
#pragma unroll
        for (int o = 16; o; o >>= 1)
            zf[j] += __shfl_xor_sync(0xffffffffu, zf[j], o);

    size_t ebase = (size_t)row * H_DIM;
#pragma unroll
    for (int m = 0; m < 8; ++m) {
        int k = lane + 32 * m;
        float acc = b3[k];
#pragma unroll
        for (int j = 0; j < 8; ++j) acc += zf[j] * W3[j * H_DIM + k];
        g_ef[ebase + k] = __float2half(gelu_exact(acc));
    }
}

// ---------------- launch ------------------------------------------------------
extern "C" void kernel_launch(void* const* d_in, const int* in_sizes, int n_in,
                              void* d_out, int out_size) {
    const float* x     = (const float*)d_in[0];
    const float* W1    = (const float*)d_in[1];
    const float* b1    = (const float*)d_in[2];
    const float* W2    = (const float*)d_in[3];
    const float* b2    = (const float*)d_in[4];
    const float* qw    = (const float*)d_in[5];
    const float* W3    = (const float*)d_in[6];
    const float* b3    = (const float*)d_in[7];
    const float* W4    = (const float*)d_in[8];
    const float* b4    = (const float*)d_in[9];
    const float* gamma = (const float*)d_in[10];
    const float* beta  = (const float*)d_in[11];
    float* out = (float*)d_out;

    int Brows = in_sizes[0] / D_DIM;   // 16384

    cudaFuncSetAttribute(gemm_gelu, cudaFuncAttributeMaxDynamicSharedMemorySize, SM_TOT);
    cudaFuncSetAttribute(gemm_resid_ln, cudaFuncAttributeMaxDynamicSharedMemorySize, SM_TOT2);

    void *pxf, *pw1f, *pw4f;
    cudaGetSymbolAddress(&pxf, g_xf);
    cudaGetSymbolAddress(&pw1f, g_w1f);
    cudaGetSymbolAddress(&pw4f, g_w4f);

    prep_gates<<<1, 32>>>(qw);

    int nx4 = (Brows * D_DIM) / 4;
    conv_half<<<(nx4 + 255) / 256, 256>>>((const float4*)x, (uint2*)pxf, nx4);
    int nw4 = (D_DIM * H_DIM) / 4;
    conv_half_w<<<(2 * nw4 + 255) / 256, 256>>>(
        (const float4*)W1, (const float4*)W4, (uint2*)pw1f, (uint2*)pw4f, nw4);

    // h = gelu(x @ W1 + b1)
    dim3 g1(H_DIM / 128, Brows / 128);
    gemm_gelu<<<g1, 256, SM_TOT>>>(b1, H_DIM, D_DIM);

    // quantum bottleneck -> e (fp16)
    quantum_kernel<<<Brows / QWARPS, QWARPS * 32>>>(W2, b2, W3, b3, Brows);

    // out = LN(x + e @ W4 + b4) — fully fused
    gemm_resid_ln<<<Brows / 32, 512, SM_TOT2>>>(b4, x, gamma, beta, out);
}

// round 12
// speedup vs baseline: 3.9644x; 1.1343x over previous
#include <cuda_runtime.h>
#include <cuda_fp16.h>
#include <cstdint>

#define BATCH   16384
#define D_DIM   768
#define H_DIM   256
#define NQ      8
#define NL      2

// ---------------- scratch -----------------------------------------------------
__device__ float2 g_C[NL][NQ][4];

__device__ __align__(256) float  g_h[BATCH * H_DIM];
__device__ __align__(256) __half g_xf[BATCH * D_DIM];
__device__ __align__(256) __half g_w1f[D_DIM * H_DIM];
__device__ __align__(256) __half g_w4f[H_DIM * D_DIM];
__device__ __align__(256) __half g_ef[BATCH * H_DIM];

// ---------------- helpers ------------------------------------------------------
__device__ __forceinline__ float2 cmul(float2 a, float2 b) {
    return make_float2(a.x * b.x - a.y * b.y, a.x * b.y + a.y * b.x);
}
__device__ __forceinline__ float2 cadd(float2 a, float2 b) {
    return make_float2(a.x + b.x, a.y + b.y);
}
__device__ __forceinline__ float gelu_exact(float v) {
    return 0.5f * v * (1.0f + erff(v * 0.70710678118654752f));
}
__device__ __forceinline__ uint32_t smem_to_u32(const void* p) {
    uint32_t a;
    asm("{ .reg .u64 t; cvta.to.shared.u64 t, %1; cvt.u32.u64 %0, t; }"
        : "=r"(a) : "l"(p));
    return a;
}
__device__ __forceinline__ uint2 cvt4_f16(float4 v) {
    __half2 p0 = __floats2half2_rn(v.x, v.y);
    __half2 p1 = __floats2half2_rn(v.z, v.w);
    uint2 o;
    o.x = *reinterpret_cast<uint32_t*>(&p0);
    o.y = *reinterpret_cast<uint32_t*>(&p1);
    return o;
}
__device__ __forceinline__ float2 shfl2(float2 v, int mask) {
    v.x = __shfl_xor_sync(0xffffffffu, v.x, mask);
    v.y = __shfl_xor_sync(0xffffffffu, v.y, mask);
    return v;
}

__device__ __forceinline__ void ldsm_x4(uint32_t addr, uint32_t* r) {
    asm volatile("ldmatrix.sync.aligned.m8n8.x4.shared.b16 {%0,%1,%2,%3}, [%4];"
        : "=r"(r[0]), "=r"(r[1]), "=r"(r[2]), "=r"(r[3]) : "r"(addr));
}
__device__ __forceinline__ void ldsm_x4t(uint32_t addr, uint32_t* r) {
    asm volatile("ldmatrix.sync.aligned.m8n8.x4.trans.shared.b16 {%0,%1,%2,%3}, [%4];"
        : "=r"(r[0]), "=r"(r[1]), "=r"(r[2]), "=r"(r[3]) : "r"(addr));
}
__device__ __forceinline__ void mma16816(float* d, const uint32_t* a,
                                         uint32_t b0, uint32_t b1) {
    asm volatile(
        "mma.sync.aligned.m16n8k16.row.col.f32.f16.f16.f32 "
        "{%0,%1,%2,%3}, {%4,%5,%6,%7}, {%8,%9}, {%0,%1,%2,%3};"
        : "+f"(d[0]), "+f"(d[1]), "+f"(d[2]), "+f"(d[3])
        : "r"(a[0]), "r"(a[1]), "r"(a[2]), "r"(a[3]), "r"(b0), "r"(b1));
}
__device__ __forceinline__ void cp16(uint32_t saddr, const void* g) {
    asm volatile("cp.async.cg.shared.global [%0], [%1], 16;"
        :: "r"(saddr), "l"(g) : "memory");
}
#define CP_COMMIT() asm volatile("cp.async.commit_group;" ::: "memory")
#define CP_WAIT(n)  asm volatile("cp.async.wait_group %0;" :: "n"(n) : "memory")

// ---------------- prep_all: gates + weight conv + x conv, ONE launch ---------
#define XB  ((BATCH * D_DIM / 4 + 255) / 256)           // 12288
#define WB  ((2 * (D_DIM * H_DIM / 4) + 255) / 256)     // 384

__global__ __launch_bounds__(256) void prep_all(
    const float* __restrict__ qw,
    const float4* __restrict__ x4,
    const float4* __restrict__ w14, const float4* __restrict__ w44,
    uint2* __restrict__ xf, uint2* __restrict__ w1f, uint2* __restrict__ w4f)
{
    int b = blockIdx.x;
    int tid = threadIdx.x;
    if (b == 0) {
        if (tid >= NL * NQ) return;
        int l = tid / NQ, i = tid % NQ;
        float w0 = qw[(l * NQ + i) * 3 + 0];
        float w1 = qw[(l * NQ + i) * 3 + 1];
        float w2 = qw[(l * NQ + i) * 3 + 2];
        float c0 = cosf(0.5f * w0), s0 = sinf(0.5f * w0);
        float c1 = cosf(0.5f * w1), s1 = sinf(0.5f * w1);
        float c2 = cosf(0.5f * w2), s2 = sinf(0.5f * w2);
        float2 e0  = make_float2(c0, -s0);
        float2 e0c = make_float2(c0,  s0);
        float2 T00 = make_float2( c1 * e0.x,   c1 * e0.y);
        float2 T01 = make_float2(-s1 * e0c.x, -s1 * e0c.y);
        float2 T10 = make_float2( s1 * e0.x,   s1 * e0.y);
        float2 T11 = make_float2( c1 * e0c.x,  c1 * e0c.y);
        float2 e2  = make_float2(c2, -s2);
        float2 e2c = make_float2(c2,  s2);
        g_C[l][i][0] = cmul(e2,  T00);
        g_C[l][i][1] = cmul(e2,  T01);
        g_C[l][i][2] = cmul(e2c, T10);
        g_C[l][i][3] = cmul(e2c, T11);
    } else if (b <= WB) {
        int i = (b - 1) * 256 + tid;
        int nw4 = D_DIM * H_DIM / 4;
        if (i >= 2 * nw4) return;
        if (i < nw4) w1f[i] = cvt4_f16(w14[i]);
        else         w4f[i - nw4] = cvt4_f16(w44[i - nw4]);
    } else {
        int i = (b - 1 - WB) * 256 + tid;
        if (i >= BATCH * D_DIM / 4) return;
        xf[i] = cvt4_f16(x4[i]);
    }
}

// ---------------- GEMM-1: h = gelu(x@W1+b1), fp16 MMA, 4-stage ---------------
#define STAGES 4
#define STAGE_BYTES 16384
#define SM_TOT (STAGES * STAGE_BYTES)

__global__ __launch_bounds__(256, 2) void gemm_gelu(
    const float* __restrict__ bias, int N, int K, int brow0)
{
    extern __shared__ char smem[];
    const __half* Af = g_xf;
    const __half* Bf = g_w1f;
    float* Cout = g_h;

    uint32_t sb = smem_to_u32(smem);
    int t = threadIdx.x, wid = t >> 5, lane = t & 31;
    int brow = brow0 + blockIdx.y * 128, bcol = blockIdx.x * 128;
    int warpM = (wid & 3) * 32, warpN = (wid >> 2) * 64;
    int grp = lane >> 2, qc = lane & 3;

    float acc[2][8][4];
#pragma unroll
    for (int i = 0; i < 2; ++i)
#pragma unroll
        for (int j = 0; j < 8; ++j)
#pragma unroll
            for (int k = 0; k < 4; ++k) acc[i][j][k] = 0.f;

    int NC = K / 32;
    int a_row0 = t >> 2, a_kseg = t & 3;
    int b_kr0  = t >> 4, b_nseg = t & 15;

    uint32_t aoff[2], boff[4];
#pragma unroll
    for (int mf = 0; mf < 2; ++mf) {
        int m = warpM + mf * 16 + (lane & 15);
        aoff[mf] = (uint32_t)((m * 64 + (lane >> 4) * 16) ^ ((m & 7) << 4));
    }
#pragma unroll
    for (int n16 = 0; n16 < 4; ++n16) {
        uint32_t nb = (uint32_t)(warpN + n16 * 16 + (lane >> 4) * 8) * 2;
        boff[n16] = (uint32_t)((lane & 15) * 256) + (nb ^ (uint32_t)((lane & 7) << 4));
    }

    auto issue_stage = [&](int ck, int stg) {
        uint32_t base = sb + stg * STAGE_BYTES;
        int k0 = ck * 32;
#pragma unroll
        for (int i = 0; i < 2; ++i) {
            int row = a_row0 + i * 64;
            uint32_t off = (uint32_t)((row * 64 + a_kseg * 16) ^ ((row & 7) << 4));
            cp16(base + off, Af + (size_t)(brow + row) * K + k0 + a_kseg * 8);
        }
#pragma unroll
        for (int i = 0; i < 2; ++i) {
            int kr = b_kr0 + i * 16;
            uint32_t off = (uint32_t)((kr * 256 + b_nseg * 16) ^ ((kr & 7) << 4));
            cp16(base + 8192 + off, Bf + (size_t)(k0 + kr) * N + bcol + b_nseg * 8);
        }
    };

#pragma unroll
    for (int p = 0; p < STAGES - 1; ++p) {
        if (p < NC) issue_stage(p, p);
        CP_COMMIT();
    }

    for (int ck = 0; ck < NC; ++ck) {
        CP_WAIT(STAGES - 2);
        __syncthreads();

        int nx = ck + STAGES - 1;
        if (nx < NC) issue_stage(nx, nx % STAGES);
        CP_COMMIT();

        uint32_t base = sb + (uint32_t)((ck % STAGES) * STAGE_BYTES);
        uint32_t bbase = base + 8192;

#pragma unroll
        for (int s = 0; s < 2; ++s) {
            uint32_t sa = (uint32_t)(s << 5);
            uint32_t sbo = (uint32_t)(s * 4096);
            uint32_t ah[2][4];
#pragma unroll
            for (int mf = 0; mf < 2; ++mf)
                ldsm_x4(base + (aoff[mf] ^ sa), ah[mf]);
#pragma unroll
            for (int n16 = 0; n16 < 4; ++n16) {
                uint32_t bh[4];
                ldsm_x4t(bbase + boff[n16] + sbo, bh);
#pragma unroll
                for (int half = 0; half < 2; ++half) {
                    int nf = n16 * 2 + half;
#pragma unroll
                    for (int mf = 0; mf < 2; ++mf)
                        mma16816(acc[mf][nf], ah[mf], bh[half * 2], bh[half * 2 + 1]);
                }
            }
        }
    }

#pragma unroll
    for (int mf = 0; mf < 2; ++mf) {
        int r0 = brow + warpM + mf * 16 + grp;
#pragma unroll
        for (int nf = 0; nf < 8; ++nf) {
            int col = bcol + warpN + nf * 8 + qc * 2;
            float bv0 = bias[col], bv1 = bias[col + 1];
            float v0 = gelu_exact(acc[mf][nf][0] + bv0);
            float v1 = gelu_exact(acc[mf][nf][1] + bv1);
            float v2 = gelu_exact(acc[mf][nf][2] + bv0);
            float v3 = gelu_exact(acc[mf][nf][3] + bv1);
            size_t o0 = (size_t)r0 * N + col;
            size_t o1 = o0 + (size_t)8 * N;
            *(float2*)(Cout + o0) = make_float2(v0, v1);
            *(float2*)(Cout + o1) = make_float2(v2, v3);
        }
    }
}

// ---------------- GEMM-2 fused: out = LN(x + e@W4 + b4) ----------------------
#define LSTAGES 3
#define LA_BYTES 2048
#define LB_BYTES 49152
#define LSTAGE_BYTES (LA_BYTES + LB_BYTES)
#define SM_TOT2 (LSTAGES * LSTAGE_BYTES)

__global__ __launch_bounds__(512, 1) void gemm_resid_ln(
    const float* __restrict__ bias, const float* __restrict__ resid,
    const float* __restrict__ gamma, const float* __restrict__ beta,
    float* __restrict__ out, int row0)
{
    extern __shared__ char smem[];
    const __half* Af = g_ef;
    const __half* Bf = g_w4f;
    const int N = D_DIM, K = H_DIM;

    uint32_t sb = smem_to_u32(smem);
    int t = threadIdx.x, wid = t >> 5, lane = t & 31;
    int brow = row0 + blockIdx.x * 32;
    int grp = lane >> 2, qc = lane & 3;

    float acc[2][6][4];
#pragma unroll
    for (int i = 0; i < 2; ++i)
#pragma unroll
        for (int j = 0; j < 6; ++j)
#pragma unroll
            for (int k = 0; k < 4; ++k) acc[i][j][k] = 0.f;

    const int NC = K / 32;

    int a_row = t >> 2, a_kseg = t & 3;
    int b_kr = t >> 4, b_nc0 = t & 15;

    uint32_t aoff[2], boff[3];
#pragma unroll
    for (int mf = 0; mf < 2; ++mf) {
        int m = mf * 16 + (lane & 15);
        aoff[mf] = (uint32_t)((m * 64 + (lane >> 4) * 16) ^ ((m & 7) << 4));
    }
#pragma unroll
    for (int n16 = 0; n16 < 3; ++n16) {
        uint32_t nb = (uint32_t)(wid * 48 + n16 * 16 + (lane >> 4) * 8) * 2;
        boff[n16] = (uint32_t)((lane & 15) * 1536) + (nb ^ (uint32_t)((lane & 7) << 4));
    }

    auto issue_stage = [&](int ck, int stg) {
        uint32_t base = sb + stg * LSTAGE_BYTES;
        int k0 = ck * 32;
        if (t < 128) {
            uint32_t off = (uint32_t)((a_row * 64 + a_kseg * 16) ^ ((a_row & 7) << 4));
            cp16(base + off, Af + (size_t)(brow + a_row) * K + k0 + a_kseg * 8);
        }
        uint32_t bb = base + LA_BYTES;
#pragma unroll
        for (int i = 0; i < 6; ++i) {
            int nc = b_nc0 + i * 16;
            uint32_t off = (uint32_t)(b_kr * 1536 + ((nc * 16) ^ ((b_kr & 7) << 4)));
            cp16(bb + off, Bf + (size_t)(k0 + b_kr) * N + nc * 8);
        }
    };

#pragma unroll
    for (int p = 0; p < LSTAGES - 1; ++p) {
        if (p < NC) issue_stage(p, p);
        CP_COMMIT();
    }

    for (int ck = 0; ck < NC; ++ck) {
        CP_WAIT(LSTAGES - 2);
        __syncthreads();

        int nx = ck + LSTAGES - 1;
        if (nx < NC) issue_stage(nx, nx % LSTAGES);
        CP_COMMIT();

        uint32_t base = sb + (uint32_t)((ck % LSTAGES) * LSTAGE_BYTES);
        uint32_t bbase = base + LA_BYTES;

#pragma unroll
        for (int s = 0; s < 2; ++s) {
            uint32_t sa = (uint32_t)(s << 5);
            uint32_t sbo = (uint32_t)(s * 16 * 1536);
            uint32_t ah[2][4];
#pragma unroll
            for (int mf = 0; mf < 2; ++mf)
                ldsm_x4(base + (aoff[mf] ^ sa), ah[mf]);
#pragma unroll
            for (int n16 = 0; n16 < 3; ++n16) {
                uint32_t bh[4];
                ldsm_x4t(bbase + boff[n16] + sbo, bh);
#pragma unroll
                for (int half = 0; half < 2; ++half) {
                    int nf = n16 * 2 + half;
#pragma unroll
                    for (int mf = 0; mf < 2; ++mf)
                        mma16816(acc[mf][nf], ah[mf], bh[half * 2], bh[half * 2 + 1]);
                }
            }
        }
    }

    CP_WAIT(0);
    __syncthreads();
    float* red = (float*)smem;

    float sums[4] = {0, 0, 0, 0}, sqs[4] = {0, 0, 0, 0};
#pragma unroll
    for (int mf = 0; mf < 2; ++mf) {
        size_t gr0 = (size_t)(brow + mf * 16 + grp) * N;
        size_t gr1 = gr0 + (size_t)8 * N;
#pragma unroll
        for (int nf = 0; nf < 6; ++nf) {
            int col = wid * 48 + nf * 8 + qc * 2;
            float2 bv = *(const float2*)(bias + col);
            float2 ra = *(const float2*)(resid + gr0 + col);
            float2 rb = *(const float2*)(resid + gr1 + col);
            float y0 = acc[mf][nf][0] + bv.x + ra.x;
            float y1 = acc[mf][nf][1] + bv.y + ra.y;
            float y2 = acc[mf][nf][2] + bv.x + rb.x;
            float y3 = acc[mf][nf][3] + bv.y + rb.y;
            acc[mf][nf][0] = y0; acc[mf][nf][1] = y1;
            acc[mf][nf][2] = y2; acc[mf][nf][3] = y3;
            sums[2 * mf]     += y0 + y1;
            sqs [2 * mf]     += y0 * y0 + y1 * y1;
            sums[2 * mf + 1] += y2 + y3;
            sqs [2 * mf + 1] += y2 * y2 + y3 * y3;
        }
    }
#pragma unroll
    for (int off = 1; off <= 2; off <<= 1) {
#pragma unroll
        for (int i = 0; i < 4; ++i) {
            sums[i] += __shfl_xor_sync(0xffffffffu, sums[i], off);
            sqs[i]  += __shfl_xor_sync(0xffffffffu, sqs[i],  off);
        }
    }
    if (qc == 0) {
#pragma unroll
        for (int i = 0; i < 4; ++i) {
            int r = (i >> 1) * 16 + (i & 1) * 8 + grp;
            red[r * 16 + wid]       = sums[i];
            red[512 + r * 16 + wid] = sqs[i];
        }
    }
    __syncthreads();

    float mu[4], inv[4];
#pragma unroll
    for (int i = 0; i < 4; ++i) {
        int r = (i >> 1) * 16 + (i & 1) * 8 + grp;
        float s = 0.f, q = 0.f;
#pragma unroll
        for (int w = 0; w < 16; ++w) { s += red[r * 16 + w]; q += red[512 + r * 16 + w]; }
        float m = s * (1.0f / D_DIM);
        float var = q * (1.0f / D_DIM) - m * m;
        mu[i] = m;
        inv[i] = rsqrtf(var + 1e-5f);
    }

#pragma unroll
    for (int mf = 0; mf < 2; ++mf) {
        size_t gr0 = (size_t)(brow + mf * 16 + grp) * N;
        size_t gr1 = gr0 + (size_t)8 * N;
        float m0 = mu[2 * mf],     i0 = inv[2 * mf];
        float m1 = mu[2 * mf + 1], i1 = inv[2 * mf + 1];
#pragma unroll
        for (int nf = 0; nf < 6; ++nf) {
            int col = wid * 48 + nf * 8 + qc * 2;
            float2 gm = *(const float2*)(gamma + col);
            float2 bt = *(const float2*)(beta + col);
            float2 oA, oB;
            oA.x = gm.x * (acc[mf][nf][0] - m0) * i0 + bt.x;
            oA.y = gm.y * (acc[mf][nf][1] - m0) * i0 + bt.y;
            oB.x = gm.x * (acc[mf][nf][2] - m1) * i1 + bt.x;
            oB.y = gm.y * (acc[mf][nf][3] - m1) * i1 + bt.y;
            *(float2*)(out + gr0 + col) = oA;
            *(float2*)(out + gr1 + col) = oB;
        }
    }
}

// ---------------- quantum bottleneck ------------------------------------------
template <int M_, int H_>
__device__ __forceinline__ void apply_gate(float2* amp, int lane,
    const float2* Cw, float c, float s)
{
    float2 C00 = Cw[0], C01 = Cw[1], C10 = Cw[2], C11 = Cw[3];
    float2 U00 = make_float2(C00.x * c + C01.x * s, C00.y * c + C01.y * s);
    float2 U01 = make_float2(C01.x * c - C00.x * s, C01.y * c - C00.y * s);
    float2 U10 = make_float2(C10.x * c + C11.x * s, C10.y * c + C11.y * s);
    float2 U11 = make_float2(C11.x * c - C10.x * s, C11.y * c - C10.y * s);

    constexpr int mreg  = (M_ >> 5) & 7;
    constexpr int mlane = M_ & 31;
    constexpr int hreg  = (H_ >> 5) & 7;
    constexpr int hlane = H_ & 31;
    bool lp = (__popc(lane & hlane) & 1) != 0;
    if (mreg == 0) {
#pragma unroll
        for (int r = 0; r < 8; ++r) {
            bool hi = lp ^ ((__popc(r & hreg) & 1) != 0);
            float2 o = shfl2(amp[r], mlane);
            float2 lo_v = cadd(cmul(U00, amp[r]), cmul(U01, o));
            float2 hi_v = cadd(cmul(U10, o), cmul(U11, amp[r]));
            amp[r] = hi ? hi_v : lo_v;
        }
    } else {
#pragma unroll
        for (int r = 0; r < 8; ++r) {
            int pr = r ^ mreg;
            if (r < pr) {
                float2 a = amp[r], b = amp[pr];
                float2 ash = (mlane != 0) ? shfl2(a, mlane) : a;
                float2 bsh = (mlane != 0) ? shfl2(b, mlane) : b;
                bool hi_r  = lp ^ ((__popc(r  & hreg) & 1) != 0);
                bool hi_pr = lp ^ ((__popc(pr & hreg) & 1) != 0);
                amp[r]  = hi_r  ? cadd(cmul(U10, bsh), cmul(U11, a))
                                : cadd(cmul(U00, a),   cmul(U01, bsh));
                amp[pr] = hi_pr ? cadd(cmul(U10, ash), cmul(U11, b))
                                : cadd(cmul(U00, b),   cmul(U01, ash));
            }
        }
    }
}

#define QWARPS 8
__global__ __launch_bounds__(QWARPS * 32) void quantum_kernel(
    const float* __restrict__ W2, const float* __restrict__ b2,
    const float* __restrict__ W3, const float* __restrict__ b3,
    int row0)
{
    int warp = threadIdx.x >> 5;
    int lane = threadIdx.x & 31;
    int row  = row0 + blockIdx.x * QWARPS + warp;

    const float* hrow = g_h + (size_t)row * H_DIM;
    float fj[8] = {0, 0, 0, 0, 0, 0, 0, 0};
#pragma unroll
    for (int m = 0; m < 8; ++m) {
        int k = lane + 32 * m;
        float hv = hrow[k];
        const float4* w2p = (const float4*)(W2 + (size_t)k * 8);
        float4 wa = w2p[0], wb = w2p[1];
        fj[0] += hv * wa.x; fj[1] += hv * wa.y;
        fj[2] += hv * wa.z; fj[3] += hv * wa.w;
        fj[4] += hv * wb.x; fj[5] += hv * wb.y;
        fj[6] += hv * wb.z; fj[7] += hv * wb.w;
    }
#pragma unroll
    for (int j = 0; j < 8; ++j)
#pragma unroll
        for (int o = 16; o; o >>= 1)
            fj[j] += __shfl_xor_sync(0xffffffffu, fj[j], o);

    float cf[8], sf[8];
#pragma unroll
    for (int j = 0; j < 8; ++j) {
        float f = 0.5f * (fj[j] + b2[j]);
        sincosf(f, &sf[j], &cf[j]);
    }

    auto vsel = [&](int w, bool b) -> float2 {
        float2 Ca = g_C[0][w][b ? 2 : 0];
        float2 Cb = g_C[0][w][b ? 3 : 1];
        return make_float2(Ca.x * cf[w] + Cb.x * sf[w], Ca.y * cf[w] + Cb.y * sf[w]);
    };
    float2 pl = vsel(3, (lane & 16) != 0);
    pl = cmul(pl, vsel(4, (lane & 8) != 0));
    pl = cmul(pl, vsel(5, (lane & 4) != 0));
    pl = cmul(pl, vsel(6, (lane & 2) != 0));
    pl = cmul(pl, vsel(7, (lane & 1) != 0));

    float2 amp[8];
    {
        float2 a0 = vsel(0, false), a1 = vsel(0, true);
        float2 b0 = vsel(1, false), b1 = vsel(1, true);
        float2 c0 = vsel(2, false), c1 = vsel(2, true);
        float2 p00 = cmul(a0, b0), p01v = cmul(a0, b1);
        float2 p10 = cmul(a1, b0), p11 = cmul(a1, b1);
        amp[0] = cmul(cmul(p00, c0), pl);
        amp[1] = cmul(cmul(p00, c1), pl);
        amp[2] = cmul(cmul(p01v, c0), pl);
        amp[3] = cmul(cmul(p01v, c1), pl);
        amp[4] = cmul(cmul(p10, c0), pl);
        amp[5] = cmul(cmul(p10, c1), pl);
        amp[6] = cmul(cmul(p11, c0), pl);
        amp[7] = cmul(cmul(p11, c1), pl);
    }

    apply_gate<0xC0, 0x7F>(amp, lane, g_C[1][0], cf[0], sf[0]);
    apply_gate<0x60, 0xC0>(amp, lane, g_C[1][1], cf[1], sf[1]);
    apply_gate<0x30, 0xE0>(amp, lane, g_C[1][2], cf[2], sf[2]);
    apply_gate<0x18, 0xF0>(amp, lane, g_C[1][3], cf[3], sf[3]);
    apply_gate<0x0C, 0xF8>(amp, lane, g_C[1][4], cf[4], sf[4]);
    apply_gate<0x06, 0xFC>(amp, lane, g_C[1][5], cf[5], sf[5]);
    apply_gate<0x03, 0xFE>(amp, lane, g_C[1][6], cf[6], sf[6]);
    apply_gate<0xC1, 0xFF>(amp, lane, g_C[1][7], cf[7], sf[7]);

    const int measm[8] = {0xD5, 0xBF, 0x5F, 0xAF, 0x57, 0xAB, 0x55, 0xAA};
    float zf[8] = {0, 0, 0, 0, 0, 0, 0, 0};
#pragma unroll
    for (int r = 0; r < 8; ++r) {
        float p = amp[r].x * amp[r].x + amp[r].y * amp[r].y;
#pragma unroll
        for (int i = 0; i < 8; ++i) {
            bool neg = ((__popc(lane & (measm[i] & 31)) ^ __popc(r & (measm[i] >> 5))) & 1) != 0;
            zf[i] += neg ? -p : p;
        }
    }
#pragma unroll
    for (int j = 0; j < 8; ++j)
#pragma unroll
        for (int o = 16; o; o >>= 1)
            zf[j] += __shfl_xor_sync(0xffffffffu, zf[j], o);

    size_t ebase = (size_t)row * H_DIM;
#pragma unroll
    for (int m = 0; m < 8; ++m) {
        int k = lane + 32 * m;
        float acc = b3[k];
#pragma unroll
        for (int j = 0; j < 8; ++j) acc += zf[j] * W3[j * H_DIM + k];
        g_ef[ebase + k] = __float2half(gelu_exact(acc));
    }
}

// ---------------- launch ------------------------------------------------------
extern "C" void kernel_launch(void* const* d_in, const int* in_sizes, int n_in,
                              void* d_out, int out_size) {
    const float* x     = (const float*)d_in[0];
    const float* W1    = (const float*)d_in[1];
    const float* b1    = (const float*)d_in[2];
    const float* W2    = (const float*)d_in[3];
    const float* b2    = (const float*)d_in[4];
    const float* qw    = (const float*)d_in[5];
    const float* W3    = (const float*)d_in[6];
    const float* b3    = (const float*)d_in[7];
    const float* W4    = (const float*)d_in[8];
    const float* b4    = (const float*)d_in[9];
    const float* gamma = (const float*)d_in[10];
    const float* beta  = (const float*)d_in[11];
    float* out = (float*)d_out;

    int Brows = in_sizes[0] / D_DIM;   // 16384
    int half  = Brows / 2;

    // one-time resources (created on the uncaptured correctness call)
    static cudaStream_t s1 = nullptr;
    static cudaEvent_t evP = nullptr, evB = nullptr;
    if (!s1) {
        cudaStreamCreateWithFlags(&s1, cudaStreamNonBlocking);
        cudaEventCreateWithFlags(&evP, cudaEventDisableTiming);
        cudaEventCreateWithFlags(&evB, cudaEventDisableTiming);
        cudaFuncSetAttribute(gemm_gelu, cudaFuncAttributeMaxDynamicSharedMemorySize, SM_TOT);
        cudaFuncSetAttribute(gemm_resid_ln, cudaFuncAttributeMaxDynamicSharedMemorySize, SM_TOT2);
    }

    void *pxf, *pw1f, *pw4f;
    cudaGetSymbolAddress(&pxf, g_xf);
    cudaGetSymbolAddress(&pw1f, g_w1f);
    cudaGetSymbolAddress(&pw4f, g_w4f);

    // stage 0: all prep in one launch (default stream)
    prep_all<<<1 + WB + XB, 256>>>(
        qw, (const float4*)x, (const float4*)W1, (const float4*)W4,
        (uint2*)pxf, (uint2*)pw1f, (uint2*)pw4f);

    // fork: stream s1 joins the capture via event
    cudaEventRecord(evP, 0);
    cudaStreamWaitEvent(s1, evP, 0);

    dim3 gG(H_DIM / 128, half / 128);   // (2, 64) per half
    int  gQ = half / QWARPS;            // 1024
    int  gF = half / 32;                // 256

    // chain A (rows [0, half)) on default stream
    gemm_gelu<<<gG, 256, SM_TOT>>>(b1, H_DIM, D_DIM, 0);
    quantum_kernel<<<gQ, QWARPS * 32>>>(W2, b2, W3, b3, 0);
    gemm_resid_ln<<<gF, 512, SM_TOT2>>>(b4, x, gamma, beta, out, 0);

    // chain B (rows [half, Brows)) on s1
    gemm_gelu<<<gG, 256, SM_TOT, s1>>>(b1, H_DIM, D_DIM, half);
    quantum_kernel<<<gQ, QWARPS * 32, 0, s1>>>(W2, b2, W3, b3, half);
    gemm_resid_ln<<<gF, 512, SM_TOT2, s1>>>(b4, x, gamma, beta, out, half);

    // join
    cudaEventRecord(evB, s1);
    cudaStreamWaitEvent(0, evB, 0);
}